// round 1
// baseline (speedup 1.0000x reference)
#include <cuda_runtime.h>
#include <math.h>

// Problem constants
#define B_ 4
#define T_ 2048
#define C_ 1024
#define H_ 16
#define D_ 64
#define M_ (B_*T_)   // 8192 rows

// Scratch (device globals: allocation-free).
// q,k,v stored as [B,H,T,D]; y stored as [B,T,H*D] (= [M, C]).
__device__ float g_q[(size_t)M_ * C_];
__device__ float g_k[(size_t)M_ * C_];
__device__ float g_v[(size_t)M_ * C_];
__device__ float g_y[(size_t)M_ * C_];

// ---------------------------------------------------------------------------
// SGEMM: C[M,N] = A[M,K] @ B[K,N], M=8192, N=K=1024.
// 128x128 block tile, BK=8, 256 threads, 8x8 micro-tile per thread.
// csel: 0/1/2 -> scatter into g_q/g_k/g_v with [B,H,T,D] layout
//       3     -> plain row-major into C_ext
// asel: 0 -> A_ext, 1 -> g_y
// ---------------------------------------------------------------------------
__global__ void __launch_bounds__(256, 2) sgemm_kernel(
    const float* __restrict__ A_ext, const float* __restrict__ Bw,
    float* __restrict__ C_ext, int asel, int csel)
{
    const int K = C_, N = C_;
    const float* A = (asel == 0) ? A_ext : (const float*)g_y;
    float* Co = (csel == 0) ? g_q : (csel == 1) ? g_k : (csel == 2) ? g_v : C_ext;

    __shared__ __align__(16) float As[8][132];  // [k][m], padded vs bank conflicts
    __shared__ __align__(16) float Bs[8][128];  // [k][n]

    const int bm = blockIdx.y * 128;
    const int bn = blockIdx.x * 128;
    const int tid = threadIdx.x;
    const int tx = tid & 15;        // n micro-tile index (0..15)
    const int ty = tid >> 4;        // m micro-tile index (0..15)

    float acc[8][8];
#pragma unroll
    for (int i = 0; i < 8; i++)
#pragma unroll
        for (int j = 0; j < 8; j++) acc[i][j] = 0.f;

    const int arow = tid >> 1;           // 0..127
    const int acol = (tid & 1) * 4;      // 0 or 4
    const int brow = tid >> 5;           // 0..7
    const int bcol = (tid & 31) * 4;     // 0..124
    const float* Ag = A + (size_t)(bm + arow) * K + acol;
    const float* Bg = Bw + (size_t)brow * N + bn + bcol;

    for (int k0 = 0; k0 < K; k0 += 8) {
        float4 a4 = *(const float4*)(Ag + k0);
        float4 b4 = *(const float4*)(Bg + (size_t)k0 * N);
        As[acol + 0][arow] = a4.x;
        As[acol + 1][arow] = a4.y;
        As[acol + 2][arow] = a4.z;
        As[acol + 3][arow] = a4.w;
        *(float4*)&Bs[brow][bcol] = b4;
        __syncthreads();
#pragma unroll
        for (int kk = 0; kk < 8; kk++) {
            float ar[8], br[8];
            *(float4*)(ar)     = *(const float4*)&As[kk][ty * 8];
            *(float4*)(ar + 4) = *(const float4*)&As[kk][ty * 8 + 4];
            *(float4*)(br)     = *(const float4*)&Bs[kk][tx * 8];
            *(float4*)(br + 4) = *(const float4*)&Bs[kk][tx * 8 + 4];
#pragma unroll
            for (int i = 0; i < 8; i++)
#pragma unroll
                for (int j = 0; j < 8; j++)
                    acc[i][j] += ar[i] * br[j];
        }
        __syncthreads();
    }

    if (csel < 3) {
        // scatter into [B,H,T,D]: m = b*T + t, n = h*D + d
#pragma unroll
        for (int i = 0; i < 8; i++) {
            int m = bm + ty * 8 + i;
            int b = m >> 11;            // / T_
            int t = m & (T_ - 1);
#pragma unroll
            for (int j = 0; j < 8; j++) {
                int n = bn + tx * 8 + j;
                int h = n >> 6;
                int d = n & 63;
                Co[(size_t)(((b * H_ + h) * T_ + t)) * D_ + d] = acc[i][j];
            }
        }
    } else {
#pragma unroll
        for (int i = 0; i < 8; i++) {
            int m = bm + ty * 8 + i;
            float4 v0 = make_float4(acc[i][0], acc[i][1], acc[i][2], acc[i][3]);
            float4 v1 = make_float4(acc[i][4], acc[i][5], acc[i][6], acc[i][7]);
            *(float4*)&Co[(size_t)m * N + bn + tx * 8]     = v0;
            *(float4*)&Co[(size_t)m * N + bn + tx * 8 + 4] = v1;
        }
    }
}

// ---------------------------------------------------------------------------
// Causal flash attention with learned null-KV column.
// grid = (T/128, B*H), block = 128. One query row per thread.
// K/V staged in SMEM in tiles of 64 rows; online softmax with lazy rescale.
// ---------------------------------------------------------------------------
__global__ void __launch_bounds__(128) attn_kernel(
    const float* __restrict__ nullk, const float* __restrict__ nullv,
    const float* __restrict__ lscale)
{
    const int bh = blockIdx.y;
    const int h = bh & (H_ - 1);
    const int b = bh >> 4;
    const int r = blockIdx.x * 128 + threadIdx.x;   // query row (0..T-1)

    const float scale = __expf(lscale[h]) * 0.125f; // exp(ls)/sqrt(64)

    const float* qb = g_q + ((size_t)bh * T_ + r) * D_;
    float q[D_];
#pragma unroll
    for (int d = 0; d < D_; d++) q[d] = qb[d] * scale;

    float o[D_];
#pragma unroll
    for (int d = 0; d < D_; d++) o[d] = 0.f;
    float mv = -3.4e38f, l = 0.f;

    __shared__ __align__(16) float ks[64][64];
    __shared__ __align__(16) float vs[64][64];

    const float* kb = g_k + (size_t)bh * T_ * D_;
    const float* vb = g_v + (size_t)bh * T_ * D_;
    const int smax = blockIdx.x * 128 + 127;        // last row this block needs

    for (int s0 = 0; s0 <= smax; s0 += 64) {
        __syncthreads();
        // stage 64x64 K and V tiles (8 float4 per thread each array half)
#pragma unroll
        for (int i = 0; i < 8; i++) {
            int idx = threadIdx.x + i * 128;        // 0..1023 float4 slots
            ((float4*)ks)[idx] = ((const float4*)(kb + (size_t)s0 * D_))[idx];
            ((float4*)vs)[idx] = ((const float4*)(vb + (size_t)s0 * D_))[idx];
        }
        __syncthreads();

        const int jmax = min(64, r - s0 + 1);       // causal bound for this row
        for (int j = 0; j < jmax; j++) {
            const float4* kr = (const float4*)&ks[j][0];
            float sa = 0.f, sb = 0.f, sc = 0.f, sd = 0.f;
#pragma unroll
            for (int d4 = 0; d4 < 16; d4 += 4) {
                float4 k0v = kr[d4 + 0];
                float4 k1v = kr[d4 + 1];
                float4 k2v = kr[d4 + 2];
                float4 k3v = kr[d4 + 3];
                sa += q[(d4+0)*4+0]*k0v.x + q[(d4+0)*4+1]*k0v.y + q[(d4+0)*4+2]*k0v.z + q[(d4+0)*4+3]*k0v.w;
                sb += q[(d4+1)*4+0]*k1v.x + q[(d4+1)*4+1]*k1v.y + q[(d4+1)*4+2]*k1v.z + q[(d4+1)*4+3]*k1v.w;
                sc += q[(d4+2)*4+0]*k2v.x + q[(d4+2)*4+1]*k2v.y + q[(d4+2)*4+2]*k2v.z + q[(d4+2)*4+3]*k2v.w;
                sd += q[(d4+3)*4+0]*k3v.x + q[(d4+3)*4+1]*k3v.y + q[(d4+3)*4+2]*k3v.z + q[(d4+3)*4+3]*k3v.w;
            }
            float s = (sa + sb) + (sc + sd);

            if (s > mv) {                            // rare: lazy rescale
                float c = __expf(mv - s);
                l *= c;
#pragma unroll
                for (int d = 0; d < D_; d++) o[d] *= c;
                mv = s;
            }
            float p = __expf(s - mv);
            l += p;
            const float4* vr = (const float4*)&vs[j][0];
#pragma unroll
            for (int d4 = 0; d4 < 16; d4++) {
                float4 vv = vr[d4];
                o[d4*4+0] += p * vv.x;
                o[d4*4+1] += p * vv.y;
                o[d4*4+2] += p * vv.z;
                o[d4*4+3] += p * vv.w;
            }
        }
    }

    // learned null-KV column (always visible)
    {
        const float* nk = nullk + h * D_;
        float s = 0.f;
#pragma unroll
        for (int d = 0; d < D_; d++) s += q[d] * nk[d];
        if (s > mv) {
            float c = __expf(mv - s);
            l *= c;
#pragma unroll
            for (int d = 0; d < D_; d++) o[d] *= c;
            mv = s;
        }
        float p = __expf(s - mv);
        l += p;
        const float* nv = nullv + h * D_;
#pragma unroll
        for (int d = 0; d < D_; d++) o[d] += p * nv[d];
    }

    const float inv = 1.f / l;
    float* yo = g_y + ((size_t)(b * T_ + r)) * C_ + h * D_;
#pragma unroll
    for (int d = 0; d < D_; d++) yo[d] = o[d] * inv;
}

// ---------------------------------------------------------------------------
// kernel_launch: 5 kernel launches, default stream, graph-capturable.
// Inputs (metadata order): x, Wq, Wk, Wv, Wo, null_k, null_v, logit_scale
// ---------------------------------------------------------------------------
extern "C" void kernel_launch(void* const* d_in, const int* in_sizes, int n_in,
                              void* d_out, int out_size) {
    const float* x  = (const float*)d_in[0];
    const float* Wq = (const float*)d_in[1];
    const float* Wk = (const float*)d_in[2];
    const float* Wv = (const float*)d_in[3];
    const float* Wo = (const float*)d_in[4];
    const float* nk = (const float*)d_in[5];
    const float* nv = (const float*)d_in[6];
    const float* ls = (const float*)d_in[7];
    float* out = (float*)d_out;

    dim3 ggrid(C_ / 128, M_ / 128);   // (8, 64)
    dim3 gblk(256);

    sgemm_kernel<<<ggrid, gblk>>>(x, Wq, nullptr, 0, 0);   // Q
    sgemm_kernel<<<ggrid, gblk>>>(x, Wk, nullptr, 0, 1);   // K
    sgemm_kernel<<<ggrid, gblk>>>(x, Wv, nullptr, 0, 2);   // V
    attn_kernel<<<dim3(T_ / 128, B_ * H_), 128>>>(nk, nv, ls);
    sgemm_kernel<<<ggrid, gblk>>>(nullptr, Wo, out, 1, 3); // out proj
}

// round 3
// speedup vs baseline: 1.3914x; 1.3914x over previous
#include <cuda_runtime.h>
#include <cuda_bf16.h>
#include <cstdint>
#include <math.h>

// Problem constants
#define B_ 4
#define T_ 2048
#define C_ 1024
#define H_ 16
#define D_ 64
#define M_ (B_*T_)   // 8192
#define N_ 1024
#define K_ 1024

// Scratch (device globals: allocation-free).
__device__ float g_q[(size_t)M_ * C_];
__device__ float g_k[(size_t)M_ * C_];
__device__ float g_v[(size_t)M_ * C_];
__device__ __nv_bfloat16 g_xhi[(size_t)M_ * C_];
__device__ __nv_bfloat16 g_xlo[(size_t)M_ * C_];
__device__ __nv_bfloat16 g_yhi[(size_t)M_ * C_];
__device__ __nv_bfloat16 g_ylo[(size_t)M_ * C_];
__device__ __nv_bfloat16 g_whi[4u * 1024u * 1024u];  // transposed [N,K] x4
__device__ __nv_bfloat16 g_wlo[4u * 1024u * 1024u];

__device__ __forceinline__ uint32_t smem_u32(const void* p) {
    uint32_t a;
    asm("{ .reg .u64 t; cvta.to.shared.u64 t, %1; cvt.u32.u64 %0, t; }" : "=r"(a) : "l"(p));
    return a;
}

#define LDSM4(r0, r1, r2, r3, a) \
    asm volatile("ldmatrix.sync.aligned.m8n8.x4.shared.b16 {%0,%1,%2,%3}, [%4];" \
        : "=r"(r0), "=r"(r1), "=r"(r2), "=r"(r3) : "r"(a))

#define MMA_BF16(c, a, b0, b1) \
    asm volatile("mma.sync.aligned.m16n8k16.row.col.f32.bf16.bf16.f32 " \
        "{%0,%1,%2,%3}, {%4,%5,%6,%7}, {%8,%9}, {%0,%1,%2,%3};" \
        : "+f"((c)[0]), "+f"((c)[1]), "+f"((c)[2]), "+f"((c)[3]) \
        : "r"((a)[0]), "r"((a)[1]), "r"((a)[2]), "r"((a)[3]), "r"(b0), "r"(b1))

// ---------------------------------------------------------------------------
// split: fp32 -> bf16 hi + bf16 lo (residual), elementwise, 4 per thread
// ---------------------------------------------------------------------------
__global__ void __launch_bounds__(256) split_kernel(
    const float* __restrict__ in, __nv_bfloat16* __restrict__ hi,
    __nv_bfloat16* __restrict__ lo)
{
    int i = (blockIdx.x * 256 + threadIdx.x) * 4;
    float4 v = *(const float4*)(in + i);
    __nv_bfloat162 h0 = __floats2bfloat162_rn(v.x, v.y);
    __nv_bfloat162 h1 = __floats2bfloat162_rn(v.z, v.w);
    float2 r0 = make_float2(v.x - __bfloat162float(h0.x), v.y - __bfloat162float(h0.y));
    float2 r1 = make_float2(v.z - __bfloat162float(h1.x), v.w - __bfloat162float(h1.y));
    ((__nv_bfloat162*)(hi + i))[0] = h0;
    ((__nv_bfloat162*)(hi + i))[1] = h1;
    ((__nv_bfloat162*)(lo + i))[0] = __floats2bfloat162_rn(r0.x, r0.y);
    ((__nv_bfloat162*)(lo + i))[1] = __floats2bfloat162_rn(r1.x, r1.y);
}

// ---------------------------------------------------------------------------
// transpose + split: W [K,N] fp32 row-major -> g_whi/g_wlo + widx*1M as [N,K] bf16
// ---------------------------------------------------------------------------
__global__ void __launch_bounds__(256) tsplit_kernel(const float* __restrict__ in, int widx) {
    __shared__ float tile[32][33];
    __nv_bfloat16* oh = g_whi + (size_t)widx * 1024 * 1024;
    __nv_bfloat16* ol = g_wlo + (size_t)widx * 1024 * 1024;
    int tx = threadIdx.x, ty = threadIdx.y;
    int x = blockIdx.x * 32 + tx, y0 = blockIdx.y * 32;
#pragma unroll
    for (int j = 0; j < 32; j += 8) tile[ty + j][tx] = in[(size_t)(y0 + ty + j) * 1024 + x];
    __syncthreads();
    int x2 = blockIdx.y * 32 + tx, y2 = blockIdx.x * 32;
#pragma unroll
    for (int j = 0; j < 32; j += 8) {
        float v = tile[tx][ty + j];
        __nv_bfloat16 h = __float2bfloat16(v);
        oh[(size_t)(y2 + ty + j) * 1024 + x2] = h;
        ol[(size_t)(y2 + ty + j) * 1024 + x2] = __float2bfloat16(v - __bfloat162float(h));
    }
}

// ---------------------------------------------------------------------------
// bf16x3 mma.sync GEMM: C[M,N] = A @ Bt^T.  A hi/lo [M,K] bf16, Bt hi/lo [N,K] bf16.
// CTA 128x128x32, 256 threads, 8 warps (2x4), warp tile 64x32 (m16n8k16 frags).
// csel 0/1/2: scatter fp32 into g_q/g_k/g_v [B,H,T,D]; 3: row-major fp32 Cext.
// ---------------------------------------------------------------------------
#define SPAD 40   // padded row stride (bf16 elems); 80 bytes
#define HL_OFF (128 * SPAD * 2)  // bytes between hi and lo planes

__global__ void __launch_bounds__(256) gemm_bf16x3(
    const __nv_bfloat16* __restrict__ Ahi, const __nv_bfloat16* __restrict__ Alo,
    const __nv_bfloat16* __restrict__ Bhi, const __nv_bfloat16* __restrict__ Blo,
    float* __restrict__ Cext, int csel)
{
    __shared__ __align__(16) __nv_bfloat16 sA[2][128][SPAD];
    __shared__ __align__(16) __nv_bfloat16 sB[2][128][SPAD];

    const int tid = threadIdx.x;
    const int warp = tid >> 5, lane = tid & 31;
    const int bm = blockIdx.y * 128, bn = blockIdx.x * 128;
    const int wm = (warp >> 2) * 64, wn = (warp & 3) * 32;
    const uint32_t aBase = smem_u32(&sA[0][0][0]);
    const uint32_t bBase = smem_u32(&sB[0][0][0]);

    float acc[4][4][4];
#pragma unroll
    for (int i = 0; i < 4; i++)
#pragma unroll
        for (int j = 0; j < 4; j++)
#pragma unroll
            for (int r = 0; r < 4; r++) acc[i][j][r] = 0.f;

    // global load mapping: thread -> (row, 16-col chunk)
    const int lr = tid >> 1;
    const int lc = (tid & 1) << 4;
    const size_t aoff = (size_t)(bm + lr) * K_ + lc;
    const size_t boff = (size_t)(bn + lr) * K_ + lc;
    uint4 pf[8];

#define LDG_TILE(k0) do { \
    pf[0] = *(const uint4*)(Ahi + aoff + (k0));     \
    pf[1] = *(const uint4*)(Ahi + aoff + (k0) + 8); \
    pf[2] = *(const uint4*)(Alo + aoff + (k0));     \
    pf[3] = *(const uint4*)(Alo + aoff + (k0) + 8); \
    pf[4] = *(const uint4*)(Bhi + boff + (k0));     \
    pf[5] = *(const uint4*)(Bhi + boff + (k0) + 8); \
    pf[6] = *(const uint4*)(Blo + boff + (k0));     \
    pf[7] = *(const uint4*)(Blo + boff + (k0) + 8); \
} while (0)

#define STS_TILE() do { \
    *(uint4*)&sA[0][lr][lc]     = pf[0]; \
    *(uint4*)&sA[0][lr][lc + 8] = pf[1]; \
    *(uint4*)&sA[1][lr][lc]     = pf[2]; \
    *(uint4*)&sA[1][lr][lc + 8] = pf[3]; \
    *(uint4*)&sB[0][lr][lc]     = pf[4]; \
    *(uint4*)&sB[0][lr][lc + 8] = pf[5]; \
    *(uint4*)&sB[1][lr][lc]     = pf[6]; \
    *(uint4*)&sB[1][lr][lc + 8] = pf[7]; \
} while (0)

    LDG_TILE(0);
    STS_TILE();
    __syncthreads();

    for (int s = 0; s < 32; ++s) {
        if (s < 31) LDG_TILE((s + 1) * 32);

#pragma unroll
        for (int kk = 0; kk < 2; kk++) {
            const int ks = kk * 16;
            uint32_t ah[4][4], al[4][4], bh[8], bl[8];
#pragma unroll
            for (int i = 0; i < 4; i++) {
                uint32_t ad = aBase + (uint32_t)(wm + i * 16 + (lane & 15)) * (SPAD * 2)
                            + (uint32_t)(ks + ((lane >> 4) << 3)) * 2;
                LDSM4(ah[i][0], ah[i][1], ah[i][2], ah[i][3], ad);
                LDSM4(al[i][0], al[i][1], al[i][2], al[i][3], ad + HL_OFF);
            }
#pragma unroll
            for (int jb = 0; jb < 2; jb++) {
                uint32_t bd = bBase + (uint32_t)(wn + jb * 16 + ((lane >> 4) << 3) + (lane & 7)) * (SPAD * 2)
                            + (uint32_t)(ks + (lane & 8)) * 2;
                LDSM4(bh[jb * 4 + 0], bh[jb * 4 + 1], bh[jb * 4 + 2], bh[jb * 4 + 3], bd);
                LDSM4(bl[jb * 4 + 0], bl[jb * 4 + 1], bl[jb * 4 + 2], bl[jb * 4 + 3], bd + HL_OFF);
            }
#pragma unroll
            for (int i = 0; i < 4; i++)
#pragma unroll
                for (int j = 0; j < 4; j++) {
                    MMA_BF16(acc[i][j], ah[i], bh[j * 2], bh[j * 2 + 1]);
                    MMA_BF16(acc[i][j], ah[i], bl[j * 2], bl[j * 2 + 1]);
                    MMA_BF16(acc[i][j], al[i], bh[j * 2], bh[j * 2 + 1]);
                }
        }
        __syncthreads();
        if (s < 31) {
            STS_TILE();
            __syncthreads();
        }
    }

    // epilogue
    const int gr = lane >> 2;
    const int gc = (lane & 3) * 2;
    float* Co = (csel == 0) ? g_q : (csel == 1) ? g_k : (csel == 2) ? g_v : Cext;
#pragma unroll
    for (int i = 0; i < 4; i++)
#pragma unroll
        for (int j = 0; j < 4; j++) {
            int m0 = bm + wm + i * 16 + gr;
            int n0 = bn + wn + j * 8 + gc;
            if (csel < 3) {
#pragma unroll
                for (int hrow = 0; hrow < 2; hrow++) {
                    int m = m0 + hrow * 8;
                    int b = m >> 11, t = m & (T_ - 1);
                    int hh = n0 >> 6, d = n0 & 63;
                    *(float2*)&Co[((size_t)((b * H_ + hh) * T_ + t)) * D_ + d] =
                        make_float2(acc[i][j][hrow * 2], acc[i][j][hrow * 2 + 1]);
                }
            } else {
                *(float2*)&Co[(size_t)m0 * N_ + n0] = make_float2(acc[i][j][0], acc[i][j][1]);
                *(float2*)&Co[(size_t)(m0 + 8) * N_ + n0] = make_float2(acc[i][j][2], acc[i][j][3]);
            }
        }
}

// ---------------------------------------------------------------------------
// Causal flash attention with learned null-KV column.
// Epilogue now writes y as bf16 hi/lo for the final GEMM.
// ---------------------------------------------------------------------------
__global__ void __launch_bounds__(128) attn_kernel(
    const float* __restrict__ nullk, const float* __restrict__ nullv,
    const float* __restrict__ lscale)
{
    const int bh = blockIdx.y;
    const int h = bh & (H_ - 1);
    const int b = bh >> 4;
    const int r = blockIdx.x * 128 + threadIdx.x;

    const float scale = __expf(lscale[h]) * 0.125f;

    const float* qb = g_q + ((size_t)bh * T_ + r) * D_;
    float q[D_];
#pragma unroll
    for (int d = 0; d < D_; d++) q[d] = qb[d] * scale;

    float o[D_];
#pragma unroll
    for (int d = 0; d < D_; d++) o[d] = 0.f;
    float mv = -3.4e38f, l = 0.f;

    __shared__ __align__(16) float ks[64][64];
    __shared__ __align__(16) float vs[64][64];

    const float* kb = g_k + (size_t)bh * T_ * D_;
    const float* vb = g_v + (size_t)bh * T_ * D_;
    const int smax = blockIdx.x * 128 + 127;

    for (int s0 = 0; s0 <= smax; s0 += 64) {
        __syncthreads();
#pragma unroll
        for (int i = 0; i < 8; i++) {
            int idx = threadIdx.x + i * 128;
            ((float4*)ks)[idx] = ((const float4*)(kb + (size_t)s0 * D_))[idx];
            ((float4*)vs)[idx] = ((const float4*)(vb + (size_t)s0 * D_))[idx];
        }
        __syncthreads();

        const int jmax = min(64, r - s0 + 1);
        for (int j = 0; j < jmax; j++) {
            const float4* kr = (const float4*)&ks[j][0];
            float sa = 0.f, sb2 = 0.f, sc = 0.f, sd = 0.f;
#pragma unroll
            for (int d4 = 0; d4 < 16; d4 += 4) {
                float4 k0v = kr[d4 + 0];
                float4 k1v = kr[d4 + 1];
                float4 k2v = kr[d4 + 2];
                float4 k3v = kr[d4 + 3];
                sa += q[(d4+0)*4+0]*k0v.x + q[(d4+0)*4+1]*k0v.y + q[(d4+0)*4+2]*k0v.z + q[(d4+0)*4+3]*k0v.w;
                sb2 += q[(d4+1)*4+0]*k1v.x + q[(d4+1)*4+1]*k1v.y + q[(d4+1)*4+2]*k1v.z + q[(d4+1)*4+3]*k1v.w;
                sc += q[(d4+2)*4+0]*k2v.x + q[(d4+2)*4+1]*k2v.y + q[(d4+2)*4+2]*k2v.z + q[(d4+2)*4+3]*k2v.w;
                sd += q[(d4+3)*4+0]*k3v.x + q[(d4+3)*4+1]*k3v.y + q[(d4+3)*4+2]*k3v.z + q[(d4+3)*4+3]*k3v.w;
            }
            float s = (sa + sb2) + (sc + sd);

            if (s > mv) {
                float c = __expf(mv - s);
                l *= c;
#pragma unroll
                for (int d = 0; d < D_; d++) o[d] *= c;
                mv = s;
            }
            float p = __expf(s - mv);
            l += p;
            const float4* vr = (const float4*)&vs[j][0];
#pragma unroll
            for (int d4 = 0; d4 < 16; d4++) {
                float4 vv = vr[d4];
                o[d4*4+0] += p * vv.x;
                o[d4*4+1] += p * vv.y;
                o[d4*4+2] += p * vv.z;
                o[d4*4+3] += p * vv.w;
            }
        }
    }

    {
        const float* nk = nullk + h * D_;
        float s = 0.f;
#pragma unroll
        for (int d = 0; d < D_; d++) s += q[d] * nk[d];
        if (s > mv) {
            float c = __expf(mv - s);
            l *= c;
#pragma unroll
            for (int d = 0; d < D_; d++) o[d] *= c;
            mv = s;
        }
        float p = __expf(s - mv);
        l += p;
        const float* nv = nullv + h * D_;
#pragma unroll
        for (int d = 0; d < D_; d++) o[d] += p * nv[d];
    }

    const float inv = 1.f / l;
    __nv_bfloat16* yh = g_yhi + ((size_t)(b * T_ + r)) * C_ + h * D_;
    __nv_bfloat16* yl = g_ylo + ((size_t)(b * T_ + r)) * C_ + h * D_;
#pragma unroll
    for (int d = 0; d < D_; d++) {
        float val = o[d] * inv;
        __nv_bfloat16 hv = __float2bfloat16(val);
        yh[d] = hv;
        yl[d] = __float2bfloat16(val - __bfloat162float(hv));
    }
}

// ---------------------------------------------------------------------------
// kernel_launch
// Inputs: x, Wq, Wk, Wv, Wo, null_k, null_v, logit_scale
// ---------------------------------------------------------------------------
extern "C" void kernel_launch(void* const* d_in, const int* in_sizes, int n_in,
                              void* d_out, int out_size) {
    const float* x  = (const float*)d_in[0];
    const float* Wq = (const float*)d_in[1];
    const float* Wk = (const float*)d_in[2];
    const float* Wv = (const float*)d_in[3];
    const float* Wo = (const float*)d_in[4];
    const float* nk = (const float*)d_in[5];
    const float* nv = (const float*)d_in[6];
    const float* ls = (const float*)d_in[7];
    float* out = (float*)d_out;

    __nv_bfloat16 *xhi, *xlo, *yhi, *ylo, *whi, *wlo;
    cudaGetSymbolAddress((void**)&xhi, g_xhi);
    cudaGetSymbolAddress((void**)&xlo, g_xlo);
    cudaGetSymbolAddress((void**)&yhi, g_yhi);
    cudaGetSymbolAddress((void**)&ylo, g_ylo);
    cudaGetSymbolAddress((void**)&whi, g_whi);
    cudaGetSymbolAddress((void**)&wlo, g_wlo);

    // prep: split x; transpose+split weights
    split_kernel<<<(M_ * C_) / (256 * 4), 256>>>(x, xhi, xlo);
    dim3 tgrid(32, 32), tblk(32, 8);
    tsplit_kernel<<<tgrid, tblk>>>(Wq, 0);
    tsplit_kernel<<<tgrid, tblk>>>(Wk, 1);
    tsplit_kernel<<<tgrid, tblk>>>(Wv, 2);
    tsplit_kernel<<<tgrid, tblk>>>(Wo, 3);

    dim3 ggrid(N_ / 128, M_ / 128);   // (8, 64)
    const size_t WSZ = 1024u * 1024u;
    gemm_bf16x3<<<ggrid, 256>>>(xhi, xlo, whi + 0 * WSZ, wlo + 0 * WSZ, nullptr, 0);  // Q
    gemm_bf16x3<<<ggrid, 256>>>(xhi, xlo, whi + 1 * WSZ, wlo + 1 * WSZ, nullptr, 1);  // K
    gemm_bf16x3<<<ggrid, 256>>>(xhi, xlo, whi + 2 * WSZ, wlo + 2 * WSZ, nullptr, 2);  // V

    attn_kernel<<<dim3(T_ / 128, B_ * H_), 128>>>(nk, nv, ls);

    gemm_bf16x3<<<ggrid, 256>>>(yhi, ylo, whi + 3 * WSZ, wlo + 3 * WSZ, out, 3);      // out proj
}

// round 4
// speedup vs baseline: 2.8380x; 2.0397x over previous
#include <cuda_runtime.h>
#include <cuda_bf16.h>
#include <cstdint>
#include <math.h>

// Problem constants
#define B_ 4
#define T_ 2048
#define C_ 1024
#define H_ 16
#define D_ 64
#define M_ (B_*T_)   // 8192
#define N_ 1024
#define K_ 1024

// Scratch (device globals: allocation-free). All activations as bf16 hi/lo pairs.
__device__ __nv_bfloat16 g_xhi[(size_t)M_ * C_];
__device__ __nv_bfloat16 g_xlo[(size_t)M_ * C_];
__device__ __nv_bfloat16 g_qhi[(size_t)M_ * C_];
__device__ __nv_bfloat16 g_qlo[(size_t)M_ * C_];
__device__ __nv_bfloat16 g_khi[(size_t)M_ * C_];
__device__ __nv_bfloat16 g_klo[(size_t)M_ * C_];
__device__ __nv_bfloat16 g_vhi[(size_t)M_ * C_];
__device__ __nv_bfloat16 g_vlo[(size_t)M_ * C_];
__device__ __nv_bfloat16 g_yhi[(size_t)M_ * C_];
__device__ __nv_bfloat16 g_ylo[(size_t)M_ * C_];
__device__ __nv_bfloat16 g_whi[4u * 1024u * 1024u];  // transposed [N,K] x4
__device__ __nv_bfloat16 g_wlo[4u * 1024u * 1024u];

__device__ __forceinline__ uint32_t smem_u32(const void* p) {
    uint32_t a;
    asm("{ .reg .u64 t; cvta.to.shared.u64 t, %1; cvt.u32.u64 %0, t; }" : "=r"(a) : "l"(p));
    return a;
}

#define LDSM4(r0, r1, r2, r3, a) \
    asm volatile("ldmatrix.sync.aligned.m8n8.x4.shared.b16 {%0,%1,%2,%3}, [%4];" \
        : "=r"(r0), "=r"(r1), "=r"(r2), "=r"(r3) : "r"(a))
#define LDSM4T(r0, r1, r2, r3, a) \
    asm volatile("ldmatrix.sync.aligned.m8n8.x4.trans.shared.b16 {%0,%1,%2,%3}, [%4];" \
        : "=r"(r0), "=r"(r1), "=r"(r2), "=r"(r3) : "r"(a))

#define MMA_BF16(c, a, b0, b1) \
    asm volatile("mma.sync.aligned.m16n8k16.row.col.f32.bf16.bf16.f32 " \
        "{%0,%1,%2,%3}, {%4,%5,%6,%7}, {%8,%9}, {%0,%1,%2,%3};" \
        : "+f"((c)[0]), "+f"((c)[1]), "+f"((c)[2]), "+f"((c)[3]) \
        : "r"((a)[0]), "r"((a)[1]), "r"((a)[2]), "r"((a)[3]), "r"(b0), "r"(b1))

__device__ __forceinline__ float ex2(float x) {
    float r;
    asm("ex2.approx.ftz.f32 %0, %1;" : "=f"(r) : "f"(x));
    return r;
}

// pack (a,b) -> bf16x2 hi + residual bf16x2 lo
__device__ __forceinline__ void packpair(float a, float b, uint32_t& hi, uint32_t& lo) {
    __nv_bfloat162 h = __floats2bfloat162_rn(a, b);
    float2 hf = __bfloat1622float2(h);
    __nv_bfloat162 l = __floats2bfloat162_rn(a - hf.x, b - hf.y);
    hi = *(uint32_t*)&h;
    lo = *(uint32_t*)&l;
}

// ---------------------------------------------------------------------------
// split: fp32 -> bf16 hi + bf16 lo (residual), elementwise, 4 per thread
// ---------------------------------------------------------------------------
__global__ void __launch_bounds__(256) split_kernel(
    const float* __restrict__ in, __nv_bfloat16* __restrict__ hi,
    __nv_bfloat16* __restrict__ lo)
{
    int i = (blockIdx.x * 256 + threadIdx.x) * 4;
    float4 v = *(const float4*)(in + i);
    __nv_bfloat162 h0 = __floats2bfloat162_rn(v.x, v.y);
    __nv_bfloat162 h1 = __floats2bfloat162_rn(v.z, v.w);
    ((__nv_bfloat162*)(hi + i))[0] = h0;
    ((__nv_bfloat162*)(hi + i))[1] = h1;
    ((__nv_bfloat162*)(lo + i))[0] = __floats2bfloat162_rn(v.x - __bfloat162float(h0.x), v.y - __bfloat162float(h0.y));
    ((__nv_bfloat162*)(lo + i))[1] = __floats2bfloat162_rn(v.z - __bfloat162float(h1.x), v.w - __bfloat162float(h1.y));
}

// ---------------------------------------------------------------------------
// transpose + split: W [K,N] fp32 row-major -> g_whi/g_wlo + widx*1M as [N,K] bf16
// ---------------------------------------------------------------------------
__global__ void __launch_bounds__(256) tsplit_kernel(const float* __restrict__ in, int widx) {
    __shared__ float tile[32][33];
    __nv_bfloat16* oh = g_whi + (size_t)widx * 1024 * 1024;
    __nv_bfloat16* ol = g_wlo + (size_t)widx * 1024 * 1024;
    int tx = threadIdx.x, ty = threadIdx.y;
    int x = blockIdx.x * 32 + tx, y0 = blockIdx.y * 32;
#pragma unroll
    for (int j = 0; j < 32; j += 8) tile[ty + j][tx] = in[(size_t)(y0 + ty + j) * 1024 + x];
    __syncthreads();
    int x2 = blockIdx.y * 32 + tx, y2 = blockIdx.x * 32;
#pragma unroll
    for (int j = 0; j < 32; j += 8) {
        float v = tile[tx][ty + j];
        __nv_bfloat16 h = __float2bfloat16(v);
        oh[(size_t)(y2 + ty + j) * 1024 + x2] = h;
        ol[(size_t)(y2 + ty + j) * 1024 + x2] = __float2bfloat16(v - __bfloat162float(h));
    }
}

// ---------------------------------------------------------------------------
// bf16x3 mma.sync GEMM: C[M,N] = A @ Bt^T.
// csel 0: split-store bf16 hi/lo into Dhi/Dlo with [B,H,T,D] layout
// csel 1: fp32 row-major into Cext
// ---------------------------------------------------------------------------
#define SPAD 40
#define HL_OFF (128 * SPAD * 2)

__global__ void __launch_bounds__(256) gemm_bf16x3(
    const __nv_bfloat16* __restrict__ Ahi, const __nv_bfloat16* __restrict__ Alo,
    const __nv_bfloat16* __restrict__ Bhi, const __nv_bfloat16* __restrict__ Blo,
    float* __restrict__ Cext, __nv_bfloat16* __restrict__ Dhi,
    __nv_bfloat16* __restrict__ Dlo, int csel)
{
    __shared__ __align__(16) __nv_bfloat16 sA[2][128][SPAD];
    __shared__ __align__(16) __nv_bfloat16 sB[2][128][SPAD];

    const int tid = threadIdx.x;
    const int warp = tid >> 5, lane = tid & 31;
    const int bm = blockIdx.y * 128, bn = blockIdx.x * 128;
    const int wm = (warp >> 2) * 64, wn = (warp & 3) * 32;
    const uint32_t aBase = smem_u32(&sA[0][0][0]);
    const uint32_t bBase = smem_u32(&sB[0][0][0]);

    float acc[4][4][4];
#pragma unroll
    for (int i = 0; i < 4; i++)
#pragma unroll
        for (int j = 0; j < 4; j++)
#pragma unroll
            for (int r = 0; r < 4; r++) acc[i][j][r] = 0.f;

    const int lr = tid >> 1;
    const int lc = (tid & 1) << 4;
    const size_t aoff = (size_t)(bm + lr) * K_ + lc;
    const size_t boff = (size_t)(bn + lr) * K_ + lc;
    uint4 pf[8];

#define LDG_TILE(k0) do { \
    pf[0] = *(const uint4*)(Ahi + aoff + (k0));     \
    pf[1] = *(const uint4*)(Ahi + aoff + (k0) + 8); \
    pf[2] = *(const uint4*)(Alo + aoff + (k0));     \
    pf[3] = *(const uint4*)(Alo + aoff + (k0) + 8); \
    pf[4] = *(const uint4*)(Bhi + boff + (k0));     \
    pf[5] = *(const uint4*)(Bhi + boff + (k0) + 8); \
    pf[6] = *(const uint4*)(Blo + boff + (k0));     \
    pf[7] = *(const uint4*)(Blo + boff + (k0) + 8); \
} while (0)

#define STS_TILE() do { \
    *(uint4*)&sA[0][lr][lc]     = pf[0]; \
    *(uint4*)&sA[0][lr][lc + 8] = pf[1]; \
    *(uint4*)&sA[1][lr][lc]     = pf[2]; \
    *(uint4*)&sA[1][lr][lc + 8] = pf[3]; \
    *(uint4*)&sB[0][lr][lc]     = pf[4]; \
    *(uint4*)&sB[0][lr][lc + 8] = pf[5]; \
    *(uint4*)&sB[1][lr][lc]     = pf[6]; \
    *(uint4*)&sB[1][lr][lc + 8] = pf[7]; \
} while (0)

    LDG_TILE(0);
    STS_TILE();
    __syncthreads();

    for (int s = 0; s < 32; ++s) {
        if (s < 31) LDG_TILE((s + 1) * 32);

#pragma unroll
        for (int kk = 0; kk < 2; kk++) {
            const int ks = kk * 16;
            uint32_t ah[4][4], al[4][4], bh[8], bl[8];
#pragma unroll
            for (int i = 0; i < 4; i++) {
                uint32_t ad = aBase + (uint32_t)(wm + i * 16 + (lane & 15)) * (SPAD * 2)
                            + (uint32_t)(ks + ((lane >> 4) << 3)) * 2;
                LDSM4(ah[i][0], ah[i][1], ah[i][2], ah[i][3], ad);
                LDSM4(al[i][0], al[i][1], al[i][2], al[i][3], ad + HL_OFF);
            }
#pragma unroll
            for (int jb = 0; jb < 2; jb++) {
                uint32_t bd = bBase + (uint32_t)(wn + jb * 16 + ((lane >> 4) << 3) + (lane & 7)) * (SPAD * 2)
                            + (uint32_t)(ks + (lane & 8)) * 2;
                LDSM4(bh[jb * 4 + 0], bh[jb * 4 + 1], bh[jb * 4 + 2], bh[jb * 4 + 3], bd);
                LDSM4(bl[jb * 4 + 0], bl[jb * 4 + 1], bl[jb * 4 + 2], bl[jb * 4 + 3], bd + HL_OFF);
            }
#pragma unroll
            for (int i = 0; i < 4; i++)
#pragma unroll
                for (int j = 0; j < 4; j++) {
                    MMA_BF16(acc[i][j], ah[i], bh[j * 2], bh[j * 2 + 1]);
                    MMA_BF16(acc[i][j], ah[i], bl[j * 2], bl[j * 2 + 1]);
                    MMA_BF16(acc[i][j], al[i], bh[j * 2], bh[j * 2 + 1]);
                }
        }
        __syncthreads();
        if (s < 31) {
            STS_TILE();
            __syncthreads();
        }
    }

    // epilogue
    const int gr = lane >> 2;
    const int gc = (lane & 3) * 2;
#pragma unroll
    for (int i = 0; i < 4; i++)
#pragma unroll
        for (int j = 0; j < 4; j++) {
            int m0 = bm + wm + i * 16 + gr;
            int n0 = bn + wn + j * 8 + gc;
            if (csel == 0) {
                int hh = n0 >> 6, d = n0 & 63;
#pragma unroll
                for (int hrow = 0; hrow < 2; hrow++) {
                    int m = m0 + hrow * 8;
                    int b = m >> 11, t = m & (T_ - 1);
                    size_t idx = ((size_t)((b * H_ + hh) * T_ + t)) * D_ + d;
                    float v0 = acc[i][j][hrow * 2], v1 = acc[i][j][hrow * 2 + 1];
                    __nv_bfloat162 hv = __floats2bfloat162_rn(v0, v1);
                    float2 hf = __bfloat1622float2(hv);
                    *(__nv_bfloat162*)(Dhi + idx) = hv;
                    *(__nv_bfloat162*)(Dlo + idx) = __floats2bfloat162_rn(v0 - hf.x, v1 - hf.y);
                }
            } else {
                *(float2*)&Cext[(size_t)m0 * N_ + n0] = make_float2(acc[i][j][0], acc[i][j][1]);
                *(float2*)&Cext[(size_t)(m0 + 8) * N_ + n0] = make_float2(acc[i][j][2], acc[i][j][3]);
            }
        }
}

// ---------------------------------------------------------------------------
// Flash attention v2 with mma.sync bf16x3 and null-KV column.
// CTA: 64 query rows of one (b,h). 4 warps, warp = 16 rows.
// ---------------------------------------------------------------------------
#define AST 72
#define S_KH  0
#define S_KL  9216
#define S_VH  18432
#define S_VL  27648
#define S_QH  36864
#define S_QL  46080
#define S_NKH 55296
#define S_NKL 57600
#define S_NVH 59904
#define S_NVL 62208
#define S_ATT_TOTAL 64512

template <int NT>
__device__ __forceinline__ void online_update(float (*s)[4], float o[8][4],
    float& m0, float& m1, float& l0, float& l1)
{
    float tm0 = -1e30f, tm1 = -1e30f;
#pragma unroll
    for (int j = 0; j < NT; j++) {
        tm0 = fmaxf(tm0, fmaxf(s[j][0], s[j][1]));
        tm1 = fmaxf(tm1, fmaxf(s[j][2], s[j][3]));
    }
    tm0 = fmaxf(tm0, __shfl_xor_sync(0xffffffffu, tm0, 1));
    tm0 = fmaxf(tm0, __shfl_xor_sync(0xffffffffu, tm0, 2));
    tm1 = fmaxf(tm1, __shfl_xor_sync(0xffffffffu, tm1, 1));
    tm1 = fmaxf(tm1, __shfl_xor_sync(0xffffffffu, tm1, 2));
    float nm0 = fmaxf(m0, tm0), nm1 = fmaxf(m1, tm1);
    float c0 = ex2(m0 - nm0), c1 = ex2(m1 - nm1);
    m0 = nm0; m1 = nm1;
    l0 *= c0; l1 *= c1;
#pragma unroll
    for (int j = 0; j < NT; j++) {
        s[j][0] = ex2(s[j][0] - m0);
        s[j][1] = ex2(s[j][1] - m0);
        s[j][2] = ex2(s[j][2] - m1);
        s[j][3] = ex2(s[j][3] - m1);
        l0 += s[j][0] + s[j][1];
        l1 += s[j][2] + s[j][3];
    }
#pragma unroll
    for (int j = 0; j < 8; j++) {
        o[j][0] *= c0; o[j][1] *= c0; o[j][2] *= c1; o[j][3] *= c1;
    }
}

__global__ void __launch_bounds__(128) attn_mma(
    const float* __restrict__ nullk, const float* __restrict__ nullv,
    const float* __restrict__ lscale)
{
    extern __shared__ char sm[];
    const uint32_t sb = smem_u32(sm);
    const int bh = blockIdx.y, h = bh & 15;
    const int qb = (T_ / 64 - 1) - blockIdx.x;     // longest CTAs first
    const int tid = threadIdx.x, warp = tid >> 5, lane = tid & 31;
    const int wm = warp * 16;
    const float sc2 = __expf(lscale[h]) * 0.125f * 1.4426950408889634f;

    // null tiles: 16 rows x 64, row 0 = null data, rest zero (masked anyway)
    for (int i = tid; i < 1024; i += 128) {
        int r = i >> 6, d = i & 63;
        float kvk = (r == 0) ? nullk[h * 64 + d] : 0.f;
        float kvv = (r == 0) ? nullv[h * 64 + d] : 0.f;
        __nv_bfloat16 kh = __float2bfloat16(kvk);
        __nv_bfloat16 vh = __float2bfloat16(kvv);
        *(__nv_bfloat16*)(sm + S_NKH + (r * AST + d) * 2) = kh;
        *(__nv_bfloat16*)(sm + S_NKL + (r * AST + d) * 2) = __float2bfloat16(kvk - __bfloat162float(kh));
        *(__nv_bfloat16*)(sm + S_NVH + (r * AST + d) * 2) = vh;
        *(__nv_bfloat16*)(sm + S_NVL + (r * AST + d) * 2) = __float2bfloat16(kvv - __bfloat162float(vh));
    }

    // stage Q (64 rows x 64 cols, hi/lo)
    const int sr = tid >> 1, scol = (tid & 1) * 32;
    {
        const uint4* qh = (const uint4*)(g_qhi + ((size_t)bh * T_ + qb * 64 + sr) * D_ + scol);
        const uint4* ql = (const uint4*)(g_qlo + ((size_t)bh * T_ + qb * 64 + sr) * D_ + scol);
        uint4* dh = (uint4*)(sm + S_QH + (sr * AST + scol) * 2);
        uint4* dl = (uint4*)(sm + S_QL + (sr * AST + scol) * 2);
#pragma unroll
        for (int i = 0; i < 4; i++) { dh[i] = qh[i]; dl[i] = ql[i]; }
    }
    __syncthreads();

    // Q fragments (4 k-steps x 4 regs, hi and lo)
    uint32_t qfh[4][4], qfl[4][4];
#pragma unroll
    for (int kk = 0; kk < 4; kk++) {
        uint32_t ad = sb + S_QH + (uint32_t)((wm + (lane & 15)) * AST + kk * 16 + ((lane >> 4) << 3)) * 2;
        LDSM4(qfh[kk][0], qfh[kk][1], qfh[kk][2], qfh[kk][3], ad);
        LDSM4(qfl[kk][0], qfl[kk][1], qfl[kk][2], qfl[kk][3], ad + (S_QL - S_QH));
    }

    float o[8][4];
#pragma unroll
    for (int j = 0; j < 8; j++)
#pragma unroll
        for (int r = 0; r < 4; r++) o[j][r] = 0.f;
    float m0 = -1e30f, m1 = -1e30f, l0 = 0.f, l1 = 0.f;

    for (int kb = 0; kb <= qb; kb++) {
        __syncthreads();   // all warps done reading prev K/V
        {
            size_t base = ((size_t)bh * T_ + kb * 64 + sr) * D_ + scol;
            uint4* s0 = (uint4*)(sm + S_KH + (sr * AST + scol) * 2);
            uint4* s1 = (uint4*)(sm + S_KL + (sr * AST + scol) * 2);
            uint4* s2 = (uint4*)(sm + S_VH + (sr * AST + scol) * 2);
            uint4* s3 = (uint4*)(sm + S_VL + (sr * AST + scol) * 2);
#pragma unroll
            for (int i = 0; i < 4; i++) {
                s0[i] = ((const uint4*)(g_khi + base))[i];
                s1[i] = ((const uint4*)(g_klo + base))[i];
                s2[i] = ((const uint4*)(g_vhi + base))[i];
                s3[i] = ((const uint4*)(g_vlo + base))[i];
            }
        }
        __syncthreads();

        // S = Q K^T
        float s[8][4];
#pragma unroll
        for (int j = 0; j < 8; j++)
#pragma unroll
            for (int r = 0; r < 4; r++) s[j][r] = 0.f;
#pragma unroll
        for (int kk = 0; kk < 4; kk++) {
            uint32_t bhf[16], blf[16];
#pragma unroll
            for (int jb = 0; jb < 4; jb++) {
                uint32_t bd = sb + S_KH + (uint32_t)((jb * 16 + ((lane >> 4) << 3) + (lane & 7)) * AST
                            + kk * 16 + (lane & 8)) * 2;
                LDSM4(bhf[jb*4+0], bhf[jb*4+1], bhf[jb*4+2], bhf[jb*4+3], bd);
                LDSM4(blf[jb*4+0], blf[jb*4+1], blf[jb*4+2], blf[jb*4+3], bd + 9216);
            }
#pragma unroll
            for (int j = 0; j < 8; j++) {
                MMA_BF16(s[j], qfh[kk], bhf[j*2], bhf[j*2+1]);
                MMA_BF16(s[j], qfh[kk], blf[j*2], blf[j*2+1]);
                MMA_BF16(s[j], qfl[kk], bhf[j*2], bhf[j*2+1]);
            }
        }

        // scale (+ causal mask on diagonal block)
        if (kb == qb) {
            const int wr0 = wm + (lane >> 2), wr1 = wr0 + 8;
#pragma unroll
            for (int j = 0; j < 8; j++) {
                int c = j * 8 + ((lane & 3) << 1);
                s[j][0] = (c     <= wr0) ? s[j][0] * sc2 : -1e30f;
                s[j][1] = (c + 1 <= wr0) ? s[j][1] * sc2 : -1e30f;
                s[j][2] = (c     <= wr1) ? s[j][2] * sc2 : -1e30f;
                s[j][3] = (c + 1 <= wr1) ? s[j][3] * sc2 : -1e30f;
            }
        } else {
#pragma unroll
            for (int j = 0; j < 8; j++) {
                s[j][0] *= sc2; s[j][1] *= sc2; s[j][2] *= sc2; s[j][3] *= sc2;
            }
        }

        online_update<8>(s, o, m0, m1, l0, l1);

        // O += P V
#pragma unroll
        for (int kk = 0; kk < 4; kk++) {
            uint32_t ph[4], pl[4];
            packpair(s[2*kk][0],   s[2*kk][1],   ph[0], pl[0]);
            packpair(s[2*kk][2],   s[2*kk][3],   ph[1], pl[1]);
            packpair(s[2*kk+1][0], s[2*kk+1][1], ph[2], pl[2]);
            packpair(s[2*kk+1][2], s[2*kk+1][3], ph[3], pl[3]);
            uint32_t vhf[16], vlf[16];
#pragma unroll
            for (int g = 0; g < 4; g++) {
                uint32_t vd = sb + S_VH + (uint32_t)((kk * 16 + (lane & 15)) * AST
                            + g * 16 + ((lane >> 4) << 3)) * 2;
                LDSM4T(vhf[g*4+0], vhf[g*4+1], vhf[g*4+2], vhf[g*4+3], vd);
                LDSM4T(vlf[g*4+0], vlf[g*4+1], vlf[g*4+2], vlf[g*4+3], vd + 9216);
            }
#pragma unroll
            for (int j = 0; j < 8; j++) {
                MMA_BF16(o[j], ph, vhf[j*2], vhf[j*2+1]);
                MMA_BF16(o[j], ph, vlf[j*2], vlf[j*2+1]);
                MMA_BF16(o[j], pl, vhf[j*2], vhf[j*2+1]);
            }
        }
    }

    // null-KV block: 16 padded cols, only col 0 real
    {
        float s[2][4];
#pragma unroll
        for (int j = 0; j < 2; j++)
#pragma unroll
            for (int r = 0; r < 4; r++) s[j][r] = 0.f;
#pragma unroll
        for (int kk = 0; kk < 4; kk++) {
            uint32_t bhf[4], blf[4];
            uint32_t bd = sb + S_NKH + (uint32_t)((((lane >> 4) << 3) + (lane & 7)) * AST
                        + kk * 16 + (lane & 8)) * 2;
            LDSM4(bhf[0], bhf[1], bhf[2], bhf[3], bd);
            LDSM4(blf[0], blf[1], blf[2], blf[3], bd + 2304);
#pragma unroll
            for (int j = 0; j < 2; j++) {
                MMA_BF16(s[j], qfh[kk], bhf[j*2], bhf[j*2+1]);
                MMA_BF16(s[j], qfh[kk], blf[j*2], blf[j*2+1]);
                MMA_BF16(s[j], qfl[kk], bhf[j*2], bhf[j*2+1]);
            }
        }
#pragma unroll
        for (int j = 0; j < 2; j++) {
            int c = j * 8 + ((lane & 3) << 1);
            s[j][0] = (c == 0) ? s[j][0] * sc2 : -1e30f;
            s[j][1] = -1e30f;
            s[j][2] = (c == 0) ? s[j][2] * sc2 : -1e30f;
            s[j][3] = -1e30f;
        }
        online_update<2>(s, o, m0, m1, l0, l1);

        uint32_t ph[4], pl[4];
        packpair(s[0][0], s[0][1], ph[0], pl[0]);
        packpair(s[0][2], s[0][3], ph[1], pl[1]);
        packpair(s[1][0], s[1][1], ph[2], pl[2]);
        packpair(s[1][2], s[1][3], ph[3], pl[3]);
        uint32_t vhf[16], vlf[16];
#pragma unroll
        for (int g = 0; g < 4; g++) {
            uint32_t vd = sb + S_NVH + (uint32_t)((lane & 15) * AST + g * 16 + ((lane >> 4) << 3)) * 2;
            LDSM4T(vhf[g*4+0], vhf[g*4+1], vhf[g*4+2], vhf[g*4+3], vd);
            LDSM4T(vlf[g*4+0], vlf[g*4+1], vlf[g*4+2], vlf[g*4+3], vd + 2304);
        }
#pragma unroll
        for (int j = 0; j < 8; j++) {
            MMA_BF16(o[j], ph, vhf[j*2], vhf[j*2+1]);
            MMA_BF16(o[j], ph, vlf[j*2], vlf[j*2+1]);
            MMA_BF16(o[j], pl, vhf[j*2], vhf[j*2+1]);
        }
    }

    // finalize: quad-reduce l, normalize, write y as bf16 hi/lo [B,T,C]
    l0 += __shfl_xor_sync(0xffffffffu, l0, 1);
    l0 += __shfl_xor_sync(0xffffffffu, l0, 2);
    l1 += __shfl_xor_sync(0xffffffffu, l1, 1);
    l1 += __shfl_xor_sync(0xffffffffu, l1, 2);
    const float i0 = 1.f / l0, i1 = 1.f / l1;
    const int b = bh >> 4;
    const int t0 = qb * 64 + wm + (lane >> 2), t1 = t0 + 8;
    const int cb = h * 64 + ((lane & 3) << 1);
#pragma unroll
    for (int j = 0; j < 8; j++) {
        int cc = cb + j * 8;
        size_t i_0 = (size_t)(b * T_ + t0) * C_ + cc;
        size_t i_1 = (size_t)(b * T_ + t1) * C_ + cc;
        uint32_t hv, lv;
        packpair(o[j][0] * i0, o[j][1] * i0, hv, lv);
        *(uint32_t*)(g_yhi + i_0) = hv;
        *(uint32_t*)(g_ylo + i_0) = lv;
        packpair(o[j][2] * i1, o[j][3] * i1, hv, lv);
        *(uint32_t*)(g_yhi + i_1) = hv;
        *(uint32_t*)(g_ylo + i_1) = lv;
    }
}

// ---------------------------------------------------------------------------
// kernel_launch
// Inputs: x, Wq, Wk, Wv, Wo, null_k, null_v, logit_scale
// ---------------------------------------------------------------------------
extern "C" void kernel_launch(void* const* d_in, const int* in_sizes, int n_in,
                              void* d_out, int out_size) {
    const float* x  = (const float*)d_in[0];
    const float* Wq = (const float*)d_in[1];
    const float* Wk = (const float*)d_in[2];
    const float* Wv = (const float*)d_in[3];
    const float* Wo = (const float*)d_in[4];
    const float* nk = (const float*)d_in[5];
    const float* nv = (const float*)d_in[6];
    const float* ls = (const float*)d_in[7];
    float* out = (float*)d_out;

    __nv_bfloat16 *xhi, *xlo, *yhi, *ylo, *whi, *wlo;
    __nv_bfloat16 *qhi, *qlo, *khi, *klo, *vhi, *vlo;
    cudaGetSymbolAddress((void**)&xhi, g_xhi);
    cudaGetSymbolAddress((void**)&xlo, g_xlo);
    cudaGetSymbolAddress((void**)&yhi, g_yhi);
    cudaGetSymbolAddress((void**)&ylo, g_ylo);
    cudaGetSymbolAddress((void**)&whi, g_whi);
    cudaGetSymbolAddress((void**)&wlo, g_wlo);
    cudaGetSymbolAddress((void**)&qhi, g_qhi);
    cudaGetSymbolAddress((void**)&qlo, g_qlo);
    cudaGetSymbolAddress((void**)&khi, g_khi);
    cudaGetSymbolAddress((void**)&klo, g_klo);
    cudaGetSymbolAddress((void**)&vhi, g_vhi);
    cudaGetSymbolAddress((void**)&vlo, g_vlo);

    cudaFuncSetAttribute(attn_mma, cudaFuncAttributeMaxDynamicSharedMemorySize, S_ATT_TOTAL);

    // prep
    split_kernel<<<(M_ * C_) / (256 * 4), 256>>>(x, xhi, xlo);
    dim3 tgrid(32, 32), tblk(32, 8);
    tsplit_kernel<<<tgrid, tblk>>>(Wq, 0);
    tsplit_kernel<<<tgrid, tblk>>>(Wk, 1);
    tsplit_kernel<<<tgrid, tblk>>>(Wv, 2);
    tsplit_kernel<<<tgrid, tblk>>>(Wo, 3);

    dim3 ggrid(N_ / 128, M_ / 128);
    const size_t WSZ = 1024u * 1024u;
    gemm_bf16x3<<<ggrid, 256>>>(xhi, xlo, whi + 0*WSZ, wlo + 0*WSZ, nullptr, qhi, qlo, 0);
    gemm_bf16x3<<<ggrid, 256>>>(xhi, xlo, whi + 1*WSZ, wlo + 1*WSZ, nullptr, khi, klo, 0);
    gemm_bf16x3<<<ggrid, 256>>>(xhi, xlo, whi + 2*WSZ, wlo + 2*WSZ, nullptr, vhi, vlo, 0);

    attn_mma<<<dim3(T_ / 64, B_ * H_), 128, S_ATT_TOTAL>>>(nk, nv, ls);

    gemm_bf16x3<<<ggrid, 256>>>(yhi, ylo, whi + 3*WSZ, wlo + 3*WSZ, out, nullptr, nullptr, 1);
}

// round 5
// speedup vs baseline: 2.9035x; 1.0231x over previous
#include <cuda_runtime.h>
#include <cuda_bf16.h>
#include <cstdint>
#include <math.h>

// Problem constants
#define B_ 4
#define T_ 2048
#define C_ 1024
#define H_ 16
#define D_ 64
#define M_ (B_*T_)   // 8192
#define N_ 1024
#define K_ 1024

// Scratch (device globals: allocation-free). All activations as bf16 hi/lo pairs.
__device__ __nv_bfloat16 g_xhi[(size_t)M_ * C_];
__device__ __nv_bfloat16 g_xlo[(size_t)M_ * C_];
__device__ __nv_bfloat16 g_qhi[(size_t)M_ * C_];
__device__ __nv_bfloat16 g_qlo[(size_t)M_ * C_];
__device__ __nv_bfloat16 g_khi[(size_t)M_ * C_];
__device__ __nv_bfloat16 g_klo[(size_t)M_ * C_];
__device__ __nv_bfloat16 g_vhi[(size_t)M_ * C_];
__device__ __nv_bfloat16 g_vlo[(size_t)M_ * C_];
__device__ __nv_bfloat16 g_yhi[(size_t)M_ * C_];
__device__ __nv_bfloat16 g_ylo[(size_t)M_ * C_];
__device__ __nv_bfloat16 g_whi[4u * 1024u * 1024u];  // transposed [N,K]; rows 0-3071 = Wq|Wk|Wv, 3072+ = Wo
__device__ __nv_bfloat16 g_wlo[4u * 1024u * 1024u];

__device__ __forceinline__ uint32_t smem_u32(const void* p) {
    uint32_t a;
    asm("{ .reg .u64 t; cvta.to.shared.u64 t, %1; cvt.u32.u64 %0, t; }" : "=r"(a) : "l"(p));
    return a;
}

#define LDSM4(r0, r1, r2, r3, a) \
    asm volatile("ldmatrix.sync.aligned.m8n8.x4.shared.b16 {%0,%1,%2,%3}, [%4];" \
        : "=r"(r0), "=r"(r1), "=r"(r2), "=r"(r3) : "r"(a))
#define LDSM4T(r0, r1, r2, r3, a) \
    asm volatile("ldmatrix.sync.aligned.m8n8.x4.trans.shared.b16 {%0,%1,%2,%3}, [%4];" \
        : "=r"(r0), "=r"(r1), "=r"(r2), "=r"(r3) : "r"(a))

#define MMA_BF16(c, a, b0, b1) \
    asm volatile("mma.sync.aligned.m16n8k16.row.col.f32.bf16.bf16.f32 " \
        "{%0,%1,%2,%3}, {%4,%5,%6,%7}, {%8,%9}, {%0,%1,%2,%3};" \
        : "+f"((c)[0]), "+f"((c)[1]), "+f"((c)[2]), "+f"((c)[3]) \
        : "r"((a)[0]), "r"((a)[1]), "r"((a)[2]), "r"((a)[3]), "r"(b0), "r"(b1))

#define CP16(dst, src) \
    asm volatile("cp.async.cg.shared.global [%0], [%1], 16;" :: "r"(dst), "l"(src))
#define CPCOMMIT() asm volatile("cp.async.commit_group;" ::: "memory")
#define CPWAIT(n)  asm volatile("cp.async.wait_group %0;" :: "n"(n) : "memory")

__device__ __forceinline__ float ex2(float x) {
    float r;
    asm("ex2.approx.ftz.f32 %0, %1;" : "=f"(r) : "f"(x));
    return r;
}

__device__ __forceinline__ void packpair(float a, float b, uint32_t& hi, uint32_t& lo) {
    __nv_bfloat162 h = __floats2bfloat162_rn(a, b);
    float2 hf = __bfloat1622float2(h);
    __nv_bfloat162 l = __floats2bfloat162_rn(a - hf.x, b - hf.y);
    hi = *(uint32_t*)&h;
    lo = *(uint32_t*)&l;
}

// ---------------------------------------------------------------------------
// split: fp32 -> bf16 hi + bf16 lo residual
// ---------------------------------------------------------------------------
__global__ void __launch_bounds__(256) split_kernel(
    const float* __restrict__ in, __nv_bfloat16* __restrict__ hi,
    __nv_bfloat16* __restrict__ lo)
{
    int i = (blockIdx.x * 256 + threadIdx.x) * 4;
    float4 v = *(const float4*)(in + i);
    __nv_bfloat162 h0 = __floats2bfloat162_rn(v.x, v.y);
    __nv_bfloat162 h1 = __floats2bfloat162_rn(v.z, v.w);
    ((__nv_bfloat162*)(hi + i))[0] = h0;
    ((__nv_bfloat162*)(hi + i))[1] = h1;
    ((__nv_bfloat162*)(lo + i))[0] = __floats2bfloat162_rn(v.x - __bfloat162float(h0.x), v.y - __bfloat162float(h0.y));
    ((__nv_bfloat162*)(lo + i))[1] = __floats2bfloat162_rn(v.z - __bfloat162float(h1.x), v.w - __bfloat162float(h1.y));
}

// ---------------------------------------------------------------------------
// transpose + split all 4 weights; blockIdx.z selects the weight
// ---------------------------------------------------------------------------
__global__ void __launch_bounds__(256) tsplit4_kernel(
    const float* __restrict__ W0, const float* __restrict__ W1,
    const float* __restrict__ W2, const float* __restrict__ W3)
{
    __shared__ float tile[32][33];
    const int widx = blockIdx.z;
    const float* in = (widx == 0) ? W0 : (widx == 1) ? W1 : (widx == 2) ? W2 : W3;
    __nv_bfloat16* oh = g_whi + (size_t)widx * 1024 * 1024;
    __nv_bfloat16* ol = g_wlo + (size_t)widx * 1024 * 1024;
    int tx = threadIdx.x, ty = threadIdx.y;
    int x = blockIdx.x * 32 + tx, y0 = blockIdx.y * 32;
#pragma unroll
    for (int j = 0; j < 32; j += 8) tile[ty + j][tx] = in[(size_t)(y0 + ty + j) * 1024 + x];
    __syncthreads();
    int x2 = blockIdx.y * 32 + tx, y2 = blockIdx.x * 32;
#pragma unroll
    for (int j = 0; j < 32; j += 8) {
        float v = tile[tx][ty + j];
        __nv_bfloat16 h = __float2bfloat16(v);
        oh[(size_t)(y2 + ty + j) * 1024 + x2] = h;
        ol[(size_t)(y2 + ty + j) * 1024 + x2] = __float2bfloat16(v - __bfloat162float(h));
    }
}

// ---------------------------------------------------------------------------
// cp.async 4-stage bf16x3 GEMM: C[M,Ntot] = A @ Bt^T
// mode 0: fused QKV (Ntot=3072); scatter bf16 hi/lo to g_q/g_k/g_v [B,H,T,D]
// mode 1: out proj (Ntot=1024); fp32 row-major to Cext
// SMEM per stage (40960 B): Ahi[128][40] | Alo | Bhi[128][40] | Blo
// ---------------------------------------------------------------------------
#define SPAD 40
#define STG_BYTES 40960
#define PL 10240          // plane size (bytes)
#define NSTAGE 4
#define NT_K 32           // 1024/32 k-tiles

__global__ void __launch_bounds__(256) gemm_cp(
    const __nv_bfloat16* __restrict__ Ahi, const __nv_bfloat16* __restrict__ Alo,
    const __nv_bfloat16* __restrict__ Bhi, const __nv_bfloat16* __restrict__ Blo,
    float* __restrict__ Cext, int mode)
{
    extern __shared__ char gsm[];
    const uint32_t sb = smem_u32(gsm);
    const int tid = threadIdx.x;
    const int warp = tid >> 5, lane = tid & 31;
    const int bm = blockIdx.y * 128, bn = blockIdx.x * 128;
    const int wm = (warp >> 2) * 64, wn = (warp & 3) * 32;

    float acc[4][4][4];
#pragma unroll
    for (int i = 0; i < 4; i++)
#pragma unroll
        for (int j = 0; j < 4; j++)
#pragma unroll
            for (int r = 0; r < 4; r++) acc[i][j][r] = 0.f;

    // loader mapping: 256 threads; thread -> (row, 16-elem col chunk)
    const int lr = tid >> 1, lc = (tid & 1) << 4;
    const size_t aoff = (size_t)(bm + lr) * K_ + lc;
    const size_t boff = (size_t)(bn + lr) * K_ + lc;
    const uint32_t drow = sb + (uint32_t)lr * (SPAD * 2) + (uint32_t)lc * 2;

#define ISSUE(st, kt) do { \
    uint32_t d = drow + (uint32_t)(st) * STG_BYTES; \
    size_t k0 = (size_t)(kt) * 32; \
    CP16(d,                Ahi + aoff + k0); \
    CP16(d + 16,           Ahi + aoff + k0 + 8); \
    CP16(d + PL,           Alo + aoff + k0); \
    CP16(d + PL + 16,      Alo + aoff + k0 + 8); \
    CP16(d + 2*PL,         Bhi + boff + k0); \
    CP16(d + 2*PL + 16,    Bhi + boff + k0 + 8); \
    CP16(d + 3*PL,         Blo + boff + k0); \
    CP16(d + 3*PL + 16,    Blo + boff + k0 + 8); \
} while (0)

    // prologue: fill NSTAGE-1 stages
#pragma unroll
    for (int s = 0; s < NSTAGE - 1; s++) { ISSUE(s, s); CPCOMMIT(); }

    // ldmatrix address components (within a stage)
    const uint32_t aAddr = (uint32_t)((wm + (lane & 15)) * (SPAD * 2) + (((lane >> 4) << 3)) * 2);
    const uint32_t bAddr = (uint32_t)(2 * PL + (wn + ((lane >> 4) << 3) + (lane & 7)) * (SPAD * 2) + ((lane & 8)) * 2);

    for (int kt = 0; kt < NT_K; ++kt) {
        CPWAIT(NSTAGE - 2);
        __syncthreads();
        {
            int nt = kt + NSTAGE - 1;
            if (nt < NT_K) ISSUE(nt & (NSTAGE - 1), nt);
            CPCOMMIT();
        }
        const uint32_t stb = sb + (uint32_t)(kt & (NSTAGE - 1)) * STG_BYTES;

#pragma unroll
        for (int kk = 0; kk < 2; kk++) {
            const uint32_t ko = (uint32_t)(kk * 16 * 2);
            uint32_t ah[4][4], al[4][4], bh[8], bl[8];
#pragma unroll
            for (int i = 0; i < 4; i++) {
                uint32_t ad = stb + aAddr + (uint32_t)(i * 16 * SPAD * 2) + ko;
                LDSM4(ah[i][0], ah[i][1], ah[i][2], ah[i][3], ad);
                LDSM4(al[i][0], al[i][1], al[i][2], al[i][3], ad + PL);
            }
#pragma unroll
            for (int jb = 0; jb < 2; jb++) {
                uint32_t bd = stb + bAddr + (uint32_t)(jb * 16 * SPAD * 2) + ko;
                LDSM4(bh[jb*4+0], bh[jb*4+1], bh[jb*4+2], bh[jb*4+3], bd);
                LDSM4(bl[jb*4+0], bl[jb*4+1], bl[jb*4+2], bl[jb*4+3], bd + PL);
            }
#pragma unroll
            for (int i = 0; i < 4; i++)
#pragma unroll
                for (int j = 0; j < 4; j++) {
                    MMA_BF16(acc[i][j], ah[i], bh[j*2], bh[j*2+1]);
                    MMA_BF16(acc[i][j], ah[i], bl[j*2], bl[j*2+1]);
                    MMA_BF16(acc[i][j], al[i], bh[j*2], bh[j*2+1]);
                }
        }
        __syncthreads();
    }

    // epilogue
    const int gr = lane >> 2, gc = (lane & 3) * 2;
#pragma unroll
    for (int i = 0; i < 4; i++)
#pragma unroll
        for (int j = 0; j < 4; j++) {
            int m0 = bm + wm + i * 16 + gr;
            int n0 = bn + wn + j * 8 + gc;
            if (mode == 0) {
                int sel = n0 >> 10;
                __nv_bfloat16* Dhi = (sel == 0) ? g_qhi : (sel == 1) ? g_khi : g_vhi;
                __nv_bfloat16* Dlo = (sel == 0) ? g_qlo : (sel == 1) ? g_klo : g_vlo;
                int hh = (n0 >> 6) & 15, d = n0 & 63;
#pragma unroll
                for (int hrow = 0; hrow < 2; hrow++) {
                    int m = m0 + hrow * 8;
                    int b = m >> 11, t = m & (T_ - 1);
                    size_t idx = ((size_t)((b * H_ + hh) * T_ + t)) * D_ + d;
                    uint32_t hv, lv;
                    packpair(acc[i][j][hrow*2], acc[i][j][hrow*2+1], hv, lv);
                    *(uint32_t*)(Dhi + idx) = hv;
                    *(uint32_t*)(Dlo + idx) = lv;
                }
            } else {
                *(float2*)&Cext[(size_t)m0 * N_ + n0] = make_float2(acc[i][j][0], acc[i][j][1]);
                *(float2*)&Cext[(size_t)(m0 + 8) * N_ + n0] = make_float2(acc[i][j][2], acc[i][j][3]);
            }
        }
}

// ---------------------------------------------------------------------------
// Flash attention v2 with mma.sync bf16x3 and null-KV column (unchanged R4).
// ---------------------------------------------------------------------------
#define AST 72
#define S_KH  0
#define S_KL  9216
#define S_VH  18432
#define S_VL  27648
#define S_QH  36864
#define S_QL  46080
#define S_NKH 55296
#define S_NKL 57600
#define S_NVH 59904
#define S_NVL 62208
#define S_ATT_TOTAL 64512

template <int NT>
__device__ __forceinline__ void online_update(float (*s)[4], float o[8][4],
    float& m0, float& m1, float& l0, float& l1)
{
    float tm0 = -1e30f, tm1 = -1e30f;
#pragma unroll
    for (int j = 0; j < NT; j++) {
        tm0 = fmaxf(tm0, fmaxf(s[j][0], s[j][1]));
        tm1 = fmaxf(tm1, fmaxf(s[j][2], s[j][3]));
    }
    tm0 = fmaxf(tm0, __shfl_xor_sync(0xffffffffu, tm0, 1));
    tm0 = fmaxf(tm0, __shfl_xor_sync(0xffffffffu, tm0, 2));
    tm1 = fmaxf(tm1, __shfl_xor_sync(0xffffffffu, tm1, 1));
    tm1 = fmaxf(tm1, __shfl_xor_sync(0xffffffffu, tm1, 2));
    float nm0 = fmaxf(m0, tm0), nm1 = fmaxf(m1, tm1);
    float c0 = ex2(m0 - nm0), c1 = ex2(m1 - nm1);
    m0 = nm0; m1 = nm1;
    l0 *= c0; l1 *= c1;
#pragma unroll
    for (int j = 0; j < NT; j++) {
        s[j][0] = ex2(s[j][0] - m0);
        s[j][1] = ex2(s[j][1] - m0);
        s[j][2] = ex2(s[j][2] - m1);
        s[j][3] = ex2(s[j][3] - m1);
        l0 += s[j][0] + s[j][1];
        l1 += s[j][2] + s[j][3];
    }
#pragma unroll
    for (int j = 0; j < 8; j++) {
        o[j][0] *= c0; o[j][1] *= c0; o[j][2] *= c1; o[j][3] *= c1;
    }
}

__global__ void __launch_bounds__(128) attn_mma(
    const float* __restrict__ nullk, const float* __restrict__ nullv,
    const float* __restrict__ lscale)
{
    extern __shared__ char sm[];
    const uint32_t sb = smem_u32(sm);
    const int bh = blockIdx.y, h = bh & 15;
    const int qb = (T_ / 64 - 1) - blockIdx.x;
    const int tid = threadIdx.x, warp = tid >> 5, lane = tid & 31;
    const int wm = warp * 16;
    const float sc2 = __expf(lscale[h]) * 0.125f * 1.4426950408889634f;

    for (int i = tid; i < 1024; i += 128) {
        int r = i >> 6, d = i & 63;
        float kvk = (r == 0) ? nullk[h * 64 + d] : 0.f;
        float kvv = (r == 0) ? nullv[h * 64 + d] : 0.f;
        __nv_bfloat16 kh = __float2bfloat16(kvk);
        __nv_bfloat16 vh = __float2bfloat16(kvv);
        *(__nv_bfloat16*)(sm + S_NKH + (r * AST + d) * 2) = kh;
        *(__nv_bfloat16*)(sm + S_NKL + (r * AST + d) * 2) = __float2bfloat16(kvk - __bfloat162float(kh));
        *(__nv_bfloat16*)(sm + S_NVH + (r * AST + d) * 2) = vh;
        *(__nv_bfloat16*)(sm + S_NVL + (r * AST + d) * 2) = __float2bfloat16(kvv - __bfloat162float(vh));
    }

    const int sr = tid >> 1, scol = (tid & 1) * 32;
    {
        const uint4* qh = (const uint4*)(g_qhi + ((size_t)bh * T_ + qb * 64 + sr) * D_ + scol);
        const uint4* ql = (const uint4*)(g_qlo + ((size_t)bh * T_ + qb * 64 + sr) * D_ + scol);
        uint4* dh = (uint4*)(sm + S_QH + (sr * AST + scol) * 2);
        uint4* dl = (uint4*)(sm + S_QL + (sr * AST + scol) * 2);
#pragma unroll
        for (int i = 0; i < 4; i++) { dh[i] = qh[i]; dl[i] = ql[i]; }
    }
    __syncthreads();

    uint32_t qfh[4][4], qfl[4][4];
#pragma unroll
    for (int kk = 0; kk < 4; kk++) {
        uint32_t ad = sb + S_QH + (uint32_t)((wm + (lane & 15)) * AST + kk * 16 + ((lane >> 4) << 3)) * 2;
        LDSM4(qfh[kk][0], qfh[kk][1], qfh[kk][2], qfh[kk][3], ad);
        LDSM4(qfl[kk][0], qfl[kk][1], qfl[kk][2], qfl[kk][3], ad + (S_QL - S_QH));
    }

    float o[8][4];
#pragma unroll
    for (int j = 0; j < 8; j++)
#pragma unroll
        for (int r = 0; r < 4; r++) o[j][r] = 0.f;
    float m0 = -1e30f, m1 = -1e30f, l0 = 0.f, l1 = 0.f;

    for (int kb = 0; kb <= qb; kb++) {
        __syncthreads();
        {
            size_t base = ((size_t)bh * T_ + kb * 64 + sr) * D_ + scol;
            uint4* s0 = (uint4*)(sm + S_KH + (sr * AST + scol) * 2);
            uint4* s1 = (uint4*)(sm + S_KL + (sr * AST + scol) * 2);
            uint4* s2 = (uint4*)(sm + S_VH + (sr * AST + scol) * 2);
            uint4* s3 = (uint4*)(sm + S_VL + (sr * AST + scol) * 2);
#pragma unroll
            for (int i = 0; i < 4; i++) {
                s0[i] = ((const uint4*)(g_khi + base))[i];
                s1[i] = ((const uint4*)(g_klo + base))[i];
                s2[i] = ((const uint4*)(g_vhi + base))[i];
                s3[i] = ((const uint4*)(g_vlo + base))[i];
            }
        }
        __syncthreads();

        float s[8][4];
#pragma unroll
        for (int j = 0; j < 8; j++)
#pragma unroll
            for (int r = 0; r < 4; r++) s[j][r] = 0.f;
#pragma unroll
        for (int kk = 0; kk < 4; kk++) {
            uint32_t bhf[16], blf[16];
#pragma unroll
            for (int jb = 0; jb < 4; jb++) {
                uint32_t bd = sb + S_KH + (uint32_t)((jb * 16 + ((lane >> 4) << 3) + (lane & 7)) * AST
                            + kk * 16 + (lane & 8)) * 2;
                LDSM4(bhf[jb*4+0], bhf[jb*4+1], bhf[jb*4+2], bhf[jb*4+3], bd);
                LDSM4(blf[jb*4+0], blf[jb*4+1], blf[jb*4+2], blf[jb*4+3], bd + 9216);
            }
#pragma unroll
            for (int j = 0; j < 8; j++) {
                MMA_BF16(s[j], qfh[kk], bhf[j*2], bhf[j*2+1]);
                MMA_BF16(s[j], qfh[kk], blf[j*2], blf[j*2+1]);
                MMA_BF16(s[j], qfl[kk], bhf[j*2], bhf[j*2+1]);
            }
        }

        if (kb == qb) {
            const int wr0 = wm + (lane >> 2), wr1 = wr0 + 8;
#pragma unroll
            for (int j = 0; j < 8; j++) {
                int c = j * 8 + ((lane & 3) << 1);
                s[j][0] = (c     <= wr0) ? s[j][0] * sc2 : -1e30f;
                s[j][1] = (c + 1 <= wr0) ? s[j][1] * sc2 : -1e30f;
                s[j][2] = (c     <= wr1) ? s[j][2] * sc2 : -1e30f;
                s[j][3] = (c + 1 <= wr1) ? s[j][3] * sc2 : -1e30f;
            }
        } else {
#pragma unroll
            for (int j = 0; j < 8; j++) {
                s[j][0] *= sc2; s[j][1] *= sc2; s[j][2] *= sc2; s[j][3] *= sc2;
            }
        }

        online_update<8>(s, o, m0, m1, l0, l1);

#pragma unroll
        for (int kk = 0; kk < 4; kk++) {
            uint32_t ph[4], pl[4];
            packpair(s[2*kk][0],   s[2*kk][1],   ph[0], pl[0]);
            packpair(s[2*kk][2],   s[2*kk][3],   ph[1], pl[1]);
            packpair(s[2*kk+1][0], s[2*kk+1][1], ph[2], pl[2]);
            packpair(s[2*kk+1][2], s[2*kk+1][3], ph[3], pl[3]);
            uint32_t vhf[16], vlf[16];
#pragma unroll
            for (int g = 0; g < 4; g++) {
                uint32_t vd = sb + S_VH + (uint32_t)((kk * 16 + (lane & 15)) * AST
                            + g * 16 + ((lane >> 4) << 3)) * 2;
                LDSM4T(vhf[g*4+0], vhf[g*4+1], vhf[g*4+2], vhf[g*4+3], vd);
                LDSM4T(vlf[g*4+0], vlf[g*4+1], vlf[g*4+2], vlf[g*4+3], vd + 9216);
            }
#pragma unroll
            for (int j = 0; j < 8; j++) {
                MMA_BF16(o[j], ph, vhf[j*2], vhf[j*2+1]);
                MMA_BF16(o[j], ph, vlf[j*2], vlf[j*2+1]);
                MMA_BF16(o[j], pl, vhf[j*2], vhf[j*2+1]);
            }
        }
    }

    {
        float s[2][4];
#pragma unroll
        for (int j = 0; j < 2; j++)
#pragma unroll
            for (int r = 0; r < 4; r++) s[j][r] = 0.f;
#pragma unroll
        for (int kk = 0; kk < 4; kk++) {
            uint32_t bhf[4], blf[4];
            uint32_t bd = sb + S_NKH + (uint32_t)((((lane >> 4) << 3) + (lane & 7)) * AST
                        + kk * 16 + (lane & 8)) * 2;
            LDSM4(bhf[0], bhf[1], bhf[2], bhf[3], bd);
            LDSM4(blf[0], blf[1], blf[2], blf[3], bd + 2304);
#pragma unroll
            for (int j = 0; j < 2; j++) {
                MMA_BF16(s[j], qfh[kk], bhf[j*2], bhf[j*2+1]);
                MMA_BF16(s[j], qfh[kk], blf[j*2], blf[j*2+1]);
                MMA_BF16(s[j], qfl[kk], bhf[j*2], bhf[j*2+1]);
            }
        }
#pragma unroll
        for (int j = 0; j < 2; j++) {
            int c = j * 8 + ((lane & 3) << 1);
            s[j][0] = (c == 0) ? s[j][0] * sc2 : -1e30f;
            s[j][1] = -1e30f;
            s[j][2] = (c == 0) ? s[j][2] * sc2 : -1e30f;
            s[j][3] = -1e30f;
        }
        online_update<2>(s, o, m0, m1, l0, l1);

        uint32_t ph[4], pl[4];
        packpair(s[0][0], s[0][1], ph[0], pl[0]);
        packpair(s[0][2], s[0][3], ph[1], pl[1]);
        packpair(s[1][0], s[1][1], ph[2], pl[2]);
        packpair(s[1][2], s[1][3], ph[3], pl[3]);
        uint32_t vhf[16], vlf[16];
#pragma unroll
        for (int g = 0; g < 4; g++) {
            uint32_t vd = sb + S_NVH + (uint32_t)((lane & 15) * AST + g * 16 + ((lane >> 4) << 3)) * 2;
            LDSM4T(vhf[g*4+0], vhf[g*4+1], vhf[g*4+2], vhf[g*4+3], vd);
            LDSM4T(vlf[g*4+0], vlf[g*4+1], vlf[g*4+2], vlf[g*4+3], vd + 2304);
        }
#pragma unroll
        for (int j = 0; j < 8; j++) {
            MMA_BF16(o[j], ph, vhf[j*2], vhf[j*2+1]);
            MMA_BF16(o[j], ph, vlf[j*2], vlf[j*2+1]);
            MMA_BF16(o[j], pl, vhf[j*2], vhf[j*2+1]);
        }
    }

    l0 += __shfl_xor_sync(0xffffffffu, l0, 1);
    l0 += __shfl_xor_sync(0xffffffffu, l0, 2);
    l1 += __shfl_xor_sync(0xffffffffu, l1, 1);
    l1 += __shfl_xor_sync(0xffffffffu, l1, 2);
    const float i0 = 1.f / l0, i1 = 1.f / l1;
    const int b = bh >> 4;
    const int t0 = qb * 64 + wm + (lane >> 2), t1 = t0 + 8;
    const int cb = h * 64 + ((lane & 3) << 1);
#pragma unroll
    for (int j = 0; j < 8; j++) {
        int cc = cb + j * 8;
        size_t i_0 = (size_t)(b * T_ + t0) * C_ + cc;
        size_t i_1 = (size_t)(b * T_ + t1) * C_ + cc;
        uint32_t hv, lv;
        packpair(o[j][0] * i0, o[j][1] * i0, hv, lv);
        *(uint32_t*)(g_yhi + i_0) = hv;
        *(uint32_t*)(g_ylo + i_0) = lv;
        packpair(o[j][2] * i1, o[j][3] * i1, hv, lv);
        *(uint32_t*)(g_yhi + i_1) = hv;
        *(uint32_t*)(g_ylo + i_1) = lv;
    }
}

// ---------------------------------------------------------------------------
// kernel_launch
// Inputs: x, Wq, Wk, Wv, Wo, null_k, null_v, logit_scale
// ---------------------------------------------------------------------------
extern "C" void kernel_launch(void* const* d_in, const int* in_sizes, int n_in,
                              void* d_out, int out_size) {
    const float* x  = (const float*)d_in[0];
    const float* Wq = (const float*)d_in[1];
    const float* Wk = (const float*)d_in[2];
    const float* Wv = (const float*)d_in[3];
    const float* Wo = (const float*)d_in[4];
    const float* nk = (const float*)d_in[5];
    const float* nv = (const float*)d_in[6];
    const float* ls = (const float*)d_in[7];
    float* out = (float*)d_out;

    __nv_bfloat16 *xhi, *xlo, *yhi, *ylo, *whi, *wlo;
    cudaGetSymbolAddress((void**)&xhi, g_xhi);
    cudaGetSymbolAddress((void**)&xlo, g_xlo);
    cudaGetSymbolAddress((void**)&yhi, g_yhi);
    cudaGetSymbolAddress((void**)&ylo, g_ylo);
    cudaGetSymbolAddress((void**)&whi, g_whi);
    cudaGetSymbolAddress((void**)&wlo, g_wlo);

    const int GEMM_SMEM = NSTAGE * STG_BYTES;   // 160 KB
    cudaFuncSetAttribute(gemm_cp, cudaFuncAttributeMaxDynamicSharedMemorySize, GEMM_SMEM);
    cudaFuncSetAttribute(attn_mma, cudaFuncAttributeMaxDynamicSharedMemorySize, S_ATT_TOTAL);

    // prep
    split_kernel<<<(M_ * C_) / (256 * 4), 256>>>(x, xhi, xlo);
    tsplit4_kernel<<<dim3(32, 32, 4), dim3(32, 8)>>>(Wq, Wk, Wv, Wo);

    const size_t WSZ = 1024u * 1024u;
    // fused QKV GEMM: N = 3072
    gemm_cp<<<dim3(24, 64), 256, GEMM_SMEM>>>(xhi, xlo, whi, wlo, nullptr, 0);

    attn_mma<<<dim3(T_ / 64, B_ * H_), 128, S_ATT_TOTAL>>>(nk, nv, ls);

    // out projection: N = 1024
    gemm_cp<<<dim3(8, 64), 256, GEMM_SMEM>>>(yhi, ylo, whi + 3 * WSZ, wlo + 3 * WSZ, out, 1);
}

// round 7
// speedup vs baseline: 3.2971x; 1.1356x over previous
#include <cuda_runtime.h>
#include <cuda_bf16.h>
#include <cstdint>
#include <math.h>

// Problem constants
#define B_ 4
#define T_ 2048
#define C_ 1024
#define H_ 16
#define D_ 64
#define M_ (B_*T_)   // 8192
#define N_ 1024
#define K_ 1024

// Scratch (device globals: allocation-free). All activations as bf16 hi/lo pairs.
__device__ __nv_bfloat16 g_xhi[(size_t)M_ * C_];
__device__ __nv_bfloat16 g_xlo[(size_t)M_ * C_];
__device__ __nv_bfloat16 g_qhi[(size_t)M_ * C_];
__device__ __nv_bfloat16 g_qlo[(size_t)M_ * C_];
__device__ __nv_bfloat16 g_khi[(size_t)M_ * C_];
__device__ __nv_bfloat16 g_klo[(size_t)M_ * C_];
__device__ __nv_bfloat16 g_vhi[(size_t)M_ * C_];
__device__ __nv_bfloat16 g_vlo[(size_t)M_ * C_];
__device__ __nv_bfloat16 g_yhi[(size_t)M_ * C_];
__device__ __nv_bfloat16 g_ylo[(size_t)M_ * C_];
__device__ __nv_bfloat16 g_whi[4u * 1024u * 1024u];  // transposed [N,K]; rows 0-3071 = Wq|Wk|Wv, then Wo
__device__ __nv_bfloat16 g_wlo[4u * 1024u * 1024u];

__device__ __forceinline__ uint32_t smem_u32(const void* p) {
    uint32_t a;
    asm("{ .reg .u64 t; cvta.to.shared.u64 t, %1; cvt.u32.u64 %0, t; }" : "=r"(a) : "l"(p));
    return a;
}

#define LDSM4(r0, r1, r2, r3, a) \
    asm volatile("ldmatrix.sync.aligned.m8n8.x4.shared.b16 {%0,%1,%2,%3}, [%4];" \
        : "=r"(r0), "=r"(r1), "=r"(r2), "=r"(r3) : "r"(a))
#define LDSM4T(r0, r1, r2, r3, a) \
    asm volatile("ldmatrix.sync.aligned.m8n8.x4.trans.shared.b16 {%0,%1,%2,%3}, [%4];" \
        : "=r"(r0), "=r"(r1), "=r"(r2), "=r"(r3) : "r"(a))

#define MMA_BF16(c, a, b0, b1) \
    asm volatile("mma.sync.aligned.m16n8k16.row.col.f32.bf16.bf16.f32 " \
        "{%0,%1,%2,%3}, {%4,%5,%6,%7}, {%8,%9}, {%0,%1,%2,%3};" \
        : "+f"((c)[0]), "+f"((c)[1]), "+f"((c)[2]), "+f"((c)[3]) \
        : "r"((a)[0]), "r"((a)[1]), "r"((a)[2]), "r"((a)[3]), "r"(b0), "r"(b1))

#define CP16(dst, src) \
    asm volatile("cp.async.cg.shared.global [%0], [%1], 16;" :: "r"(dst), "l"(src))
#define CPCOMMIT() asm volatile("cp.async.commit_group;" ::: "memory")
#define CPWAIT(n)  asm volatile("cp.async.wait_group %0;" :: "n"(n) : "memory")

__device__ __forceinline__ float ex2(float x) {
    float r;
    asm("ex2.approx.ftz.f32 %0, %1;" : "=f"(r) : "f"(x));
    return r;
}

__device__ __forceinline__ void packpair(float a, float b, uint32_t& hi, uint32_t& lo) {
    __nv_bfloat162 h = __floats2bfloat162_rn(a, b);
    float2 hf = __bfloat1622float2(h);
    __nv_bfloat162 l = __floats2bfloat162_rn(a - hf.x, b - hf.y);
    hi = *(uint32_t*)&h;
    lo = *(uint32_t*)&l;
}

// ---------------------------------------------------------------------------
// split: fp32 -> bf16 hi + bf16 lo residual
// ---------------------------------------------------------------------------
__global__ void __launch_bounds__(256) split_kernel(
    const float* __restrict__ in, __nv_bfloat16* __restrict__ hi,
    __nv_bfloat16* __restrict__ lo)
{
    int i = (blockIdx.x * 256 + threadIdx.x) * 4;
    float4 v = *(const float4*)(in + i);
    __nv_bfloat162 h0 = __floats2bfloat162_rn(v.x, v.y);
    __nv_bfloat162 h1 = __floats2bfloat162_rn(v.z, v.w);
    ((__nv_bfloat162*)(hi + i))[0] = h0;
    ((__nv_bfloat162*)(hi + i))[1] = h1;
    ((__nv_bfloat162*)(lo + i))[0] = __floats2bfloat162_rn(v.x - __bfloat162float(h0.x), v.y - __bfloat162float(h0.y));
    ((__nv_bfloat162*)(lo + i))[1] = __floats2bfloat162_rn(v.z - __bfloat162float(h1.x), v.w - __bfloat162float(h1.y));
}

// ---------------------------------------------------------------------------
// transpose + split all 4 weights; blockIdx.z selects the weight
// ---------------------------------------------------------------------------
__global__ void __launch_bounds__(256) tsplit4_kernel(
    const float* __restrict__ W0, const float* __restrict__ W1,
    const float* __restrict__ W2, const float* __restrict__ W3)
{
    __shared__ float tile[32][33];
    const int widx = blockIdx.z;
    const float* in = (widx == 0) ? W0 : (widx == 1) ? W1 : (widx == 2) ? W2 : W3;
    __nv_bfloat16* oh = g_whi + (size_t)widx * 1024 * 1024;
    __nv_bfloat16* ol = g_wlo + (size_t)widx * 1024 * 1024;
    int tx = threadIdx.x, ty = threadIdx.y;
    int x = blockIdx.x * 32 + tx, y0 = blockIdx.y * 32;
#pragma unroll
    for (int j = 0; j < 32; j += 8) tile[ty + j][tx] = in[(size_t)(y0 + ty + j) * 1024 + x];
    __syncthreads();
    int x2 = blockIdx.y * 32 + tx, y2 = blockIdx.x * 32;
#pragma unroll
    for (int j = 0; j < 32; j += 8) {
        float v = tile[tx][ty + j];
        __nv_bfloat16 h = __float2bfloat16(v);
        oh[(size_t)(y2 + ty + j) * 1024 + x2] = h;
        ol[(size_t)(y2 + ty + j) * 1024 + x2] = __float2bfloat16(v - __bfloat162float(h));
    }
}

// ---------------------------------------------------------------------------
// cp.async 2-stage bf16x3 GEMM (80KB smem -> 2 CTAs/SM, 16 warps)
// mode 0: fused QKV (Ntot=3072) -> scatter bf16 hi/lo to g_q/g_k/g_v [B,H,T,D]
// mode 1: out proj (Ntot=1024) -> fp32 row-major Cext
// ---------------------------------------------------------------------------
#define SPAD 40
#define STG_BYTES 40960
#define PL 10240
#define NSTAGE 2
#define NT_K 32

__global__ void __launch_bounds__(256, 2) gemm_cp(
    const __nv_bfloat16* __restrict__ Ahi, const __nv_bfloat16* __restrict__ Alo,
    const __nv_bfloat16* __restrict__ Bhi, const __nv_bfloat16* __restrict__ Blo,
    float* __restrict__ Cext, int mode)
{
    extern __shared__ char gsm[];
    const uint32_t sb = smem_u32(gsm);
    const int tid = threadIdx.x;
    const int warp = tid >> 5, lane = tid & 31;
    const int bm = blockIdx.y * 128, bn = blockIdx.x * 128;
    const int wm = (warp >> 2) * 64, wn = (warp & 3) * 32;

    float acc[4][4][4];
#pragma unroll
    for (int i = 0; i < 4; i++)
#pragma unroll
        for (int j = 0; j < 4; j++)
#pragma unroll
            for (int r = 0; r < 4; r++) acc[i][j][r] = 0.f;

    const int lr = tid >> 1, lc = (tid & 1) << 4;
    const size_t aoff = (size_t)(bm + lr) * K_ + lc;
    const size_t boff = (size_t)(bn + lr) * K_ + lc;
    const uint32_t drow = sb + (uint32_t)lr * (SPAD * 2) + (uint32_t)lc * 2;

#define ISSUE(st, kt) do { \
    uint32_t d = drow + (uint32_t)(st) * STG_BYTES; \
    size_t k0 = (size_t)(kt) * 32; \
    CP16(d,                Ahi + aoff + k0); \
    CP16(d + 16,           Ahi + aoff + k0 + 8); \
    CP16(d + PL,           Alo + aoff + k0); \
    CP16(d + PL + 16,      Alo + aoff + k0 + 8); \
    CP16(d + 2*PL,         Bhi + boff + k0); \
    CP16(d + 2*PL + 16,    Bhi + boff + k0 + 8); \
    CP16(d + 3*PL,         Blo + boff + k0); \
    CP16(d + 3*PL + 16,    Blo + boff + k0 + 8); \
} while (0)

    ISSUE(0, 0);
    CPCOMMIT();

    const uint32_t aAddr = (uint32_t)((wm + (lane & 15)) * (SPAD * 2) + (((lane >> 4) << 3)) * 2);
    const uint32_t bAddr = (uint32_t)(2 * PL + (wn + ((lane >> 4) << 3) + (lane & 7)) * (SPAD * 2) + ((lane & 8)) * 2);

    for (int kt = 0; kt < NT_K; ++kt) {
        {
            int nt = kt + 1;
            if (nt < NT_K) ISSUE(nt & 1, nt);
            CPCOMMIT();
        }
        CPWAIT(1);
        __syncthreads();
        const uint32_t stb = sb + (uint32_t)(kt & 1) * STG_BYTES;

#pragma unroll
        for (int kk = 0; kk < 2; kk++) {
            const uint32_t ko = (uint32_t)(kk * 16 * 2);
            uint32_t ah[4][4], al[4][4];
#pragma unroll
            for (int i = 0; i < 4; i++) {
                uint32_t ad = stb + aAddr + (uint32_t)(i * 16 * SPAD * 2) + ko;
                LDSM4(ah[i][0], ah[i][1], ah[i][2], ah[i][3], ad);
                LDSM4(al[i][0], al[i][1], al[i][2], al[i][3], ad + PL);
            }
#pragma unroll
            for (int jb = 0; jb < 2; jb++) {
                uint32_t bh[4], bl[4];
                uint32_t bd = stb + bAddr + (uint32_t)(jb * 16 * SPAD * 2) + ko;
                LDSM4(bh[0], bh[1], bh[2], bh[3], bd);
                LDSM4(bl[0], bl[1], bl[2], bl[3], bd + PL);
#pragma unroll
                for (int i = 0; i < 4; i++) {
                    MMA_BF16(acc[i][2*jb],   ah[i], bh[0], bh[1]);
                    MMA_BF16(acc[i][2*jb],   ah[i], bl[0], bl[1]);
                    MMA_BF16(acc[i][2*jb],   al[i], bh[0], bh[1]);
                    MMA_BF16(acc[i][2*jb+1], ah[i], bh[2], bh[3]);
                    MMA_BF16(acc[i][2*jb+1], ah[i], bl[2], bl[3]);
                    MMA_BF16(acc[i][2*jb+1], al[i], bh[2], bh[3]);
                }
            }
        }
        __syncthreads();
    }

    const int gr = lane >> 2, gc = (lane & 3) * 2;
#pragma unroll
    for (int i = 0; i < 4; i++)
#pragma unroll
        for (int j = 0; j < 4; j++) {
            int m0 = bm + wm + i * 16 + gr;
            int n0 = bn + wn + j * 8 + gc;
            if (mode == 0) {
                int sel = n0 >> 10;
                __nv_bfloat16* Dhi = (sel == 0) ? g_qhi : (sel == 1) ? g_khi : g_vhi;
                __nv_bfloat16* Dlo = (sel == 0) ? g_qlo : (sel == 1) ? g_klo : g_vlo;
                int hh = (n0 >> 6) & 15, d = n0 & 63;
#pragma unroll
                for (int hrow = 0; hrow < 2; hrow++) {
                    int m = m0 + hrow * 8;
                    int b = m >> 11, t = m & (T_ - 1);
                    size_t idx = ((size_t)((b * H_ + hh) * T_ + t)) * D_ + d;
                    uint32_t hv, lv;
                    packpair(acc[i][j][hrow*2], acc[i][j][hrow*2+1], hv, lv);
                    *(uint32_t*)(Dhi + idx) = hv;
                    *(uint32_t*)(Dlo + idx) = lv;
                }
            } else {
                *(float2*)&Cext[(size_t)m0 * N_ + n0] = make_float2(acc[i][j][0], acc[i][j][1]);
                *(float2*)&Cext[(size_t)(m0 + 8) * N_ + n0] = make_float2(acc[i][j][2], acc[i][j][3]);
            }
        }
}

// ---------------------------------------------------------------------------
// Flash attention v3: 256 threads, 128 q-rows/CTA, 8 warps x 16 rows.
// K/V tiles of 64 shared by all 8 warps; warp-uniform skip below diagonal.
// ---------------------------------------------------------------------------
#define AST 72
#define PL64  (64 * AST * 2)    // 9216
#define PL128 (128 * AST * 2)   // 18432
#define PL16  (16 * AST * 2)    // 2304
#define S_KH  0
#define S_KL  (S_KH + PL64)
#define S_VH  (S_KL + PL64)
#define S_VL  (S_VH + PL64)
#define S_QH  (S_VL + PL64)
#define S_QL  (S_QH + PL128)
#define S_NKH (S_QL + PL128)
#define S_NKL (S_NKH + PL16)
#define S_NVH (S_NKL + PL16)
#define S_NVL (S_NVH + PL16)
#define S_ATT_TOTAL (S_NVL + PL16)   // 82944

template <int NT>
__device__ __forceinline__ void online_update(float (*s)[4], float o[8][4],
    float& m0, float& m1, float& l0, float& l1)
{
    float tm0 = -1e30f, tm1 = -1e30f;
#pragma unroll
    for (int j = 0; j < NT; j++) {
        tm0 = fmaxf(tm0, fmaxf(s[j][0], s[j][1]));
        tm1 = fmaxf(tm1, fmaxf(s[j][2], s[j][3]));
    }
    tm0 = fmaxf(tm0, __shfl_xor_sync(0xffffffffu, tm0, 1));
    tm0 = fmaxf(tm0, __shfl_xor_sync(0xffffffffu, tm0, 2));
    tm1 = fmaxf(tm1, __shfl_xor_sync(0xffffffffu, tm1, 1));
    tm1 = fmaxf(tm1, __shfl_xor_sync(0xffffffffu, tm1, 2));
    float nm0 = fmaxf(m0, tm0), nm1 = fmaxf(m1, tm1);
    float c0 = ex2(m0 - nm0), c1 = ex2(m1 - nm1);
    m0 = nm0; m1 = nm1;
    l0 *= c0; l1 *= c1;
#pragma unroll
    for (int j = 0; j < NT; j++) {
        s[j][0] = ex2(s[j][0] - m0);
        s[j][1] = ex2(s[j][1] - m0);
        s[j][2] = ex2(s[j][2] - m1);
        s[j][3] = ex2(s[j][3] - m1);
        l0 += s[j][0] + s[j][1];
        l1 += s[j][2] + s[j][3];
    }
#pragma unroll
    for (int j = 0; j < 8; j++) {
        o[j][0] *= c0; o[j][1] *= c0; o[j][2] *= c1; o[j][3] *= c1;
    }
}

__global__ void __launch_bounds__(256, 2) attn_mma(
    const float* __restrict__ nullk, const float* __restrict__ nullv,
    const float* __restrict__ lscale)
{
    extern __shared__ char sm[];
    const uint32_t sb = smem_u32(sm);
    const int bh = blockIdx.y, h = bh & 15;
    const int qblk = (T_ / 128 - 1) - blockIdx.x;   // longest first
    const int qbase = qblk * 128;
    const int tid = threadIdx.x, warp = tid >> 5, lane = tid & 31;
    const int wm = warp * 16;
    const float sc2 = __expf(lscale[h]) * 0.125f * 1.4426950408889634f;

    // null tiles: 16 x 64, row 0 real
    for (int i = tid; i < 1024; i += 256) {
        int r = i >> 6, d = i & 63;
        float kvk = (r == 0) ? nullk[h * 64 + d] : 0.f;
        float kvv = (r == 0) ? nullv[h * 64 + d] : 0.f;
        __nv_bfloat16 kh = __float2bfloat16(kvk);
        __nv_bfloat16 vh = __float2bfloat16(kvv);
        *(__nv_bfloat16*)(sm + S_NKH + (r * AST + d) * 2) = kh;
        *(__nv_bfloat16*)(sm + S_NKL + (r * AST + d) * 2) = __float2bfloat16(kvk - __bfloat162float(kh));
        *(__nv_bfloat16*)(sm + S_NVH + (r * AST + d) * 2) = vh;
        *(__nv_bfloat16*)(sm + S_NVL + (r * AST + d) * 2) = __float2bfloat16(kvv - __bfloat162float(vh));
    }

    // stage Q: 128 rows x 64 cols hi/lo (256 threads: row=tid>>1, col chunk=(tid&1)*32)
    {
        const int sr = tid >> 1, scol = (tid & 1) * 32;
        const uint4* qh = (const uint4*)(g_qhi + ((size_t)bh * T_ + qbase + sr) * D_ + scol);
        const uint4* ql = (const uint4*)(g_qlo + ((size_t)bh * T_ + qbase + sr) * D_ + scol);
        uint4* dh = (uint4*)(sm + S_QH + (sr * AST + scol) * 2);
        uint4* dl = (uint4*)(sm + S_QL + (sr * AST + scol) * 2);
#pragma unroll
        for (int i = 0; i < 4; i++) { dh[i] = qh[i]; dl[i] = ql[i]; }
    }
    __syncthreads();

    uint32_t qfh[4][4], qfl[4][4];
#pragma unroll
    for (int kk = 0; kk < 4; kk++) {
        uint32_t ad = sb + S_QH + (uint32_t)((wm + (lane & 15)) * AST + kk * 16 + ((lane >> 4) << 3)) * 2;
        LDSM4(qfh[kk][0], qfh[kk][1], qfh[kk][2], qfh[kk][3], ad);
        LDSM4(qfl[kk][0], qfl[kk][1], qfl[kk][2], qfl[kk][3], ad + (S_QL - S_QH));
    }

    float o[8][4];
#pragma unroll
    for (int j = 0; j < 8; j++)
#pragma unroll
        for (int r = 0; r < 4; r++) o[j][r] = 0.f;
    float m0 = -1e30f, m1 = -1e30f, l0 = 0.f, l1 = 0.f;

    const int qmin_w = qbase + wm;
    const int qmax_w = qbase + wm + 15;
    const int nkb = (qbase + 128) / 64;

    // K/V staging map: row=tid>>2 (0..63), col chunk=(tid&3)*16 (two uint4 per plane)
    const int sr = tid >> 2, scol = (tid & 3) * 16;

    for (int kb = 0; kb < nkb; kb++) {
        __syncthreads();
        {
            size_t base = ((size_t)bh * T_ + kb * 64 + sr) * D_ + scol;
            uint32_t doff = (uint32_t)((sr * AST + scol) * 2);
            *(uint4*)(sm + S_KH + doff)      = *(const uint4*)(g_khi + base);
            *(uint4*)(sm + S_KH + doff + 16) = *(const uint4*)(g_khi + base + 8);
            *(uint4*)(sm + S_KL + doff)      = *(const uint4*)(g_klo + base);
            *(uint4*)(sm + S_KL + doff + 16) = *(const uint4*)(g_klo + base + 8);
            *(uint4*)(sm + S_VH + doff)      = *(const uint4*)(g_vhi + base);
            *(uint4*)(sm + S_VH + doff + 16) = *(const uint4*)(g_vhi + base + 8);
            *(uint4*)(sm + S_VL + doff)      = *(const uint4*)(g_vlo + base);
            *(uint4*)(sm + S_VL + doff + 16) = *(const uint4*)(g_vlo + base + 8);
        }
        __syncthreads();

        if (kb * 64 > qmax_w) continue;     // warp fully below diagonal: skip

        // S = Q K^T
        float s[8][4];
#pragma unroll
        for (int j = 0; j < 8; j++)
#pragma unroll
            for (int r = 0; r < 4; r++) s[j][r] = 0.f;
#pragma unroll
        for (int kk = 0; kk < 4; kk++) {
#pragma unroll
            for (int jb = 0; jb < 4; jb++) {
                uint32_t bhr[4], blr[4];
                uint32_t bd = sb + S_KH + (uint32_t)((jb * 16 + ((lane >> 4) << 3) + (lane & 7)) * AST
                            + kk * 16 + (lane & 8)) * 2;
                LDSM4(bhr[0], bhr[1], bhr[2], bhr[3], bd);
                LDSM4(blr[0], blr[1], blr[2], blr[3], bd + PL64);
                MMA_BF16(s[2*jb],   qfh[kk], bhr[0], bhr[1]);
                MMA_BF16(s[2*jb],   qfh[kk], blr[0], blr[1]);
                MMA_BF16(s[2*jb],   qfl[kk], bhr[0], bhr[1]);
                MMA_BF16(s[2*jb+1], qfh[kk], bhr[2], bhr[3]);
                MMA_BF16(s[2*jb+1], qfh[kk], blr[2], blr[3]);
                MMA_BF16(s[2*jb+1], qfl[kk], bhr[2], bhr[3]);
            }
        }

        // scale + causal mask
        if (kb * 64 + 63 > qmin_w) {
            const int q0 = qmin_w + (lane >> 2), q1 = q0 + 8;
#pragma unroll
            for (int j = 0; j < 8; j++) {
                int c = kb * 64 + j * 8 + ((lane & 3) << 1);
                s[j][0] = (c     <= q0) ? s[j][0] * sc2 : -1e30f;
                s[j][1] = (c + 1 <= q0) ? s[j][1] * sc2 : -1e30f;
                s[j][2] = (c     <= q1) ? s[j][2] * sc2 : -1e30f;
                s[j][3] = (c + 1 <= q1) ? s[j][3] * sc2 : -1e30f;
            }
        } else {
#pragma unroll
            for (int j = 0; j < 8; j++) {
                s[j][0] *= sc2; s[j][1] *= sc2; s[j][2] *= sc2; s[j][3] *= sc2;
            }
        }

        online_update<8>(s, o, m0, m1, l0, l1);

        // O += P V
#pragma unroll
        for (int kk = 0; kk < 4; kk++) {
            uint32_t ph[4], pl[4];
            packpair(s[2*kk][0],   s[2*kk][1],   ph[0], pl[0]);
            packpair(s[2*kk][2],   s[2*kk][3],   ph[1], pl[1]);
            packpair(s[2*kk+1][0], s[2*kk+1][1], ph[2], pl[2]);
            packpair(s[2*kk+1][2], s[2*kk+1][3], ph[3], pl[3]);
#pragma unroll
            for (int g = 0; g < 4; g++) {
                uint32_t vh[4], vl[4];
                uint32_t vd = sb + S_VH + (uint32_t)((kk * 16 + (lane & 15)) * AST
                            + g * 16 + ((lane >> 4) << 3)) * 2;
                LDSM4T(vh[0], vh[1], vh[2], vh[3], vd);
                LDSM4T(vl[0], vl[1], vl[2], vl[3], vd + PL64);
                MMA_BF16(o[2*g],   ph, vh[0], vh[1]);
                MMA_BF16(o[2*g],   ph, vl[0], vl[1]);
                MMA_BF16(o[2*g],   pl, vh[0], vh[1]);
                MMA_BF16(o[2*g+1], ph, vh[2], vh[3]);
                MMA_BF16(o[2*g+1], ph, vl[2], vl[3]);
                MMA_BF16(o[2*g+1], pl, vh[2], vh[3]);
            }
        }
    }

    // null-KV block (16 padded cols, col 0 real)
    {
        float s[2][4];
#pragma unroll
        for (int j = 0; j < 2; j++)
#pragma unroll
            for (int r = 0; r < 4; r++) s[j][r] = 0.f;
#pragma unroll
        for (int kk = 0; kk < 4; kk++) {
            uint32_t bhr[4], blr[4];
            uint32_t bd = sb + S_NKH + (uint32_t)((((lane >> 4) << 3) + (lane & 7)) * AST
                        + kk * 16 + (lane & 8)) * 2;
            LDSM4(bhr[0], bhr[1], bhr[2], bhr[3], bd);
            LDSM4(blr[0], blr[1], blr[2], blr[3], bd + PL16);
            MMA_BF16(s[0], qfh[kk], bhr[0], bhr[1]);
            MMA_BF16(s[0], qfh[kk], blr[0], blr[1]);
            MMA_BF16(s[0], qfl[kk], bhr[0], bhr[1]);
            MMA_BF16(s[1], qfh[kk], bhr[2], bhr[3]);
            MMA_BF16(s[1], qfh[kk], blr[2], blr[3]);
            MMA_BF16(s[1], qfl[kk], bhr[2], bhr[3]);
        }
#pragma unroll
        for (int j = 0; j < 2; j++) {
            int c = j * 8 + ((lane & 3) << 1);
            s[j][0] = (c == 0) ? s[j][0] * sc2 : -1e30f;
            s[j][1] = -1e30f;
            s[j][2] = (c == 0) ? s[j][2] * sc2 : -1e30f;
            s[j][3] = -1e30f;
        }
        online_update<2>(s, o, m0, m1, l0, l1);

        uint32_t ph[4], pl[4];
        packpair(s[0][0], s[0][1], ph[0], pl[0]);
        packpair(s[0][2], s[0][3], ph[1], pl[1]);
        packpair(s[1][0], s[1][1], ph[2], pl[2]);
        packpair(s[1][2], s[1][3], ph[3], pl[3]);
#pragma unroll
        for (int g = 0; g < 4; g++) {
            uint32_t vh[4], vl[4];
            uint32_t vd = sb + S_NVH + (uint32_t)((lane & 15) * AST + g * 16 + ((lane >> 4) << 3)) * 2;
            LDSM4T(vh[0], vh[1], vh[2], vh[3], vd);
            LDSM4T(vl[0], vl[1], vl[2], vl[3], vd + PL16);
            MMA_BF16(o[2*g],   ph, vh[0], vh[1]);
            MMA_BF16(o[2*g],   ph, vl[0], vl[1]);
            MMA_BF16(o[2*g],   pl, vh[0], vh[1]);
            MMA_BF16(o[2*g+1], ph, vh[2], vh[3]);
            MMA_BF16(o[2*g+1], ph, vl[2], vl[3]);
            MMA_BF16(o[2*g+1], pl, vh[2], vh[3]);
        }
    }

    // finalize
    l0 += __shfl_xor_sync(0xffffffffu, l0, 1);
    l0 += __shfl_xor_sync(0xffffffffu, l0, 2);
    l1 += __shfl_xor_sync(0xffffffffu, l1, 1);
    l1 += __shfl_xor_sync(0xffffffffu, l1, 2);
    const float i0 = 1.f / l0, i1 = 1.f / l1;
    const int b = bh >> 4;
    const int t0 = qbase + wm + (lane >> 2), t1 = t0 + 8;
    const int cb = h * 64 + ((lane & 3) << 1);
#pragma unroll
    for (int j = 0; j < 8; j++) {
        int cc = cb + j * 8;
        size_t i_0 = (size_t)(b * T_ + t0) * C_ + cc;
        size_t i_1 = (size_t)(b * T_ + t1) * C_ + cc;
        uint32_t hv, lv;
        packpair(o[j][0] * i0, o[j][1] * i0, hv, lv);
        *(uint32_t*)(g_yhi + i_0) = hv;
        *(uint32_t*)(g_ylo + i_0) = lv;
        packpair(o[j][2] * i1, o[j][3] * i1, hv, lv);
        *(uint32_t*)(g_yhi + i_1) = hv;
        *(uint32_t*)(g_ylo + i_1) = lv;
    }
}

// ---------------------------------------------------------------------------
// kernel_launch
// Inputs: x, Wq, Wk, Wv, Wo, null_k, null_v, logit_scale
// ---------------------------------------------------------------------------
extern "C" void kernel_launch(void* const* d_in, const int* in_sizes, int n_in,
                              void* d_out, int out_size) {
    const float* x  = (const float*)d_in[0];
    const float* Wq = (const float*)d_in[1];
    const float* Wk = (const float*)d_in[2];
    const float* Wv = (const float*)d_in[3];
    const float* Wo = (const float*)d_in[4];
    const float* nk = (const float*)d_in[5];
    const float* nv = (const float*)d_in[6];
    const float* ls = (const float*)d_in[7];
    float* out = (float*)d_out;

    __nv_bfloat16 *xhi, *xlo, *yhi, *ylo, *whi, *wlo;
    cudaGetSymbolAddress((void**)&xhi, g_xhi);
    cudaGetSymbolAddress((void**)&xlo, g_xlo);
    cudaGetSymbolAddress((void**)&yhi, g_yhi);
    cudaGetSymbolAddress((void**)&ylo, g_ylo);
    cudaGetSymbolAddress((void**)&whi, g_whi);
    cudaGetSymbolAddress((void**)&wlo, g_wlo);

    const int GEMM_SMEM = NSTAGE * STG_BYTES;   // 80 KB
    cudaFuncSetAttribute(gemm_cp, cudaFuncAttributeMaxDynamicSharedMemorySize, GEMM_SMEM);
    cudaFuncSetAttribute(attn_mma, cudaFuncAttributeMaxDynamicSharedMemorySize, S_ATT_TOTAL);

    split_kernel<<<(M_ * C_) / (256 * 4), 256>>>(x, xhi, xlo);
    tsplit4_kernel<<<dim3(32, 32, 4), dim3(32, 8)>>>(Wq, Wk, Wv, Wo);

    const size_t WSZ = 1024u * 1024u;
    gemm_cp<<<dim3(24, 64), 256, GEMM_SMEM>>>(xhi, xlo, whi, wlo, nullptr, 0);

    attn_mma<<<dim3(T_ / 128, B_ * H_), 256, S_ATT_TOTAL>>>(nk, nv, ls);

    gemm_cp<<<dim3(8, 64), 256, GEMM_SMEM>>>(yhi, ylo, whi + 3 * WSZ, wlo + 3 * WSZ, out, 1);
}

// round 8
// speedup vs baseline: 3.4120x; 1.0349x over previous
#include <cuda_runtime.h>
#include <cuda_bf16.h>
#include <cstdint>
#include <math.h>

// Problem constants
#define B_ 4
#define T_ 2048
#define C_ 1024
#define H_ 16
#define D_ 64
#define M_ (B_*T_)   // 8192
#define N_ 1024
#define K_ 1024

// Scratch (device globals: allocation-free). All activations as bf16 hi/lo pairs.
__device__ __nv_bfloat16 g_xhi[(size_t)M_ * C_];
__device__ __nv_bfloat16 g_xlo[(size_t)M_ * C_];
__device__ __nv_bfloat16 g_qhi[(size_t)M_ * C_];
__device__ __nv_bfloat16 g_qlo[(size_t)M_ * C_];
__device__ __nv_bfloat16 g_khi[(size_t)M_ * C_];
__device__ __nv_bfloat16 g_klo[(size_t)M_ * C_];
__device__ __nv_bfloat16 g_vhi[(size_t)M_ * C_];
__device__ __nv_bfloat16 g_vlo[(size_t)M_ * C_];
__device__ __nv_bfloat16 g_yhi[(size_t)M_ * C_];
__device__ __nv_bfloat16 g_ylo[(size_t)M_ * C_];
__device__ __nv_bfloat16 g_whi[4u * 1024u * 1024u];  // transposed [N,K]; rows 0-3071 = Wq|Wk|Wv, then Wo
__device__ __nv_bfloat16 g_wlo[4u * 1024u * 1024u];

__device__ __forceinline__ uint32_t smem_u32(const void* p) {
    uint32_t a;
    asm("{ .reg .u64 t; cvta.to.shared.u64 t, %1; cvt.u32.u64 %0, t; }" : "=r"(a) : "l"(p));
    return a;
}

#define LDSM4(r0, r1, r2, r3, a) \
    asm volatile("ldmatrix.sync.aligned.m8n8.x4.shared.b16 {%0,%1,%2,%3}, [%4];" \
        : "=r"(r0), "=r"(r1), "=r"(r2), "=r"(r3) : "r"(a))
#define LDSM4T(r0, r1, r2, r3, a) \
    asm volatile("ldmatrix.sync.aligned.m8n8.x4.trans.shared.b16 {%0,%1,%2,%3}, [%4];" \
        : "=r"(r0), "=r"(r1), "=r"(r2), "=r"(r3) : "r"(a))

#define MMA_BF16(c, a, b0, b1) \
    asm volatile("mma.sync.aligned.m16n8k16.row.col.f32.bf16.bf16.f32 " \
        "{%0,%1,%2,%3}, {%4,%5,%6,%7}, {%8,%9}, {%0,%1,%2,%3};" \
        : "+f"((c)[0]), "+f"((c)[1]), "+f"((c)[2]), "+f"((c)[3]) \
        : "r"((a)[0]), "r"((a)[1]), "r"((a)[2]), "r"((a)[3]), "r"(b0), "r"(b1))

#define CP16(dst, src) \
    asm volatile("cp.async.cg.shared.global [%0], [%1], 16;" :: "r"(dst), "l"(src))
#define CPCOMMIT() asm volatile("cp.async.commit_group;" ::: "memory")
#define CPWAIT(n)  asm volatile("cp.async.wait_group %0;" :: "n"(n) : "memory")

__device__ __forceinline__ float ex2(float x) {
    float r;
    asm("ex2.approx.ftz.f32 %0, %1;" : "=f"(r) : "f"(x));
    return r;
}

// precise split (rounding) for Q / y epilogue
__device__ __forceinline__ void packpair(float a, float b, uint32_t& hi, uint32_t& lo) {
    __nv_bfloat162 h = __floats2bfloat162_rn(a, b);
    float2 hf = __bfloat1622float2(h);
    __nv_bfloat162 l = __floats2bfloat162_rn(a - hf.x, b - hf.y);
    hi = *(uint32_t*)&h;
    lo = *(uint32_t*)&l;
}

// fast truncation split for P (values >= 0): pure ALU, no cvt
__device__ __forceinline__ void packtrunc(float a, float b, uint32_t& hi, uint32_t& lo) {
    uint32_t ba = __float_as_uint(a), bb = __float_as_uint(b);
    hi = __byte_perm(ba, bb, 0x7632);
    float ra = a - __uint_as_float(ba & 0xFFFF0000u);
    float rb = b - __uint_as_float(bb & 0xFFFF0000u);
    lo = __byte_perm(__float_as_uint(ra), __float_as_uint(rb), 0x7632);
}

// ---------------------------------------------------------------------------
// split: fp32 -> bf16 hi + bf16 lo residual
// ---------------------------------------------------------------------------
__global__ void __launch_bounds__(256) split_kernel(
    const float* __restrict__ in, __nv_bfloat16* __restrict__ hi,
    __nv_bfloat16* __restrict__ lo)
{
    int i = (blockIdx.x * 256 + threadIdx.x) * 4;
    float4 v = *(const float4*)(in + i);
    __nv_bfloat162 h0 = __floats2bfloat162_rn(v.x, v.y);
    __nv_bfloat162 h1 = __floats2bfloat162_rn(v.z, v.w);
    ((__nv_bfloat162*)(hi + i))[0] = h0;
    ((__nv_bfloat162*)(hi + i))[1] = h1;
    ((__nv_bfloat162*)(lo + i))[0] = __floats2bfloat162_rn(v.x - __bfloat162float(h0.x), v.y - __bfloat162float(h0.y));
    ((__nv_bfloat162*)(lo + i))[1] = __floats2bfloat162_rn(v.z - __bfloat162float(h1.x), v.w - __bfloat162float(h1.y));
}

// ---------------------------------------------------------------------------
// transpose + split all 4 weights; blockIdx.z selects the weight
// ---------------------------------------------------------------------------
__global__ void __launch_bounds__(256) tsplit4_kernel(
    const float* __restrict__ W0, const float* __restrict__ W1,
    const float* __restrict__ W2, const float* __restrict__ W3)
{
    __shared__ float tile[32][33];
    const int widx = blockIdx.z;
    const float* in = (widx == 0) ? W0 : (widx == 1) ? W1 : (widx == 2) ? W2 : W3;
    __nv_bfloat16* oh = g_whi + (size_t)widx * 1024 * 1024;
    __nv_bfloat16* ol = g_wlo + (size_t)widx * 1024 * 1024;
    int tx = threadIdx.x, ty = threadIdx.y;
    int x = blockIdx.x * 32 + tx, y0 = blockIdx.y * 32;
#pragma unroll
    for (int j = 0; j < 32; j += 8) tile[ty + j][tx] = in[(size_t)(y0 + ty + j) * 1024 + x];
    __syncthreads();
    int x2 = blockIdx.y * 32 + tx, y2 = blockIdx.x * 32;
#pragma unroll
    for (int j = 0; j < 32; j += 8) {
        float v = tile[tx][ty + j];
        __nv_bfloat16 h = __float2bfloat16(v);
        oh[(size_t)(y2 + ty + j) * 1024 + x2] = h;
        ol[(size_t)(y2 + ty + j) * 1024 + x2] = __float2bfloat16(v - __bfloat162float(h));
    }
}

// ---------------------------------------------------------------------------
// cp.async 2-stage bf16x3 GEMM (80KB smem -> 2 CTAs/SM) — unchanged from R7
// ---------------------------------------------------------------------------
#define SPAD 40
#define STG_BYTES 40960
#define PL 10240
#define NSTAGE 2
#define NT_K 32

__global__ void __launch_bounds__(256, 2) gemm_cp(
    const __nv_bfloat16* __restrict__ Ahi, const __nv_bfloat16* __restrict__ Alo,
    const __nv_bfloat16* __restrict__ Bhi, const __nv_bfloat16* __restrict__ Blo,
    float* __restrict__ Cext, int mode)
{
    extern __shared__ char gsm[];
    const uint32_t sb = smem_u32(gsm);
    const int tid = threadIdx.x;
    const int warp = tid >> 5, lane = tid & 31;
    const int bm = blockIdx.y * 128, bn = blockIdx.x * 128;
    const int wm = (warp >> 2) * 64, wn = (warp & 3) * 32;

    float acc[4][4][4];
#pragma unroll
    for (int i = 0; i < 4; i++)
#pragma unroll
        for (int j = 0; j < 4; j++)
#pragma unroll
            for (int r = 0; r < 4; r++) acc[i][j][r] = 0.f;

    const int lr = tid >> 1, lc = (tid & 1) << 4;
    const size_t aoff = (size_t)(bm + lr) * K_ + lc;
    const size_t boff = (size_t)(bn + lr) * K_ + lc;
    const uint32_t drow = sb + (uint32_t)lr * (SPAD * 2) + (uint32_t)lc * 2;

#define ISSUE(st, kt) do { \
    uint32_t d = drow + (uint32_t)(st) * STG_BYTES; \
    size_t k0 = (size_t)(kt) * 32; \
    CP16(d,                Ahi + aoff + k0); \
    CP16(d + 16,           Ahi + aoff + k0 + 8); \
    CP16(d + PL,           Alo + aoff + k0); \
    CP16(d + PL + 16,      Alo + aoff + k0 + 8); \
    CP16(d + 2*PL,         Bhi + boff + k0); \
    CP16(d + 2*PL + 16,    Bhi + boff + k0 + 8); \
    CP16(d + 3*PL,         Blo + boff + k0); \
    CP16(d + 3*PL + 16,    Blo + boff + k0 + 8); \
} while (0)

    ISSUE(0, 0);
    CPCOMMIT();

    const uint32_t aAddr = (uint32_t)((wm + (lane & 15)) * (SPAD * 2) + (((lane >> 4) << 3)) * 2);
    const uint32_t bAddr = (uint32_t)(2 * PL + (wn + ((lane >> 4) << 3) + (lane & 7)) * (SPAD * 2) + ((lane & 8)) * 2);

    for (int kt = 0; kt < NT_K; ++kt) {
        {
            int nt = kt + 1;
            if (nt < NT_K) ISSUE(nt & 1, nt);
            CPCOMMIT();
        }
        CPWAIT(1);
        __syncthreads();
        const uint32_t stb = sb + (uint32_t)(kt & 1) * STG_BYTES;

#pragma unroll
        for (int kk = 0; kk < 2; kk++) {
            const uint32_t ko = (uint32_t)(kk * 16 * 2);
            uint32_t ah[4][4], al[4][4];
#pragma unroll
            for (int i = 0; i < 4; i++) {
                uint32_t ad = stb + aAddr + (uint32_t)(i * 16 * SPAD * 2) + ko;
                LDSM4(ah[i][0], ah[i][1], ah[i][2], ah[i][3], ad);
                LDSM4(al[i][0], al[i][1], al[i][2], al[i][3], ad + PL);
            }
#pragma unroll
            for (int jb = 0; jb < 2; jb++) {
                uint32_t bh[4], bl[4];
                uint32_t bd = stb + bAddr + (uint32_t)(jb * 16 * SPAD * 2) + ko;
                LDSM4(bh[0], bh[1], bh[2], bh[3], bd);
                LDSM4(bl[0], bl[1], bl[2], bl[3], bd + PL);
#pragma unroll
                for (int i = 0; i < 4; i++) {
                    MMA_BF16(acc[i][2*jb],   ah[i], bh[0], bh[1]);
                    MMA_BF16(acc[i][2*jb],   ah[i], bl[0], bl[1]);
                    MMA_BF16(acc[i][2*jb],   al[i], bh[0], bh[1]);
                    MMA_BF16(acc[i][2*jb+1], ah[i], bh[2], bh[3]);
                    MMA_BF16(acc[i][2*jb+1], ah[i], bl[2], bl[3]);
                    MMA_BF16(acc[i][2*jb+1], al[i], bh[2], bh[3]);
                }
            }
        }
        __syncthreads();
    }

    const int gr = lane >> 2, gc = (lane & 3) * 2;
#pragma unroll
    for (int i = 0; i < 4; i++)
#pragma unroll
        for (int j = 0; j < 4; j++) {
            int m0 = bm + wm + i * 16 + gr;
            int n0 = bn + wn + j * 8 + gc;
            if (mode == 0) {
                int sel = n0 >> 10;
                __nv_bfloat16* Dhi = (sel == 0) ? g_qhi : (sel == 1) ? g_khi : g_vhi;
                __nv_bfloat16* Dlo = (sel == 0) ? g_qlo : (sel == 1) ? g_klo : g_vlo;
                int hh = (n0 >> 6) & 15, d = n0 & 63;
#pragma unroll
                for (int hrow = 0; hrow < 2; hrow++) {
                    int m = m0 + hrow * 8;
                    int b = m >> 11, t = m & (T_ - 1);
                    size_t idx = ((size_t)((b * H_ + hh) * T_ + t)) * D_ + d;
                    uint32_t hv, lv;
                    packpair(acc[i][j][hrow*2], acc[i][j][hrow*2+1], hv, lv);
                    *(uint32_t*)(Dhi + idx) = hv;
                    *(uint32_t*)(Dlo + idx) = lv;
                }
            } else {
                *(float2*)&Cext[(size_t)m0 * N_ + n0] = make_float2(acc[i][j][0], acc[i][j][1]);
                *(float2*)&Cext[(size_t)(m0 + 8) * N_ + n0] = make_float2(acc[i][j][2], acc[i][j][3]);
            }
        }
}

// ---------------------------------------------------------------------------
// Flash attention v4: 256 threads, 128 q-rows/CTA, 8 warps x 16 rows.
// No online max (bounded logits -> raw exp2, normalize at end).
// Q prescaled at frag load (direct from gmem, no Q smem).
// K/V: 2-stage cp.async double buffer.
// ---------------------------------------------------------------------------
#define AST 72
#define PL64  (64 * AST * 2)     // 9216
#define PL16  (16 * AST * 2)     // 2304
#define STAGE_B (4 * PL64)       // 36864: KH | KL | VH | VL
#define S_NULL  (2 * STAGE_B)    // 73728
#define S_NKH (S_NULL)
#define S_NKL (S_NULL + PL16)
#define S_NVH (S_NULL + 2*PL16)
#define S_NVL (S_NULL + 3*PL16)
#define S_ATT_TOTAL (S_NULL + 4*PL16)   // 82944

__global__ void __launch_bounds__(256, 2) attn_mma(
    const float* __restrict__ nullk, const float* __restrict__ nullv,
    const float* __restrict__ lscale)
{
    extern __shared__ char sm[];
    const uint32_t sb = smem_u32(sm);
    const int bh = blockIdx.y, h = bh & 15;
    const int qblk = (T_ / 128 - 1) - blockIdx.x;   // longest first
    const int qbase = qblk * 128;
    const int tid = threadIdx.x, warp = tid >> 5, lane = tid & 31;
    const int wm = warp * 16;
    const float sc2 = __expf(lscale[h]) * 0.125f * 1.4426950408889634f;

    // null tiles: 16 x 64, row 0 real
    for (int i = tid; i < 1024; i += 256) {
        int r = i >> 6, d = i & 63;
        float kvk = (r == 0) ? nullk[h * 64 + d] : 0.f;
        float kvv = (r == 0) ? nullv[h * 64 + d] : 0.f;
        __nv_bfloat16 kh = __float2bfloat16(kvk);
        __nv_bfloat16 vh = __float2bfloat16(kvv);
        *(__nv_bfloat16*)(sm + S_NKH + (r * AST + d) * 2) = kh;
        *(__nv_bfloat16*)(sm + S_NKL + (r * AST + d) * 2) = __float2bfloat16(kvk - __bfloat162float(kh));
        *(__nv_bfloat16*)(sm + S_NVH + (r * AST + d) * 2) = vh;
        *(__nv_bfloat16*)(sm + S_NVL + (r * AST + d) * 2) = __float2bfloat16(kvv - __bfloat162float(vh));
    }

    // Q fragments directly from gmem, prescaled by sc2, re-split hi/lo (rounding)
    uint32_t qfh[4][4], qfl[4][4];
    {
        const size_t qrow0 = (size_t)bh * T_ + qbase + wm + (lane >> 2);
        const int cc = (lane & 3) * 2;
#pragma unroll
        for (int kk = 0; kk < 4; kk++) {
#pragma unroll
            for (int rg = 0; rg < 4; rg++) {
                int roff = (rg & 1) * 8;
                int col = kk * 16 + cc + (rg >> 1) * 8;
                size_t idx = (qrow0 + roff) * D_ + col;
                __nv_bfloat162 a  = *(const __nv_bfloat162*)(g_qhi + idx);
                __nv_bfloat162 b2 = *(const __nv_bfloat162*)(g_qlo + idx);
                float2 fa = __bfloat1622float2(a), fb = __bfloat1622float2(b2);
                packpair((fa.x + fb.x) * sc2, (fa.y + fb.y) * sc2, qfh[kk][rg], qfl[kk][rg]);
            }
        }
    }

    float o[8][4];
#pragma unroll
    for (int j = 0; j < 8; j++)
#pragma unroll
        for (int r = 0; r < 4; r++) o[j][r] = 0.f;
    float l0 = 0.f, l1 = 0.f;

    const int qmin_w = qbase + wm;
    const int qmax_w = qbase + wm + 15;
    const int nkb = (qbase + 128) / 64;

    // K/V cp.async staging map: row=tid>>2 (0..63), col chunk=(tid&3)*16
    const int sr = tid >> 2, scol = (tid & 3) * 16;
    const uint32_t doff = (uint32_t)((sr * AST + scol) * 2);
    const size_t gbase0 = ((size_t)bh * T_ + sr) * D_ + scol;

#define AISS(st, kb_) do { \
    size_t base_ = gbase0 + (size_t)(kb_) * 64 * D_; \
    uint32_t d_ = sb + (uint32_t)(st) * STAGE_B + doff; \
    CP16(d_,                    g_khi + base_); \
    CP16(d_ + 16,               g_khi + base_ + 8); \
    CP16(d_ + PL64,             g_klo + base_); \
    CP16(d_ + PL64 + 16,        g_klo + base_ + 8); \
    CP16(d_ + 2*PL64,           g_vhi + base_); \
    CP16(d_ + 2*PL64 + 16,      g_vhi + base_ + 8); \
    CP16(d_ + 3*PL64,           g_vlo + base_); \
    CP16(d_ + 3*PL64 + 16,      g_vlo + base_ + 8); \
} while (0)

    AISS(0, 0);
    CPCOMMIT();

    for (int kb = 0; kb < nkb; kb++) {
        __syncthreads();                 // everyone done reading the other stage
        if (kb + 1 < nkb) AISS((kb + 1) & 1, kb + 1);
        CPCOMMIT();
        CPWAIT(1);
        __syncthreads();                 // stage kb visible to all
        if (kb * 64 > qmax_w) continue;  // warp fully below diagonal
        const uint32_t stb = sb + (uint32_t)(kb & 1) * STAGE_B;

        // S = Qs K^T  (Q prescaled)
        float s[8][4];
#pragma unroll
        for (int j = 0; j < 8; j++)
#pragma unroll
            for (int r = 0; r < 4; r++) s[j][r] = 0.f;
#pragma unroll
        for (int kk = 0; kk < 4; kk++) {
#pragma unroll
            for (int jb = 0; jb < 4; jb++) {
                uint32_t bhr[4], blr[4];
                uint32_t bd = stb + (uint32_t)((jb * 16 + ((lane >> 4) << 3) + (lane & 7)) * AST
                            + kk * 16 + (lane & 8)) * 2;
                LDSM4(bhr[0], bhr[1], bhr[2], bhr[3], bd);
                LDSM4(blr[0], blr[1], blr[2], blr[3], bd + PL64);
                MMA_BF16(s[2*jb],   qfh[kk], bhr[0], bhr[1]);
                MMA_BF16(s[2*jb],   qfh[kk], blr[0], blr[1]);
                MMA_BF16(s[2*jb],   qfl[kk], bhr[0], bhr[1]);
                MMA_BF16(s[2*jb+1], qfh[kk], bhr[2], bhr[3]);
                MMA_BF16(s[2*jb+1], qfh[kk], blr[2], blr[3]);
                MMA_BF16(s[2*jb+1], qfl[kk], bhr[2], bhr[3]);
            }
        }

        // causal mask (diagonal warp-block only; no scaling needed)
        if (kb * 64 + 63 > qmin_w) {
            const int q0 = qmin_w + (lane >> 2), q1 = q0 + 8;
#pragma unroll
            for (int j = 0; j < 8; j++) {
                int c = kb * 64 + j * 8 + ((lane & 3) << 1);
                if (c     > q0) s[j][0] = -1e30f;
                if (c + 1 > q0) s[j][1] = -1e30f;
                if (c     > q1) s[j][2] = -1e30f;
                if (c + 1 > q1) s[j][3] = -1e30f;
            }
        }

        // p = exp2(s) raw; accumulate l
#pragma unroll
        for (int j = 0; j < 8; j++) {
            s[j][0] = ex2(s[j][0]); s[j][1] = ex2(s[j][1]);
            s[j][2] = ex2(s[j][2]); s[j][3] = ex2(s[j][3]);
            l0 += s[j][0] + s[j][1];
            l1 += s[j][2] + s[j][3];
        }

        // O += P V
#pragma unroll
        for (int kk = 0; kk < 4; kk++) {
            uint32_t ph[4], pl[4];
            packtrunc(s[2*kk][0],   s[2*kk][1],   ph[0], pl[0]);
            packtrunc(s[2*kk][2],   s[2*kk][3],   ph[1], pl[1]);
            packtrunc(s[2*kk+1][0], s[2*kk+1][1], ph[2], pl[2]);
            packtrunc(s[2*kk+1][2], s[2*kk+1][3], ph[3], pl[3]);
#pragma unroll
            for (int g = 0; g < 4; g++) {
                uint32_t vh[4], vl[4];
                uint32_t vd = stb + 2*PL64 + (uint32_t)((kk * 16 + (lane & 15)) * AST
                            + g * 16 + ((lane >> 4) << 3)) * 2;
                LDSM4T(vh[0], vh[1], vh[2], vh[3], vd);
                LDSM4T(vl[0], vl[1], vl[2], vl[3], vd + PL64);
                MMA_BF16(o[2*g],   ph, vh[0], vh[1]);
                MMA_BF16(o[2*g],   ph, vl[0], vl[1]);
                MMA_BF16(o[2*g],   pl, vh[0], vh[1]);
                MMA_BF16(o[2*g+1], ph, vh[2], vh[3]);
                MMA_BF16(o[2*g+1], ph, vl[2], vl[3]);
                MMA_BF16(o[2*g+1], pl, vh[2], vh[3]);
            }
        }
    }

    // null-KV block (16 padded cols, col 0 real)
    {
        float s[2][4];
#pragma unroll
        for (int j = 0; j < 2; j++)
#pragma unroll
            for (int r = 0; r < 4; r++) s[j][r] = 0.f;
#pragma unroll
        for (int kk = 0; kk < 4; kk++) {
            uint32_t bhr[4], blr[4];
            uint32_t bd = sb + S_NKH + (uint32_t)((((lane >> 4) << 3) + (lane & 7)) * AST
                        + kk * 16 + (lane & 8)) * 2;
            LDSM4(bhr[0], bhr[1], bhr[2], bhr[3], bd);
            LDSM4(blr[0], blr[1], blr[2], blr[3], bd + PL16);
            MMA_BF16(s[0], qfh[kk], bhr[0], bhr[1]);
            MMA_BF16(s[0], qfh[kk], blr[0], blr[1]);
            MMA_BF16(s[0], qfl[kk], bhr[0], bhr[1]);
            MMA_BF16(s[1], qfh[kk], bhr[2], bhr[3]);
            MMA_BF16(s[1], qfh[kk], blr[2], blr[3]);
            MMA_BF16(s[1], qfl[kk], bhr[2], bhr[3]);
        }
#pragma unroll
        for (int j = 0; j < 2; j++) {
            int c = j * 8 + ((lane & 3) << 1);
            s[j][0] = (c == 0) ? ex2(s[j][0]) : 0.f;
            s[j][1] = 0.f;
            s[j][2] = (c == 0) ? ex2(s[j][2]) : 0.f;
            s[j][3] = 0.f;
            l0 += s[j][0];
            l1 += s[j][2];
        }

        uint32_t ph[4], pl[4];
        packtrunc(s[0][0], s[0][1], ph[0], pl[0]);
        packtrunc(s[0][2], s[0][3], ph[1], pl[1]);
        packtrunc(s[1][0], s[1][1], ph[2], pl[2]);
        packtrunc(s[1][2], s[1][3], ph[3], pl[3]);
#pragma unroll
        for (int g = 0; g < 4; g++) {
            uint32_t vh[4], vl[4];
            uint32_t vd = sb + S_NVH + (uint32_t)((lane & 15) * AST + g * 16 + ((lane >> 4) << 3)) * 2;
            LDSM4T(vh[0], vh[1], vh[2], vh[3], vd);
            LDSM4T(vl[0], vl[1], vl[2], vl[3], vd + PL16);
            MMA_BF16(o[2*g],   ph, vh[0], vh[1]);
            MMA_BF16(o[2*g],   ph, vl[0], vl[1]);
            MMA_BF16(o[2*g],   pl, vh[0], vh[1]);
            MMA_BF16(o[2*g+1], ph, vh[2], vh[3]);
            MMA_BF16(o[2*g+1], ph, vl[2], vl[3]);
            MMA_BF16(o[2*g+1], pl, vh[2], vh[3]);
        }
    }

    // finalize: quad-reduce l, normalize, write y bf16 hi/lo
    l0 += __shfl_xor_sync(0xffffffffu, l0, 1);
    l0 += __shfl_xor_sync(0xffffffffu, l0, 2);
    l1 += __shfl_xor_sync(0xffffffffu, l1, 1);
    l1 += __shfl_xor_sync(0xffffffffu, l1, 2);
    const float i0 = 1.f / l0, i1 = 1.f / l1;
    const int b = bh >> 4;
    const int t0 = qbase + wm + (lane >> 2), t1 = t0 + 8;
    const int cb = h * 64 + ((lane & 3) << 1);
#pragma unroll
    for (int j = 0; j < 8; j++) {
        int cc = cb + j * 8;
        size_t i_0 = (size_t)(b * T_ + t0) * C_ + cc;
        size_t i_1 = (size_t)(b * T_ + t1) * C_ + cc;
        uint32_t hv, lv;
        packpair(o[j][0] * i0, o[j][1] * i0, hv, lv);
        *(uint32_t*)(g_yhi + i_0) = hv;
        *(uint32_t*)(g_ylo + i_0) = lv;
        packpair(o[j][2] * i1, o[j][3] * i1, hv, lv);
        *(uint32_t*)(g_yhi + i_1) = hv;
        *(uint32_t*)(g_ylo + i_1) = lv;
    }
}

// ---------------------------------------------------------------------------
// kernel_launch
// Inputs: x, Wq, Wk, Wv, Wo, null_k, null_v, logit_scale
// ---------------------------------------------------------------------------
extern "C" void kernel_launch(void* const* d_in, const int* in_sizes, int n_in,
                              void* d_out, int out_size) {
    const float* x  = (const float*)d_in[0];
    const float* Wq = (const float*)d_in[1];
    const float* Wk = (const float*)d_in[2];
    const float* Wv = (const float*)d_in[3];
    const float* Wo = (const float*)d_in[4];
    const float* nk = (const float*)d_in[5];
    const float* nv = (const float*)d_in[6];
    const float* ls = (const float*)d_in[7];
    float* out = (float*)d_out;

    __nv_bfloat16 *xhi, *xlo, *yhi, *ylo, *whi, *wlo;
    cudaGetSymbolAddress((void**)&xhi, g_xhi);
    cudaGetSymbolAddress((void**)&xlo, g_xlo);
    cudaGetSymbolAddress((void**)&yhi, g_yhi);
    cudaGetSymbolAddress((void**)&ylo, g_ylo);
    cudaGetSymbolAddress((void**)&whi, g_whi);
    cudaGetSymbolAddress((void**)&wlo, g_wlo);

    const int GEMM_SMEM = NSTAGE * STG_BYTES;   // 80 KB
    cudaFuncSetAttribute(gemm_cp, cudaFuncAttributeMaxDynamicSharedMemorySize, GEMM_SMEM);
    cudaFuncSetAttribute(attn_mma, cudaFuncAttributeMaxDynamicSharedMemorySize, S_ATT_TOTAL);

    split_kernel<<<(M_ * C_) / (256 * 4), 256>>>(x, xhi, xlo);
    tsplit4_kernel<<<dim3(32, 32, 4), dim3(32, 8)>>>(Wq, Wk, Wv, Wo);

    const size_t WSZ = 1024u * 1024u;
    gemm_cp<<<dim3(24, 64), 256, GEMM_SMEM>>>(xhi, xlo, whi, wlo, nullptr, 0);

    attn_mma<<<dim3(T_ / 128, B_ * H_), 256, S_ATT_TOTAL>>>(nk, nv, ls);

    gemm_cp<<<dim3(8, 64), 256, GEMM_SMEM>>>(yhi, ylo, whi + 3 * WSZ, wlo + 3 * WSZ, out, 1);
}

// round 9
// speedup vs baseline: 3.8772x; 1.1363x over previous
#include <cuda_runtime.h>
#include <cuda_bf16.h>
#include <cuda_fp16.h>
#include <cstdint>
#include <math.h>

// Problem constants
#define B_ 4
#define T_ 2048
#define C_ 1024
#define H_ 16
#define D_ 64
#define M_ (B_*T_)   // 8192
#define N_ 1024
#define K_ 1024

// Scratch (device globals: allocation-free).
__device__ __nv_bfloat16 g_xhi[(size_t)M_ * C_];
__device__ __nv_bfloat16 g_xlo[(size_t)M_ * C_];
__device__ __nv_bfloat16 g_yhi[(size_t)M_ * C_];
__device__ __nv_bfloat16 g_ylo[(size_t)M_ * C_];
__device__ __nv_bfloat16 g_whi[4u * 1024u * 1024u];  // transposed [N,K]; rows 0-3071 = Wq|Wk|Wv, then Wo
__device__ __nv_bfloat16 g_wlo[4u * 1024u * 1024u];
// fp16 attention operand planes [B,H,T,D]
__device__ __half g_q16h[(size_t)M_ * C_];   // Q prescaled by exp(ls)*0.125*log2e, hi
__device__ __half g_q16l[(size_t)M_ * C_];   // Q lo
__device__ __half g_k16 [(size_t)M_ * C_];   // K single
__device__ __half g_v16h[(size_t)M_ * C_];   // V hi
__device__ __half g_v16l[(size_t)M_ * C_];   // V lo

__device__ __forceinline__ uint32_t smem_u32(const void* p) {
    uint32_t a;
    asm("{ .reg .u64 t; cvta.to.shared.u64 t, %1; cvt.u32.u64 %0, t; }" : "=r"(a) : "l"(p));
    return a;
}

#define LDSM4(r0, r1, r2, r3, a) \
    asm volatile("ldmatrix.sync.aligned.m8n8.x4.shared.b16 {%0,%1,%2,%3}, [%4];" \
        : "=r"(r0), "=r"(r1), "=r"(r2), "=r"(r3) : "r"(a))
#define LDSM4T(r0, r1, r2, r3, a) \
    asm volatile("ldmatrix.sync.aligned.m8n8.x4.trans.shared.b16 {%0,%1,%2,%3}, [%4];" \
        : "=r"(r0), "=r"(r1), "=r"(r2), "=r"(r3) : "r"(a))

#define MMA_BF16(c, a, b0, b1) \
    asm volatile("mma.sync.aligned.m16n8k16.row.col.f32.bf16.bf16.f32 " \
        "{%0,%1,%2,%3}, {%4,%5,%6,%7}, {%8,%9}, {%0,%1,%2,%3};" \
        : "+f"((c)[0]), "+f"((c)[1]), "+f"((c)[2]), "+f"((c)[3]) \
        : "r"((a)[0]), "r"((a)[1]), "r"((a)[2]), "r"((a)[3]), "r"(b0), "r"(b1))

#define MMA_F16(c, a, b0, b1) \
    asm volatile("mma.sync.aligned.m16n8k16.row.col.f32.f16.f16.f32 " \
        "{%0,%1,%2,%3}, {%4,%5,%6,%7}, {%8,%9}, {%0,%1,%2,%3};" \
        : "+f"((c)[0]), "+f"((c)[1]), "+f"((c)[2]), "+f"((c)[3]) \
        : "r"((a)[0]), "r"((a)[1]), "r"((a)[2]), "r"((a)[3]), "r"(b0), "r"(b1))

#define CP16(dst, src) \
    asm volatile("cp.async.cg.shared.global [%0], [%1], 16;" :: "r"(dst), "l"(src))
#define CPCOMMIT() asm volatile("cp.async.commit_group;" ::: "memory")
#define CPWAIT(n)  asm volatile("cp.async.wait_group %0;" :: "n"(n) : "memory")

__device__ __forceinline__ float ex2(float x) {
    float r;
    asm("ex2.approx.ftz.f32 %0, %1;" : "=f"(r) : "f"(x));
    return r;
}

// bf16 precise split (for GEMM epilogue / y)
__device__ __forceinline__ void packpair(float a, float b, uint32_t& hi, uint32_t& lo) {
    __nv_bfloat162 h = __floats2bfloat162_rn(a, b);
    float2 hf = __bfloat1622float2(h);
    __nv_bfloat162 l = __floats2bfloat162_rn(a - hf.x, b - hf.y);
    hi = *(uint32_t*)&h;
    lo = *(uint32_t*)&l;
}
// fp16 precise split
__device__ __forceinline__ void packpair_h(float a, float b, uint32_t& hi, uint32_t& lo) {
    __half2 h = __floats2half2_rn(a, b);
    float2 hf = __half22float2(h);
    __half2 l = __floats2half2_rn(a - hf.x, b - hf.y);
    hi = *(uint32_t*)&h;
    lo = *(uint32_t*)&l;
}
__device__ __forceinline__ uint32_t pack_h2(float a, float b) {
    __half2 h = __floats2half2_rn(a, b);
    return *(uint32_t*)&h;
}

// ---------------------------------------------------------------------------
// split: fp32 -> bf16 hi + bf16 lo residual
// ---------------------------------------------------------------------------
__global__ void __launch_bounds__(256) split_kernel(
    const float* __restrict__ in, __nv_bfloat16* __restrict__ hi,
    __nv_bfloat16* __restrict__ lo)
{
    int i = (blockIdx.x * 256 + threadIdx.x) * 4;
    float4 v = *(const float4*)(in + i);
    __nv_bfloat162 h0 = __floats2bfloat162_rn(v.x, v.y);
    __nv_bfloat162 h1 = __floats2bfloat162_rn(v.z, v.w);
    ((__nv_bfloat162*)(hi + i))[0] = h0;
    ((__nv_bfloat162*)(hi + i))[1] = h1;
    ((__nv_bfloat162*)(lo + i))[0] = __floats2bfloat162_rn(v.x - __bfloat162float(h0.x), v.y - __bfloat162float(h0.y));
    ((__nv_bfloat162*)(lo + i))[1] = __floats2bfloat162_rn(v.z - __bfloat162float(h1.x), v.w - __bfloat162float(h1.y));
}

// ---------------------------------------------------------------------------
// transpose + split all 4 weights; blockIdx.z selects the weight
// ---------------------------------------------------------------------------
__global__ void __launch_bounds__(256) tsplit4_kernel(
    const float* __restrict__ W0, const float* __restrict__ W1,
    const float* __restrict__ W2, const float* __restrict__ W3)
{
    __shared__ float tile[32][33];
    const int widx = blockIdx.z;
    const float* in = (widx == 0) ? W0 : (widx == 1) ? W1 : (widx == 2) ? W2 : W3;
    __nv_bfloat16* oh = g_whi + (size_t)widx * 1024 * 1024;
    __nv_bfloat16* ol = g_wlo + (size_t)widx * 1024 * 1024;
    int tx = threadIdx.x, ty = threadIdx.y;
    int x = blockIdx.x * 32 + tx, y0 = blockIdx.y * 32;
#pragma unroll
    for (int j = 0; j < 32; j += 8) tile[ty + j][tx] = in[(size_t)(y0 + ty + j) * 1024 + x];
    __syncthreads();
    int x2 = blockIdx.y * 32 + tx, y2 = blockIdx.x * 32;
#pragma unroll
    for (int j = 0; j < 32; j += 8) {
        float v = tile[tx][ty + j];
        __nv_bfloat16 h = __float2bfloat16(v);
        oh[(size_t)(y2 + ty + j) * 1024 + x2] = h;
        ol[(size_t)(y2 + ty + j) * 1024 + x2] = __float2bfloat16(v - __bfloat162float(h));
    }
}

// ---------------------------------------------------------------------------
// cp.async 2-stage bf16x3 GEMM (80KB smem -> 2 CTAs/SM)
// mode 0: fused QKV -> fp16 planes (Q prescaled, K single, V hi/lo), [B,H,T,D]
// mode 1: out proj -> fp32 row-major Cext
// ---------------------------------------------------------------------------
#define SPAD 40
#define STG_BYTES 40960
#define PL 10240
#define NSTAGE 2
#define NT_K 32

__global__ void __launch_bounds__(256, 2) gemm_cp(
    const __nv_bfloat16* __restrict__ Ahi, const __nv_bfloat16* __restrict__ Alo,
    const __nv_bfloat16* __restrict__ Bhi, const __nv_bfloat16* __restrict__ Blo,
    float* __restrict__ Cext, const float* __restrict__ ls, int mode)
{
    extern __shared__ char gsm[];
    const uint32_t sb = smem_u32(gsm);
    const int tid = threadIdx.x;
    const int warp = tid >> 5, lane = tid & 31;
    const int bm = blockIdx.y * 128, bn = blockIdx.x * 128;
    const int wm = (warp >> 2) * 64, wn = (warp & 3) * 32;

    float acc[4][4][4];
#pragma unroll
    for (int i = 0; i < 4; i++)
#pragma unroll
        for (int j = 0; j < 4; j++)
#pragma unroll
            for (int r = 0; r < 4; r++) acc[i][j][r] = 0.f;

    const int lr = tid >> 1, lc = (tid & 1) << 4;
    const size_t aoff = (size_t)(bm + lr) * K_ + lc;
    const size_t boff = (size_t)(bn + lr) * K_ + lc;
    const uint32_t drow = sb + (uint32_t)lr * (SPAD * 2) + (uint32_t)lc * 2;

#define ISSUE(st, kt) do { \
    uint32_t d = drow + (uint32_t)(st) * STG_BYTES; \
    size_t k0 = (size_t)(kt) * 32; \
    CP16(d,                Ahi + aoff + k0); \
    CP16(d + 16,           Ahi + aoff + k0 + 8); \
    CP16(d + PL,           Alo + aoff + k0); \
    CP16(d + PL + 16,      Alo + aoff + k0 + 8); \
    CP16(d + 2*PL,         Bhi + boff + k0); \
    CP16(d + 2*PL + 16,    Bhi + boff + k0 + 8); \
    CP16(d + 3*PL,         Blo + boff + k0); \
    CP16(d + 3*PL + 16,    Blo + boff + k0 + 8); \
} while (0)

    ISSUE(0, 0);
    CPCOMMIT();

    const uint32_t aAddr = (uint32_t)((wm + (lane & 15)) * (SPAD * 2) + (((lane >> 4) << 3)) * 2);
    const uint32_t bAddr = (uint32_t)(2 * PL + (wn + ((lane >> 4) << 3) + (lane & 7)) * (SPAD * 2) + ((lane & 8)) * 2);

    for (int kt = 0; kt < NT_K; ++kt) {
        {
            int nt = kt + 1;
            if (nt < NT_K) ISSUE(nt & 1, nt);
            CPCOMMIT();
        }
        CPWAIT(1);
        __syncthreads();
        const uint32_t stb = sb + (uint32_t)(kt & 1) * STG_BYTES;

#pragma unroll
        for (int kk = 0; kk < 2; kk++) {
            const uint32_t ko = (uint32_t)(kk * 16 * 2);
            uint32_t ah[4][4], al[4][4];
#pragma unroll
            for (int i = 0; i < 4; i++) {
                uint32_t ad = stb + aAddr + (uint32_t)(i * 16 * SPAD * 2) + ko;
                LDSM4(ah[i][0], ah[i][1], ah[i][2], ah[i][3], ad);
                LDSM4(al[i][0], al[i][1], al[i][2], al[i][3], ad + PL);
            }
#pragma unroll
            for (int jb = 0; jb < 2; jb++) {
                uint32_t bh[4], bl[4];
                uint32_t bd = stb + bAddr + (uint32_t)(jb * 16 * SPAD * 2) + ko;
                LDSM4(bh[0], bh[1], bh[2], bh[3], bd);
                LDSM4(bl[0], bl[1], bl[2], bl[3], bd + PL);
#pragma unroll
                for (int i = 0; i < 4; i++) {
                    MMA_BF16(acc[i][2*jb],   ah[i], bh[0], bh[1]);
                    MMA_BF16(acc[i][2*jb],   ah[i], bl[0], bl[1]);
                    MMA_BF16(acc[i][2*jb],   al[i], bh[0], bh[1]);
                    MMA_BF16(acc[i][2*jb+1], ah[i], bh[2], bh[3]);
                    MMA_BF16(acc[i][2*jb+1], ah[i], bl[2], bl[3]);
                    MMA_BF16(acc[i][2*jb+1], al[i], bh[2], bh[3]);
                }
            }
        }
        __syncthreads();
    }

    const int gr = lane >> 2, gc = (lane & 3) * 2;
    if (mode == 0) {
        const int sel = (bn + wn) >> 10;            // 0=Q 1=K 2=V (warp-constant)
        const int hh = ((bn + wn) >> 6) & 15;
        const float qs = (sel == 0) ? __expf(ls[hh]) * 0.125f * 1.4426950408889634f : 1.f;
#pragma unroll
        for (int i = 0; i < 4; i++)
#pragma unroll
            for (int j = 0; j < 4; j++) {
                int m0 = bm + wm + i * 16 + gr;
                int n0 = bn + wn + j * 8 + gc;
                int d = n0 & 63;
#pragma unroll
                for (int hrow = 0; hrow < 2; hrow++) {
                    int m = m0 + hrow * 8;
                    int b = m >> 11, t = m & (T_ - 1);
                    size_t idx = ((size_t)((b * H_ + hh) * T_ + t)) * D_ + d;
                    float v0 = acc[i][j][hrow*2] * qs, v1 = acc[i][j][hrow*2+1] * qs;
                    if (sel == 0) {
                        uint32_t hv, lv;
                        packpair_h(v0, v1, hv, lv);
                        *(uint32_t*)(g_q16h + idx) = hv;
                        *(uint32_t*)(g_q16l + idx) = lv;
                    } else if (sel == 1) {
                        *(uint32_t*)(g_k16 + idx) = pack_h2(v0, v1);
                    } else {
                        uint32_t hv, lv;
                        packpair_h(v0, v1, hv, lv);
                        *(uint32_t*)(g_v16h + idx) = hv;
                        *(uint32_t*)(g_v16l + idx) = lv;
                    }
                }
            }
    } else {
#pragma unroll
        for (int i = 0; i < 4; i++)
#pragma unroll
            for (int j = 0; j < 4; j++) {
                int m0 = bm + wm + i * 16 + gr;
                int n0 = bn + wn + j * 8 + gc;
                *(float2*)&Cext[(size_t)m0 * N_ + n0] = make_float2(acc[i][j][0], acc[i][j][1]);
                *(float2*)&Cext[(size_t)(m0 + 8) * N_ + n0] = make_float2(acc[i][j][2], acc[i][j][3]);
            }
    }
}

// ---------------------------------------------------------------------------
// Flash attention v5 (fp16): 256 threads, 128 q-rows/CTA, 8 warps x 16 rows.
// QK^T = 2 MMAs (Q fp16 hi/lo x K fp16 single); PV = 2 MMAs (P fp16 x V hi/lo).
// No online max; K/V 2-stage cp.async double buffer (3 planes/stage).
// ---------------------------------------------------------------------------
#define AST 72
#define PL64  (64 * AST * 2)     // 9216
#define PL16  (16 * AST * 2)     // 2304
#define STAGE_B (3 * PL64)       // 27648: K | VH | VL
#define S_NULL  (2 * STAGE_B)    // 55296
#define S_NK  (S_NULL)
#define S_NVH (S_NULL + PL16)
#define S_NVL (S_NULL + 2*PL16)
#define S_ATT_TOTAL (S_NULL + 3*PL16)   // 62208

__global__ void __launch_bounds__(256, 2) attn_mma(
    const float* __restrict__ nullk, const float* __restrict__ nullv,
    const float* __restrict__ lscale)
{
    extern __shared__ char sm[];
    const uint32_t sb = smem_u32(sm);
    const int bh = blockIdx.y, h = bh & 15;
    const int qblk = (T_ / 128 - 1) - blockIdx.x;   // longest first
    const int qbase = qblk * 128;
    const int tid = threadIdx.x, warp = tid >> 5, lane = tid & 31;
    const int wm = warp * 16;

    // null tiles: 16 x 64, row 0 real (K single fp16; V fp16 hi/lo)
    for (int i = tid; i < 1024; i += 256) {
        int r = i >> 6, d = i & 63;
        float kvk = (r == 0) ? nullk[h * 64 + d] : 0.f;
        float kvv = (r == 0) ? nullv[h * 64 + d] : 0.f;
        __half vh = __float2half(kvv);
        *(__half*)(sm + S_NK  + (r * AST + d) * 2) = __float2half(kvk);
        *(__half*)(sm + S_NVH + (r * AST + d) * 2) = vh;
        *(__half*)(sm + S_NVL + (r * AST + d) * 2) = __float2half(kvv - __half2float(vh));
    }

    // Q fragments: direct LDG from prescaled fp16 planes
    uint32_t qfh[4][4], qfl[4][4];
    {
        const size_t qrow0 = (size_t)bh * T_ + qbase + wm + (lane >> 2);
        const int cc = (lane & 3) * 2;
#pragma unroll
        for (int kk = 0; kk < 4; kk++) {
#pragma unroll
            for (int rg = 0; rg < 4; rg++) {
                int roff = (rg & 1) * 8;
                int col = kk * 16 + cc + (rg >> 1) * 8;
                size_t idx = (qrow0 + roff) * D_ + col;
                qfh[kk][rg] = *(const uint32_t*)(g_q16h + idx);
                qfl[kk][rg] = *(const uint32_t*)(g_q16l + idx);
            }
        }
    }

    float o[8][4];
#pragma unroll
    for (int j = 0; j < 8; j++)
#pragma unroll
        for (int r = 0; r < 4; r++) o[j][r] = 0.f;
    float l0 = 0.f, l1 = 0.f;

    const int qmin_w = qbase + wm;
    const int qmax_w = qbase + wm + 15;
    const int nkb = (qbase + 128) / 64;

    // K/V cp.async staging map: row=tid>>2 (0..63), col chunk=(tid&3)*16
    const int sr = tid >> 2, scol = (tid & 3) * 16;
    const uint32_t doff = (uint32_t)((sr * AST + scol) * 2);
    const size_t gbase0 = ((size_t)bh * T_ + sr) * D_ + scol;

#define AISS(st, kb_) do { \
    size_t base_ = gbase0 + (size_t)(kb_) * 64 * D_; \
    uint32_t d_ = sb + (uint32_t)(st) * STAGE_B + doff; \
    CP16(d_,                    g_k16  + base_); \
    CP16(d_ + 16,               g_k16  + base_ + 8); \
    CP16(d_ + PL64,             g_v16h + base_); \
    CP16(d_ + PL64 + 16,        g_v16h + base_ + 8); \
    CP16(d_ + 2*PL64,           g_v16l + base_); \
    CP16(d_ + 2*PL64 + 16,      g_v16l + base_ + 8); \
} while (0)

    AISS(0, 0);
    CPCOMMIT();

    for (int kb = 0; kb < nkb; kb++) {
        __syncthreads();                 // everyone done reading the other stage
        if (kb + 1 < nkb) AISS((kb + 1) & 1, kb + 1);
        CPCOMMIT();
        CPWAIT(1);
        __syncthreads();                 // stage kb visible to all
        if (kb * 64 > qmax_w) continue;  // warp fully below diagonal
        const uint32_t stb = sb + (uint32_t)(kb & 1) * STAGE_B;

        // S = Qs K^T   (2 MMAs per acc)
        float s[8][4];
#pragma unroll
        for (int j = 0; j < 8; j++)
#pragma unroll
            for (int r = 0; r < 4; r++) s[j][r] = 0.f;
#pragma unroll
        for (int kk = 0; kk < 4; kk++) {
#pragma unroll
            for (int jb = 0; jb < 4; jb++) {
                uint32_t kf[4];
                uint32_t bd = stb + (uint32_t)((jb * 16 + ((lane >> 4) << 3) + (lane & 7)) * AST
                            + kk * 16 + (lane & 8)) * 2;
                LDSM4(kf[0], kf[1], kf[2], kf[3], bd);
                MMA_F16(s[2*jb],   qfh[kk], kf[0], kf[1]);
                MMA_F16(s[2*jb],   qfl[kk], kf[0], kf[1]);
                MMA_F16(s[2*jb+1], qfh[kk], kf[2], kf[3]);
                MMA_F16(s[2*jb+1], qfl[kk], kf[2], kf[3]);
            }
        }

        // causal mask (diagonal warp-block only)
        if (kb * 64 + 63 > qmin_w) {
            const int q0 = qmin_w + (lane >> 2), q1 = q0 + 8;
#pragma unroll
            for (int j = 0; j < 8; j++) {
                int c = kb * 64 + j * 8 + ((lane & 3) << 1);
                if (c     > q0) s[j][0] = -1e30f;
                if (c + 1 > q0) s[j][1] = -1e30f;
                if (c     > q1) s[j][2] = -1e30f;
                if (c + 1 > q1) s[j][3] = -1e30f;
            }
        }

        // p = exp2(s); accumulate l
#pragma unroll
        for (int j = 0; j < 8; j++) {
            s[j][0] = ex2(s[j][0]); s[j][1] = ex2(s[j][1]);
            s[j][2] = ex2(s[j][2]); s[j][3] = ex2(s[j][3]);
            l0 += s[j][0] + s[j][1];
            l1 += s[j][2] + s[j][3];
        }

        // O += P V   (P fp16 single; V fp16 hi/lo -> 2 MMAs per acc)
#pragma unroll
        for (int kk = 0; kk < 4; kk++) {
            uint32_t ph[4];
            ph[0] = pack_h2(s[2*kk][0],   s[2*kk][1]);
            ph[1] = pack_h2(s[2*kk][2],   s[2*kk][3]);
            ph[2] = pack_h2(s[2*kk+1][0], s[2*kk+1][1]);
            ph[3] = pack_h2(s[2*kk+1][2], s[2*kk+1][3]);
#pragma unroll
            for (int g = 0; g < 4; g++) {
                uint32_t vh[4], vl[4];
                uint32_t vd = stb + PL64 + (uint32_t)((kk * 16 + (lane & 15)) * AST
                            + g * 16 + ((lane >> 4) << 3)) * 2;
                LDSM4T(vh[0], vh[1], vh[2], vh[3], vd);
                LDSM4T(vl[0], vl[1], vl[2], vl[3], vd + PL64);
                MMA_F16(o[2*g],   ph, vh[0], vh[1]);
                MMA_F16(o[2*g],   ph, vl[0], vl[1]);
                MMA_F16(o[2*g+1], ph, vh[2], vh[3]);
                MMA_F16(o[2*g+1], ph, vl[2], vl[3]);
            }
        }
    }

    // null-KV block (16 padded cols, col 0 real)
    {
        float s[2][4];
#pragma unroll
        for (int j = 0; j < 2; j++)
#pragma unroll
            for (int r = 0; r < 4; r++) s[j][r] = 0.f;
#pragma unroll
        for (int kk = 0; kk < 4; kk++) {
            uint32_t kf[4];
            uint32_t bd = sb + S_NK + (uint32_t)((((lane >> 4) << 3) + (lane & 7)) * AST
                        + kk * 16 + (lane & 8)) * 2;
            LDSM4(kf[0], kf[1], kf[2], kf[3], bd);
            MMA_F16(s[0], qfh[kk], kf[0], kf[1]);
            MMA_F16(s[0], qfl[kk], kf[0], kf[1]);
            MMA_F16(s[1], qfh[kk], kf[2], kf[3]);
            MMA_F16(s[1], qfl[kk], kf[2], kf[3]);
        }
#pragma unroll
        for (int j = 0; j < 2; j++) {
            int c = j * 8 + ((lane & 3) << 1);
            s[j][0] = (c == 0) ? ex2(s[j][0]) : 0.f;
            s[j][1] = 0.f;
            s[j][2] = (c == 0) ? ex2(s[j][2]) : 0.f;
            s[j][3] = 0.f;
            l0 += s[j][0];
            l1 += s[j][2];
        }

        uint32_t ph[4];
        ph[0] = pack_h2(s[0][0], s[0][1]);
        ph[1] = pack_h2(s[0][2], s[0][3]);
        ph[2] = pack_h2(s[1][0], s[1][1]);
        ph[3] = pack_h2(s[1][2], s[1][3]);
#pragma unroll
        for (int g = 0; g < 4; g++) {
            uint32_t vh[4], vl[4];
            uint32_t vd = sb + S_NVH + (uint32_t)((lane & 15) * AST + g * 16 + ((lane >> 4) << 3)) * 2;
            LDSM4T(vh[0], vh[1], vh[2], vh[3], vd);
            LDSM4T(vl[0], vl[1], vl[2], vl[3], vd + PL16);
            MMA_F16(o[2*g],   ph, vh[0], vh[1]);
            MMA_F16(o[2*g],   ph, vl[0], vl[1]);
            MMA_F16(o[2*g+1], ph, vh[2], vh[3]);
            MMA_F16(o[2*g+1], ph, vl[2], vl[3]);
        }
    }

    // finalize: quad-reduce l, normalize, write y bf16 hi/lo
    l0 += __shfl_xor_sync(0xffffffffu, l0, 1);
    l0 += __shfl_xor_sync(0xffffffffu, l0, 2);
    l1 += __shfl_xor_sync(0xffffffffu, l1, 1);
    l1 += __shfl_xor_sync(0xffffffffu, l1, 2);
    const float i0 = 1.f / l0, i1 = 1.f / l1;
    const int b = bh >> 4;
    const int t0 = qbase + wm + (lane >> 2), t1 = t0 + 8;
    const int cb = h * 64 + ((lane & 3) << 1);
#pragma unroll
    for (int j = 0; j < 8; j++) {
        int cc = cb + j * 8;
        size_t i_0 = (size_t)(b * T_ + t0) * C_ + cc;
        size_t i_1 = (size_t)(b * T_ + t1) * C_ + cc;
        uint32_t hv, lv;
        packpair(o[j][0] * i0, o[j][1] * i0, hv, lv);
        *(uint32_t*)(g_yhi + i_0) = hv;
        *(uint32_t*)(g_ylo + i_0) = lv;
        packpair(o[j][2] * i1, o[j][3] * i1, hv, lv);
        *(uint32_t*)(g_yhi + i_1) = hv;
        *(uint32_t*)(g_ylo + i_1) = lv;
    }
}

// ---------------------------------------------------------------------------
// kernel_launch
// Inputs: x, Wq, Wk, Wv, Wo, null_k, null_v, logit_scale
// ---------------------------------------------------------------------------
extern "C" void kernel_launch(void* const* d_in, const int* in_sizes, int n_in,
                              void* d_out, int out_size) {
    const float* x  = (const float*)d_in[0];
    const float* Wq = (const float*)d_in[1];
    const float* Wk = (const float*)d_in[2];
    const float* Wv = (const float*)d_in[3];
    const float* Wo = (const float*)d_in[4];
    const float* nk = (const float*)d_in[5];
    const float* nv = (const float*)d_in[6];
    const float* ls = (const float*)d_in[7];
    float* out = (float*)d_out;

    __nv_bfloat16 *xhi, *xlo, *yhi, *ylo, *whi, *wlo;
    cudaGetSymbolAddress((void**)&xhi, g_xhi);
    cudaGetSymbolAddress((void**)&xlo, g_xlo);
    cudaGetSymbolAddress((void**)&yhi, g_yhi);
    cudaGetSymbolAddress((void**)&ylo, g_ylo);
    cudaGetSymbolAddress((void**)&whi, g_whi);
    cudaGetSymbolAddress((void**)&wlo, g_wlo);

    const int GEMM_SMEM = NSTAGE * STG_BYTES;   // 80 KB
    cudaFuncSetAttribute(gemm_cp, cudaFuncAttributeMaxDynamicSharedMemorySize, GEMM_SMEM);
    cudaFuncSetAttribute(attn_mma, cudaFuncAttributeMaxDynamicSharedMemorySize, S_ATT_TOTAL);

    split_kernel<<<(M_ * C_) / (256 * 4), 256>>>(x, xhi, xlo);
    tsplit4_kernel<<<dim3(32, 32, 4), dim3(32, 8)>>>(Wq, Wk, Wv, Wo);

    const size_t WSZ = 1024u * 1024u;
    gemm_cp<<<dim3(24, 64), 256, GEMM_SMEM>>>(xhi, xlo, whi, wlo, nullptr, ls, 0);

    attn_mma<<<dim3(T_ / 128, B_ * H_), 256, S_ATT_TOTAL>>>(nk, nv, ls);

    gemm_cp<<<dim3(8, 64), 256, GEMM_SMEM>>>(yhi, ylo, whi + 3 * WSZ, wlo + 3 * WSZ, out, ls, 1);
}

// round 10
// speedup vs baseline: 4.8346x; 1.2469x over previous
#include <cuda_runtime.h>
#include <cuda_bf16.h>
#include <cuda_fp16.h>
#include <cstdint>
#include <math.h>

// Problem constants
#define B_ 4
#define T_ 2048
#define C_ 1024
#define H_ 16
#define D_ 64
#define M_ (B_*T_)   // 8192
#define N_ 1024
#define K_ 1024

// Scratch (device globals: allocation-free).
__device__ __half g_x16h[(size_t)M_ * C_];           // x fp16 hi
__device__ __half g_x16l[(size_t)M_ * C_];           // x fp16 lo
__device__ __nv_bfloat16 g_yhi[(size_t)M_ * C_];     // attention out, bf16 hi/lo
__device__ __nv_bfloat16 g_ylo[(size_t)M_ * C_];
__device__ __half g_w16[3u * 1024u * 1024u];         // Wq|Wk|Wv transposed [N,K], single fp16
__device__ __nv_bfloat16 g_wohi[1024u * 1024u];      // Wo transposed, bf16 hi/lo
__device__ __nv_bfloat16 g_wolo[1024u * 1024u];
// fp16 attention operand planes [B,H,T,D]
__device__ __half g_q16h[(size_t)M_ * C_];   // Q prescaled by exp(ls)*0.125*log2e, hi
__device__ __half g_q16l[(size_t)M_ * C_];   // Q lo
__device__ __half g_k16 [(size_t)M_ * C_];   // K single
__device__ __half g_v16 [(size_t)M_ * C_];   // V single

__device__ __forceinline__ uint32_t smem_u32(const void* p) {
    uint32_t a;
    asm("{ .reg .u64 t; cvta.to.shared.u64 t, %1; cvt.u32.u64 %0, t; }" : "=r"(a) : "l"(p));
    return a;
}

#define LDSM4(r0, r1, r2, r3, a) \
    asm volatile("ldmatrix.sync.aligned.m8n8.x4.shared.b16 {%0,%1,%2,%3}, [%4];" \
        : "=r"(r0), "=r"(r1), "=r"(r2), "=r"(r3) : "r"(a))
#define LDSM4T(r0, r1, r2, r3, a) \
    asm volatile("ldmatrix.sync.aligned.m8n8.x4.trans.shared.b16 {%0,%1,%2,%3}, [%4];" \
        : "=r"(r0), "=r"(r1), "=r"(r2), "=r"(r3) : "r"(a))

#define MMA_BF16(c, a, b0, b1) \
    asm volatile("mma.sync.aligned.m16n8k16.row.col.f32.bf16.bf16.f32 " \
        "{%0,%1,%2,%3}, {%4,%5,%6,%7}, {%8,%9}, {%0,%1,%2,%3};" \
        : "+f"((c)[0]), "+f"((c)[1]), "+f"((c)[2]), "+f"((c)[3]) \
        : "r"((a)[0]), "r"((a)[1]), "r"((a)[2]), "r"((a)[3]), "r"(b0), "r"(b1))

#define MMA_F16(c, a, b0, b1) \
    asm volatile("mma.sync.aligned.m16n8k16.row.col.f32.f16.f16.f32 " \
        "{%0,%1,%2,%3}, {%4,%5,%6,%7}, {%8,%9}, {%0,%1,%2,%3};" \
        : "+f"((c)[0]), "+f"((c)[1]), "+f"((c)[2]), "+f"((c)[3]) \
        : "r"((a)[0]), "r"((a)[1]), "r"((a)[2]), "r"((a)[3]), "r"(b0), "r"(b1))

#define CP16(dst, src) \
    asm volatile("cp.async.cg.shared.global [%0], [%1], 16;" :: "r"(dst), "l"(src))
#define CPCOMMIT() asm volatile("cp.async.commit_group;" ::: "memory")
#define CPWAIT(n)  asm volatile("cp.async.wait_group %0;" :: "n"(n) : "memory")

__device__ __forceinline__ float ex2(float x) {
    float r;
    asm("ex2.approx.ftz.f32 %0, %1;" : "=f"(r) : "f"(x));
    return r;
}

// bf16 precise split (for y epilogue)
__device__ __forceinline__ void packpair(float a, float b, uint32_t& hi, uint32_t& lo) {
    __nv_bfloat162 h = __floats2bfloat162_rn(a, b);
    float2 hf = __bfloat1622float2(h);
    __nv_bfloat162 l = __floats2bfloat162_rn(a - hf.x, b - hf.y);
    hi = *(uint32_t*)&h;
    lo = *(uint32_t*)&l;
}
// fp16 precise split
__device__ __forceinline__ void packpair_h(float a, float b, uint32_t& hi, uint32_t& lo) {
    __half2 h = __floats2half2_rn(a, b);
    float2 hf = __half22float2(h);
    __half2 l = __floats2half2_rn(a - hf.x, b - hf.y);
    hi = *(uint32_t*)&h;
    lo = *(uint32_t*)&l;
}
__device__ __forceinline__ uint32_t pack_h2(float a, float b) {
    __half2 h = __floats2half2_rn(a, b);
    return *(uint32_t*)&h;
}

// ---------------------------------------------------------------------------
// split x: fp32 -> fp16 hi + fp16 lo residual
// ---------------------------------------------------------------------------
__global__ void __launch_bounds__(256) splitx_kernel(const float* __restrict__ in) {
    int i = (blockIdx.x * 256 + threadIdx.x) * 4;
    float4 v = *(const float4*)(in + i);
    __half2 h0 = __floats2half2_rn(v.x, v.y);
    __half2 h1 = __floats2half2_rn(v.z, v.w);
    float2 f0 = __half22float2(h0), f1 = __half22float2(h1);
    ((__half2*)(g_x16h + i))[0] = h0;
    ((__half2*)(g_x16h + i))[1] = h1;
    ((__half2*)(g_x16l + i))[0] = __floats2half2_rn(v.x - f0.x, v.y - f0.y);
    ((__half2*)(g_x16l + i))[1] = __floats2half2_rn(v.z - f1.x, v.w - f1.y);
}

// ---------------------------------------------------------------------------
// transpose weights: Wq/Wk/Wv -> single fp16 [N,K]; Wo -> bf16 hi/lo [N,K]
// ---------------------------------------------------------------------------
__global__ void __launch_bounds__(256) tsplitw_kernel(
    const float* __restrict__ W0, const float* __restrict__ W1,
    const float* __restrict__ W2, const float* __restrict__ W3)
{
    __shared__ float tile[32][33];
    const int widx = blockIdx.z;
    const float* in = (widx == 0) ? W0 : (widx == 1) ? W1 : (widx == 2) ? W2 : W3;
    int tx = threadIdx.x, ty = threadIdx.y;
    int x = blockIdx.x * 32 + tx, y0 = blockIdx.y * 32;
#pragma unroll
    for (int j = 0; j < 32; j += 8) tile[ty + j][tx] = in[(size_t)(y0 + ty + j) * 1024 + x];
    __syncthreads();
    int x2 = blockIdx.y * 32 + tx, y2 = blockIdx.x * 32;
    if (widx < 3) {
        __half* o16 = g_w16 + (size_t)widx * 1024 * 1024;
#pragma unroll
        for (int j = 0; j < 32; j += 8)
            o16[(size_t)(y2 + ty + j) * 1024 + x2] = __float2half(tile[tx][ty + j]);
    } else {
#pragma unroll
        for (int j = 0; j < 32; j += 8) {
            float v = tile[tx][ty + j];
            __nv_bfloat16 h = __float2bfloat16(v);
            g_wohi[(size_t)(y2 + ty + j) * 1024 + x2] = h;
            g_wolo[(size_t)(y2 + ty + j) * 1024 + x2] = __float2bfloat16(v - __bfloat162float(h));
        }
    }
}

// ---------------------------------------------------------------------------
// fp16 QKV GEMM (2 MMAs/tile): C = x @ W^T, N=3072.
// A fp16 hi/lo; B single fp16. 2-stage cp.async, 3 planes/stage (60KB total).
// Epilogue: Q prescaled fp16 hi/lo; K,V single fp16; [B,H,T,D] scatter.
// ---------------------------------------------------------------------------
#define QSPAD 40
#define QPL 10240
#define QSTG (3 * QPL)         // 30720 per stage
#define NT_K 32

__global__ void __launch_bounds__(256, 2) gemm_qkv(const float* __restrict__ ls) {
    extern __shared__ char gsm[];
    const uint32_t sb = smem_u32(gsm);
    const int tid = threadIdx.x;
    const int warp = tid >> 5, lane = tid & 31;
    const int bm = blockIdx.y * 128, bn = blockIdx.x * 128;
    const int wm = (warp >> 2) * 64, wn = (warp & 3) * 32;

    float acc[4][4][4];
#pragma unroll
    for (int i = 0; i < 4; i++)
#pragma unroll
        for (int j = 0; j < 4; j++)
#pragma unroll
            for (int r = 0; r < 4; r++) acc[i][j][r] = 0.f;

    const int lr = tid >> 1, lc = (tid & 1) << 4;
    const size_t aoff = (size_t)(bm + lr) * K_ + lc;
    const size_t boff = (size_t)(bn + lr) * K_ + lc;
    const uint32_t drow = sb + (uint32_t)lr * (QSPAD * 2) + (uint32_t)lc * 2;

#define QISSUE(st, kt) do { \
    uint32_t d = drow + (uint32_t)(st) * QSTG; \
    size_t k0 = (size_t)(kt) * 32; \
    CP16(d,                 g_x16h + aoff + k0); \
    CP16(d + 16,            g_x16h + aoff + k0 + 8); \
    CP16(d + QPL,           g_x16l + aoff + k0); \
    CP16(d + QPL + 16,      g_x16l + aoff + k0 + 8); \
    CP16(d + 2*QPL,         g_w16  + boff + k0); \
    CP16(d + 2*QPL + 16,    g_w16  + boff + k0 + 8); \
} while (0)

    QISSUE(0, 0);
    CPCOMMIT();

    const uint32_t aAddr = (uint32_t)((wm + (lane & 15)) * (QSPAD * 2) + (((lane >> 4) << 3)) * 2);
    const uint32_t bAddr = (uint32_t)(2 * QPL + (wn + ((lane >> 4) << 3) + (lane & 7)) * (QSPAD * 2) + ((lane & 8)) * 2);

    for (int kt = 0; kt < NT_K; ++kt) {
        {
            int nt = kt + 1;
            if (nt < NT_K) QISSUE(nt & 1, nt);
            CPCOMMIT();
        }
        CPWAIT(1);
        __syncthreads();
        const uint32_t stb = sb + (uint32_t)(kt & 1) * QSTG;

#pragma unroll
        for (int kk = 0; kk < 2; kk++) {
            const uint32_t ko = (uint32_t)(kk * 16 * 2);
            uint32_t ah[4][4], al[4][4];
#pragma unroll
            for (int i = 0; i < 4; i++) {
                uint32_t ad = stb + aAddr + (uint32_t)(i * 16 * QSPAD * 2) + ko;
                LDSM4(ah[i][0], ah[i][1], ah[i][2], ah[i][3], ad);
                LDSM4(al[i][0], al[i][1], al[i][2], al[i][3], ad + QPL);
            }
#pragma unroll
            for (int jb = 0; jb < 2; jb++) {
                uint32_t bh[4];
                uint32_t bd = stb + bAddr + (uint32_t)(jb * 16 * QSPAD * 2) + ko;
                LDSM4(bh[0], bh[1], bh[2], bh[3], bd);
#pragma unroll
                for (int i = 0; i < 4; i++) {
                    MMA_F16(acc[i][2*jb],   ah[i], bh[0], bh[1]);
                    MMA_F16(acc[i][2*jb],   al[i], bh[0], bh[1]);
                    MMA_F16(acc[i][2*jb+1], ah[i], bh[2], bh[3]);
                    MMA_F16(acc[i][2*jb+1], al[i], bh[2], bh[3]);
                }
            }
        }
        __syncthreads();
    }

    const int gr = lane >> 2, gc = (lane & 3) * 2;
    const int sel = (bn + wn) >> 10;            // 0=Q 1=K 2=V (warp-constant)
    const int hh = ((bn + wn) >> 6) & 15;
    const float qs = (sel == 0) ? __expf(ls[hh]) * 0.125f * 1.4426950408889634f : 1.f;
#pragma unroll
    for (int i = 0; i < 4; i++)
#pragma unroll
        for (int j = 0; j < 4; j++) {
            int m0 = bm + wm + i * 16 + gr;
            int n0 = bn + wn + j * 8 + gc;
            int d = n0 & 63;
#pragma unroll
            for (int hrow = 0; hrow < 2; hrow++) {
                int m = m0 + hrow * 8;
                int b = m >> 11, t = m & (T_ - 1);
                size_t idx = ((size_t)((b * H_ + hh) * T_ + t)) * D_ + d;
                float v0 = acc[i][j][hrow*2] * qs, v1 = acc[i][j][hrow*2+1] * qs;
                if (sel == 0) {
                    uint32_t hv, lv;
                    packpair_h(v0, v1, hv, lv);
                    *(uint32_t*)(g_q16h + idx) = hv;
                    *(uint32_t*)(g_q16l + idx) = lv;
                } else if (sel == 1) {
                    *(uint32_t*)(g_k16 + idx) = pack_h2(v0, v1);
                } else {
                    *(uint32_t*)(g_v16 + idx) = pack_h2(v0, v1);
                }
            }
        }
}

// ---------------------------------------------------------------------------
// bf16x3 out-projection GEMM (unchanged math): out = y @ Wo^T, fp32 out.
// ---------------------------------------------------------------------------
#define SPAD 40
#define STG_BYTES 40960
#define PL 10240

__global__ void __launch_bounds__(256, 2) gemm_out(float* __restrict__ Cext) {
    extern __shared__ char gsm[];
    const uint32_t sb = smem_u32(gsm);
    const int tid = threadIdx.x;
    const int warp = tid >> 5, lane = tid & 31;
    const int bm = blockIdx.y * 128, bn = blockIdx.x * 128;
    const int wm = (warp >> 2) * 64, wn = (warp & 3) * 32;

    float acc[4][4][4];
#pragma unroll
    for (int i = 0; i < 4; i++)
#pragma unroll
        for (int j = 0; j < 4; j++)
#pragma unroll
            for (int r = 0; r < 4; r++) acc[i][j][r] = 0.f;

    const int lr = tid >> 1, lc = (tid & 1) << 4;
    const size_t aoff = (size_t)(bm + lr) * K_ + lc;
    const size_t boff = (size_t)(bn + lr) * K_ + lc;
    const uint32_t drow = sb + (uint32_t)lr * (SPAD * 2) + (uint32_t)lc * 2;

#define OISSUE(st, kt) do { \
    uint32_t d = drow + (uint32_t)(st) * STG_BYTES; \
    size_t k0 = (size_t)(kt) * 32; \
    CP16(d,                g_yhi  + aoff + k0); \
    CP16(d + 16,           g_yhi  + aoff + k0 + 8); \
    CP16(d + PL,           g_ylo  + aoff + k0); \
    CP16(d + PL + 16,      g_ylo  + aoff + k0 + 8); \
    CP16(d + 2*PL,         g_wohi + boff + k0); \
    CP16(d + 2*PL + 16,    g_wohi + boff + k0 + 8); \
    CP16(d + 3*PL,         g_wolo + boff + k0); \
    CP16(d + 3*PL + 16,    g_wolo + boff + k0 + 8); \
} while (0)

    OISSUE(0, 0);
    CPCOMMIT();

    const uint32_t aAddr = (uint32_t)((wm + (lane & 15)) * (SPAD * 2) + (((lane >> 4) << 3)) * 2);
    const uint32_t bAddr = (uint32_t)(2 * PL + (wn + ((lane >> 4) << 3) + (lane & 7)) * (SPAD * 2) + ((lane & 8)) * 2);

    for (int kt = 0; kt < NT_K; ++kt) {
        {
            int nt = kt + 1;
            if (nt < NT_K) OISSUE(nt & 1, nt);
            CPCOMMIT();
        }
        CPWAIT(1);
        __syncthreads();
        const uint32_t stb = sb + (uint32_t)(kt & 1) * STG_BYTES;

#pragma unroll
        for (int kk = 0; kk < 2; kk++) {
            const uint32_t ko = (uint32_t)(kk * 16 * 2);
            uint32_t ah[4][4], al[4][4];
#pragma unroll
            for (int i = 0; i < 4; i++) {
                uint32_t ad = stb + aAddr + (uint32_t)(i * 16 * SPAD * 2) + ko;
                LDSM4(ah[i][0], ah[i][1], ah[i][2], ah[i][3], ad);
                LDSM4(al[i][0], al[i][1], al[i][2], al[i][3], ad + PL);
            }
#pragma unroll
            for (int jb = 0; jb < 2; jb++) {
                uint32_t bh[4], bl[4];
                uint32_t bd = stb + bAddr + (uint32_t)(jb * 16 * SPAD * 2) + ko;
                LDSM4(bh[0], bh[1], bh[2], bh[3], bd);
                LDSM4(bl[0], bl[1], bl[2], bl[3], bd + PL);
#pragma unroll
                for (int i = 0; i < 4; i++) {
                    MMA_BF16(acc[i][2*jb],   ah[i], bh[0], bh[1]);
                    MMA_BF16(acc[i][2*jb],   ah[i], bl[0], bl[1]);
                    MMA_BF16(acc[i][2*jb],   al[i], bh[0], bh[1]);
                    MMA_BF16(acc[i][2*jb+1], ah[i], bh[2], bh[3]);
                    MMA_BF16(acc[i][2*jb+1], ah[i], bl[2], bl[3]);
                    MMA_BF16(acc[i][2*jb+1], al[i], bh[2], bh[3]);
                }
            }
        }
        __syncthreads();
    }

    const int gr = lane >> 2, gc = (lane & 3) * 2;
#pragma unroll
    for (int i = 0; i < 4; i++)
#pragma unroll
        for (int j = 0; j < 4; j++) {
            int m0 = bm + wm + i * 16 + gr;
            int n0 = bn + wn + j * 8 + gc;
            *(float2*)&Cext[(size_t)m0 * N_ + n0] = make_float2(acc[i][j][0], acc[i][j][1]);
            *(float2*)&Cext[(size_t)(m0 + 8) * N_ + n0] = make_float2(acc[i][j][2], acc[i][j][3]);
        }
}

// ---------------------------------------------------------------------------
// Flash attention v6 (fp16, V single): 256 threads, 128 q-rows/CTA.
// QK^T = 2 MMAs (Q hi/lo x K); PV = 1 MMA (P x V). No online max.
// K/V 2-stage cp.async double buffer (2 planes/stage).
// ---------------------------------------------------------------------------
#define AST 72
#define PL64  (64 * AST * 2)     // 9216
#define PL16  (16 * AST * 2)     // 2304
#define STAGE_B (2 * PL64)       // 18432: K | V
#define S_NULL  (2 * STAGE_B)    // 36864
#define S_NK  (S_NULL)
#define S_NV  (S_NULL + PL16)
#define S_ATT_TOTAL (S_NULL + 2*PL16)   // 41472

__global__ void __launch_bounds__(256, 2) attn_mma(
    const float* __restrict__ nullk, const float* __restrict__ nullv)
{
    extern __shared__ char sm[];
    const uint32_t sb = smem_u32(sm);
    const int bh = blockIdx.y, h = bh & 15;
    const int qblk = (T_ / 128 - 1) - blockIdx.x;   // longest first
    const int qbase = qblk * 128;
    const int tid = threadIdx.x, warp = tid >> 5, lane = tid & 31;
    const int wm = warp * 16;

    // null tiles: 16 x 64, row 0 real (K, V single fp16)
    for (int i = tid; i < 1024; i += 256) {
        int r = i >> 6, d = i & 63;
        float kvk = (r == 0) ? nullk[h * 64 + d] : 0.f;
        float kvv = (r == 0) ? nullv[h * 64 + d] : 0.f;
        *(__half*)(sm + S_NK + (r * AST + d) * 2) = __float2half(kvk);
        *(__half*)(sm + S_NV + (r * AST + d) * 2) = __float2half(kvv);
    }

    // Q fragments: direct LDG from prescaled fp16 planes
    uint32_t qfh[4][4], qfl[4][4];
    {
        const size_t qrow0 = (size_t)bh * T_ + qbase + wm + (lane >> 2);
        const int cc = (lane & 3) * 2;
#pragma unroll
        for (int kk = 0; kk < 4; kk++) {
#pragma unroll
            for (int rg = 0; rg < 4; rg++) {
                int roff = (rg & 1) * 8;
                int col = kk * 16 + cc + (rg >> 1) * 8;
                size_t idx = (qrow0 + roff) * D_ + col;
                qfh[kk][rg] = *(const uint32_t*)(g_q16h + idx);
                qfl[kk][rg] = *(const uint32_t*)(g_q16l + idx);
            }
        }
    }

    float o[8][4];
#pragma unroll
    for (int j = 0; j < 8; j++)
#pragma unroll
        for (int r = 0; r < 4; r++) o[j][r] = 0.f;
    float l0 = 0.f, l1 = 0.f;

    const int qmin_w = qbase + wm;
    const int qmax_w = qbase + wm + 15;
    const int nkb = (qbase + 128) / 64;

    // K/V cp.async staging map: row=tid>>2 (0..63), col chunk=(tid&3)*16
    const int sr = tid >> 2, scol = (tid & 3) * 16;
    const uint32_t doff = (uint32_t)((sr * AST + scol) * 2);
    const size_t gbase0 = ((size_t)bh * T_ + sr) * D_ + scol;

#define AISS(st, kb_) do { \
    size_t base_ = gbase0 + (size_t)(kb_) * 64 * D_; \
    uint32_t d_ = sb + (uint32_t)(st) * STAGE_B + doff; \
    CP16(d_,              g_k16 + base_); \
    CP16(d_ + 16,         g_k16 + base_ + 8); \
    CP16(d_ + PL64,       g_v16 + base_); \
    CP16(d_ + PL64 + 16,  g_v16 + base_ + 8); \
} while (0)

    AISS(0, 0);
    CPCOMMIT();

    for (int kb = 0; kb < nkb; kb++) {
        __syncthreads();                 // everyone done reading the other stage
        if (kb + 1 < nkb) AISS((kb + 1) & 1, kb + 1);
        CPCOMMIT();
        CPWAIT(1);
        __syncthreads();                 // stage kb visible to all
        if (kb * 64 > qmax_w) continue;  // warp fully below diagonal
        const uint32_t stb = sb + (uint32_t)(kb & 1) * STAGE_B;

        // S = Qs K^T   (2 MMAs per acc)
        float s[8][4];
#pragma unroll
        for (int j = 0; j < 8; j++)
#pragma unroll
            for (int r = 0; r < 4; r++) s[j][r] = 0.f;
#pragma unroll
        for (int kk = 0; kk < 4; kk++) {
#pragma unroll
            for (int jb = 0; jb < 4; jb++) {
                uint32_t kf[4];
                uint32_t bd = stb + (uint32_t)((jb * 16 + ((lane >> 4) << 3) + (lane & 7)) * AST
                            + kk * 16 + (lane & 8)) * 2;
                LDSM4(kf[0], kf[1], kf[2], kf[3], bd);
                MMA_F16(s[2*jb],   qfh[kk], kf[0], kf[1]);
                MMA_F16(s[2*jb],   qfl[kk], kf[0], kf[1]);
                MMA_F16(s[2*jb+1], qfh[kk], kf[2], kf[3]);
                MMA_F16(s[2*jb+1], qfl[kk], kf[2], kf[3]);
            }
        }

        // causal mask (diagonal warp-block only)
        if (kb * 64 + 63 > qmin_w) {
            const int q0 = qmin_w + (lane >> 2), q1 = q0 + 8;
#pragma unroll
            for (int j = 0; j < 8; j++) {
                int c = kb * 64 + j * 8 + ((lane & 3) << 1);
                if (c     > q0) s[j][0] = -1e30f;
                if (c + 1 > q0) s[j][1] = -1e30f;
                if (c     > q1) s[j][2] = -1e30f;
                if (c + 1 > q1) s[j][3] = -1e30f;
            }
        }

        // p = exp2(s); accumulate l
#pragma unroll
        for (int j = 0; j < 8; j++) {
            s[j][0] = ex2(s[j][0]); s[j][1] = ex2(s[j][1]);
            s[j][2] = ex2(s[j][2]); s[j][3] = ex2(s[j][3]);
            l0 += s[j][0] + s[j][1];
            l1 += s[j][2] + s[j][3];
        }

        // O += P V   (1 MMA per acc)
#pragma unroll
        for (int kk = 0; kk < 4; kk++) {
            uint32_t ph[4];
            ph[0] = pack_h2(s[2*kk][0],   s[2*kk][1]);
            ph[1] = pack_h2(s[2*kk][2],   s[2*kk][3]);
            ph[2] = pack_h2(s[2*kk+1][0], s[2*kk+1][1]);
            ph[3] = pack_h2(s[2*kk+1][2], s[2*kk+1][3]);
#pragma unroll
            for (int g = 0; g < 4; g++) {
                uint32_t vh[4];
                uint32_t vd = stb + PL64 + (uint32_t)((kk * 16 + (lane & 15)) * AST
                            + g * 16 + ((lane >> 4) << 3)) * 2;
                LDSM4T(vh[0], vh[1], vh[2], vh[3], vd);
                MMA_F16(o[2*g],   ph, vh[0], vh[1]);
                MMA_F16(o[2*g+1], ph, vh[2], vh[3]);
            }
        }
    }

    // null-KV block (16 padded cols, col 0 real)
    {
        float s[2][4];
#pragma unroll
        for (int j = 0; j < 2; j++)
#pragma unroll
            for (int r = 0; r < 4; r++) s[j][r] = 0.f;
#pragma unroll
        for (int kk = 0; kk < 4; kk++) {
            uint32_t kf[4];
            uint32_t bd = sb + S_NK + (uint32_t)((((lane >> 4) << 3) + (lane & 7)) * AST
                        + kk * 16 + (lane & 8)) * 2;
            LDSM4(kf[0], kf[1], kf[2], kf[3], bd);
            MMA_F16(s[0], qfh[kk], kf[0], kf[1]);
            MMA_F16(s[0], qfl[kk], kf[0], kf[1]);
            MMA_F16(s[1], qfh[kk], kf[2], kf[3]);
            MMA_F16(s[1], qfl[kk], kf[2], kf[3]);
        }
#pragma unroll
        for (int j = 0; j < 2; j++) {
            int c = j * 8 + ((lane & 3) << 1);
            s[j][0] = (c == 0) ? ex2(s[j][0]) : 0.f;
            s[j][1] = 0.f;
            s[j][2] = (c == 0) ? ex2(s[j][2]) : 0.f;
            s[j][3] = 0.f;
            l0 += s[j][0];
            l1 += s[j][2];
        }

        uint32_t ph[4];
        ph[0] = pack_h2(s[0][0], s[0][1]);
        ph[1] = pack_h2(s[0][2], s[0][3]);
        ph[2] = pack_h2(s[1][0], s[1][1]);
        ph[3] = pack_h2(s[1][2], s[1][3]);
#pragma unroll
        for (int g = 0; g < 4; g++) {
            uint32_t vh[4];
            uint32_t vd = sb + S_NV + (uint32_t)((lane & 15) * AST + g * 16 + ((lane >> 4) << 3)) * 2;
            LDSM4T(vh[0], vh[1], vh[2], vh[3], vd);
            MMA_F16(o[2*g],   ph, vh[0], vh[1]);
            MMA_F16(o[2*g+1], ph, vh[2], vh[3]);
        }
    }

    // finalize: quad-reduce l, normalize, write y bf16 hi/lo
    l0 += __shfl_xor_sync(0xffffffffu, l0, 1);
    l0 += __shfl_xor_sync(0xffffffffu, l0, 2);
    l1 += __shfl_xor_sync(0xffffffffu, l1, 1);
    l1 += __shfl_xor_sync(0xffffffffu, l1, 2);
    const float i0 = 1.f / l0, i1 = 1.f / l1;
    const int b = bh >> 4;
    const int t0 = qbase + wm + (lane >> 2), t1 = t0 + 8;
    const int cb = h * 64 + ((lane & 3) << 1);
#pragma unroll
    for (int j = 0; j < 8; j++) {
        int cc = cb + j * 8;
        size_t i_0 = (size_t)(b * T_ + t0) * C_ + cc;
        size_t i_1 = (size_t)(b * T_ + t1) * C_ + cc;
        uint32_t hv, lv;
        packpair(o[j][0] * i0, o[j][1] * i0, hv, lv);
        *(uint32_t*)(g_yhi + i_0) = hv;
        *(uint32_t*)(g_ylo + i_0) = lv;
        packpair(o[j][2] * i1, o[j][3] * i1, hv, lv);
        *(uint32_t*)(g_yhi + i_1) = hv;
        *(uint32_t*)(g_ylo + i_1) = lv;
    }
}

// ---------------------------------------------------------------------------
// kernel_launch
// Inputs: x, Wq, Wk, Wv, Wo, null_k, null_v, logit_scale
// ---------------------------------------------------------------------------
extern "C" void kernel_launch(void* const* d_in, const int* in_sizes, int n_in,
                              void* d_out, int out_size) {
    const float* x  = (const float*)d_in[0];
    const float* Wq = (const float*)d_in[1];
    const float* Wk = (const float*)d_in[2];
    const float* Wv = (const float*)d_in[3];
    const float* Wo = (const float*)d_in[4];
    const float* nk = (const float*)d_in[5];
    const float* nv = (const float*)d_in[6];
    const float* ls = (const float*)d_in[7];
    float* out = (float*)d_out;

    const int QKV_SMEM = 2 * QSTG;        // 61440
    const int OUT_SMEM = 2 * STG_BYTES;   // 81920
    cudaFuncSetAttribute(gemm_qkv, cudaFuncAttributeMaxDynamicSharedMemorySize, QKV_SMEM);
    cudaFuncSetAttribute(gemm_out, cudaFuncAttributeMaxDynamicSharedMemorySize, OUT_SMEM);
    cudaFuncSetAttribute(attn_mma, cudaFuncAttributeMaxDynamicSharedMemorySize, S_ATT_TOTAL);

    splitx_kernel<<<(M_ * C_) / (256 * 4), 256>>>(x);
    tsplitw_kernel<<<dim3(32, 32, 4), dim3(32, 8)>>>(Wq, Wk, Wv, Wo);

    gemm_qkv<<<dim3(24, 64), 256, QKV_SMEM>>>(ls);

    attn_mma<<<dim3(T_ / 128, B_ * H_), 256, S_ATT_TOTAL>>>(nk, nv);

    gemm_out<<<dim3(8, 64), 256, OUT_SMEM>>>(out);
}

// round 11
// speedup vs baseline: 5.2154x; 1.0788x over previous
#include <cuda_runtime.h>
#include <cuda_bf16.h>
#include <cuda_fp16.h>
#include <cstdint>
#include <math.h>

// Problem constants
#define B_ 4
#define T_ 2048
#define C_ 1024
#define H_ 16
#define D_ 64
#define M_ (B_*T_)   // 8192
#define N_ 1024
#define K_ 1024

// Scratch (device globals: allocation-free). All fp16 planes.
__device__ __half g_x16h[(size_t)M_ * C_];           // x fp16 hi
__device__ __half g_x16l[(size_t)M_ * C_];           // x fp16 lo
__device__ __half g_y16h[(size_t)M_ * C_];           // attention out fp16 hi
__device__ __half g_y16l[(size_t)M_ * C_];           // attention out fp16 lo
__device__ __half g_w16[3u * 1024u * 1024u];         // Wq|Wk|Wv transposed [N,K], single fp16
__device__ __half g_wo16[1024u * 1024u];             // Wo transposed [N,K], single fp16
// fp16 attention operand planes [B,H,T,D]
__device__ __half g_q16h[(size_t)M_ * C_];   // Q prescaled by exp(ls)*0.125*log2e, hi
__device__ __half g_q16l[(size_t)M_ * C_];   // Q lo
__device__ __half g_k16 [(size_t)M_ * C_];   // K single
__device__ __half g_v16 [(size_t)M_ * C_];   // V single

__device__ __forceinline__ uint32_t smem_u32(const void* p) {
    uint32_t a;
    asm("{ .reg .u64 t; cvta.to.shared.u64 t, %1; cvt.u32.u64 %0, t; }" : "=r"(a) : "l"(p));
    return a;
}

#define LDSM4(r0, r1, r2, r3, a) \
    asm volatile("ldmatrix.sync.aligned.m8n8.x4.shared.b16 {%0,%1,%2,%3}, [%4];" \
        : "=r"(r0), "=r"(r1), "=r"(r2), "=r"(r3) : "r"(a))
#define LDSM4T(r0, r1, r2, r3, a) \
    asm volatile("ldmatrix.sync.aligned.m8n8.x4.trans.shared.b16 {%0,%1,%2,%3}, [%4];" \
        : "=r"(r0), "=r"(r1), "=r"(r2), "=r"(r3) : "r"(a))

#define MMA_F16(c, a, b0, b1) \
    asm volatile("mma.sync.aligned.m16n8k16.row.col.f32.f16.f16.f32 " \
        "{%0,%1,%2,%3}, {%4,%5,%6,%7}, {%8,%9}, {%0,%1,%2,%3};" \
        : "+f"((c)[0]), "+f"((c)[1]), "+f"((c)[2]), "+f"((c)[3]) \
        : "r"((a)[0]), "r"((a)[1]), "r"((a)[2]), "r"((a)[3]), "r"(b0), "r"(b1))

#define CP16(dst, src) \
    asm volatile("cp.async.cg.shared.global [%0], [%1], 16;" :: "r"(dst), "l"(src))
#define CPCOMMIT() asm volatile("cp.async.commit_group;" ::: "memory")
#define CPWAIT(n)  asm volatile("cp.async.wait_group %0;" :: "n"(n) : "memory")

__device__ __forceinline__ float ex2(float x) {
    float r;
    asm("ex2.approx.ftz.f32 %0, %1;" : "=f"(r) : "f"(x));
    return r;
}

// fp16 precise split
__device__ __forceinline__ void packpair_h(float a, float b, uint32_t& hi, uint32_t& lo) {
    __half2 h = __floats2half2_rn(a, b);
    float2 hf = __half22float2(h);
    __half2 l = __floats2half2_rn(a - hf.x, b - hf.y);
    hi = *(uint32_t*)&h;
    lo = *(uint32_t*)&l;
}
__device__ __forceinline__ uint32_t pack_h2(float a, float b) {
    __half2 h = __floats2half2_rn(a, b);
    return *(uint32_t*)&h;
}

// ---------------------------------------------------------------------------
// split x: fp32 -> fp16 hi + fp16 lo residual
// ---------------------------------------------------------------------------
__global__ void __launch_bounds__(256) splitx_kernel(const float* __restrict__ in) {
    int i = (blockIdx.x * 256 + threadIdx.x) * 4;
    float4 v = *(const float4*)(in + i);
    __half2 h0 = __floats2half2_rn(v.x, v.y);
    __half2 h1 = __floats2half2_rn(v.z, v.w);
    float2 f0 = __half22float2(h0), f1 = __half22float2(h1);
    ((__half2*)(g_x16h + i))[0] = h0;
    ((__half2*)(g_x16h + i))[1] = h1;
    ((__half2*)(g_x16l + i))[0] = __floats2half2_rn(v.x - f0.x, v.y - f0.y);
    ((__half2*)(g_x16l + i))[1] = __floats2half2_rn(v.z - f1.x, v.w - f1.y);
}

// ---------------------------------------------------------------------------
// transpose weights: Wq/Wk/Wv -> g_w16, Wo -> g_wo16, all single fp16 [N,K]
// ---------------------------------------------------------------------------
__global__ void __launch_bounds__(256) tsplitw_kernel(
    const float* __restrict__ W0, const float* __restrict__ W1,
    const float* __restrict__ W2, const float* __restrict__ W3)
{
    __shared__ float tile[32][33];
    const int widx = blockIdx.z;
    const float* in = (widx == 0) ? W0 : (widx == 1) ? W1 : (widx == 2) ? W2 : W3;
    __half* o16 = (widx < 3) ? (g_w16 + (size_t)widx * 1024 * 1024) : g_wo16;
    int tx = threadIdx.x, ty = threadIdx.y;
    int x = blockIdx.x * 32 + tx, y0 = blockIdx.y * 32;
#pragma unroll
    for (int j = 0; j < 32; j += 8) tile[ty + j][tx] = in[(size_t)(y0 + ty + j) * 1024 + x];
    __syncthreads();
    int x2 = blockIdx.y * 32 + tx, y2 = blockIdx.x * 32;
#pragma unroll
    for (int j = 0; j < 32; j += 8)
        o16[(size_t)(y2 + ty + j) * 1024 + x2] = __float2half(tile[tx][ty + j]);
}

// ---------------------------------------------------------------------------
// fp16 GEMM (2 MMAs/tile): C = A @ B^T. A fp16 hi/lo; B single fp16.
// 2-stage cp.async, 3 planes/stage (60KB total, 2 CTAs/SM).
// mode 0 (QKV, N=3072): Q prescaled fp16 hi/lo; K,V single fp16; [B,H,T,D] scatter.
// mode 1 (out, N=1024): fp32 row-major Cext.
// ---------------------------------------------------------------------------
#define QSPAD 40
#define QPL 10240
#define QSTG (3 * QPL)         // 30720 per stage
#define NT_K 32

__global__ void __launch_bounds__(256, 2) gemm16(
    const __half* __restrict__ Ahi, const __half* __restrict__ Alo,
    const __half* __restrict__ Bw,
    float* __restrict__ Cext, const float* __restrict__ ls, int mode)
{
    extern __shared__ char gsm[];
    const uint32_t sb = smem_u32(gsm);
    const int tid = threadIdx.x;
    const int warp = tid >> 5, lane = tid & 31;
    const int bm = blockIdx.y * 128, bn = blockIdx.x * 128;
    const int wm = (warp >> 2) * 64, wn = (warp & 3) * 32;

    float acc[4][4][4];
#pragma unroll
    for (int i = 0; i < 4; i++)
#pragma unroll
        for (int j = 0; j < 4; j++)
#pragma unroll
            for (int r = 0; r < 4; r++) acc[i][j][r] = 0.f;

    const int lr = tid >> 1, lc = (tid & 1) << 4;
    const size_t aoff = (size_t)(bm + lr) * K_ + lc;
    const size_t boff = (size_t)(bn + lr) * K_ + lc;
    const uint32_t drow = sb + (uint32_t)lr * (QSPAD * 2) + (uint32_t)lc * 2;

#define QISSUE(st, kt) do { \
    uint32_t d = drow + (uint32_t)(st) * QSTG; \
    size_t k0 = (size_t)(kt) * 32; \
    CP16(d,                 Ahi + aoff + k0); \
    CP16(d + 16,            Ahi + aoff + k0 + 8); \
    CP16(d + QPL,           Alo + aoff + k0); \
    CP16(d + QPL + 16,      Alo + aoff + k0 + 8); \
    CP16(d + 2*QPL,         Bw  + boff + k0); \
    CP16(d + 2*QPL + 16,    Bw  + boff + k0 + 8); \
} while (0)

    QISSUE(0, 0);
    CPCOMMIT();

    const uint32_t aAddr = (uint32_t)((wm + (lane & 15)) * (QSPAD * 2) + (((lane >> 4) << 3)) * 2);
    const uint32_t bAddr = (uint32_t)(2 * QPL + (wn + ((lane >> 4) << 3) + (lane & 7)) * (QSPAD * 2) + ((lane & 8)) * 2);

    for (int kt = 0; kt < NT_K; ++kt) {
        {
            int nt = kt + 1;
            if (nt < NT_K) QISSUE(nt & 1, nt);
            CPCOMMIT();
        }
        CPWAIT(1);
        __syncthreads();
        const uint32_t stb = sb + (uint32_t)(kt & 1) * QSTG;

#pragma unroll
        for (int kk = 0; kk < 2; kk++) {
            const uint32_t ko = (uint32_t)(kk * 16 * 2);
            uint32_t ah[4][4], al[4][4];
#pragma unroll
            for (int i = 0; i < 4; i++) {
                uint32_t ad = stb + aAddr + (uint32_t)(i * 16 * QSPAD * 2) + ko;
                LDSM4(ah[i][0], ah[i][1], ah[i][2], ah[i][3], ad);
                LDSM4(al[i][0], al[i][1], al[i][2], al[i][3], ad + QPL);
            }
#pragma unroll
            for (int jb = 0; jb < 2; jb++) {
                uint32_t bh[4];
                uint32_t bd = stb + bAddr + (uint32_t)(jb * 16 * QSPAD * 2) + ko;
                LDSM4(bh[0], bh[1], bh[2], bh[3], bd);
#pragma unroll
                for (int i = 0; i < 4; i++) {
                    MMA_F16(acc[i][2*jb],   ah[i], bh[0], bh[1]);
                    MMA_F16(acc[i][2*jb],   al[i], bh[0], bh[1]);
                    MMA_F16(acc[i][2*jb+1], ah[i], bh[2], bh[3]);
                    MMA_F16(acc[i][2*jb+1], al[i], bh[2], bh[3]);
                }
            }
        }
        __syncthreads();
    }

    const int gr = lane >> 2, gc = (lane & 3) * 2;
    if (mode == 0) {
        const int sel = (bn + wn) >> 10;            // 0=Q 1=K 2=V (warp-constant)
        const int hh = ((bn + wn) >> 6) & 15;
        const float qs = (sel == 0) ? __expf(ls[hh]) * 0.125f * 1.4426950408889634f : 1.f;
#pragma unroll
        for (int i = 0; i < 4; i++)
#pragma unroll
            for (int j = 0; j < 4; j++) {
                int m0 = bm + wm + i * 16 + gr;
                int n0 = bn + wn + j * 8 + gc;
                int d = n0 & 63;
#pragma unroll
                for (int hrow = 0; hrow < 2; hrow++) {
                    int m = m0 + hrow * 8;
                    int b = m >> 11, t = m & (T_ - 1);
                    size_t idx = ((size_t)((b * H_ + hh) * T_ + t)) * D_ + d;
                    float v0 = acc[i][j][hrow*2] * qs, v1 = acc[i][j][hrow*2+1] * qs;
                    if (sel == 0) {
                        uint32_t hv, lv;
                        packpair_h(v0, v1, hv, lv);
                        *(uint32_t*)(g_q16h + idx) = hv;
                        *(uint32_t*)(g_q16l + idx) = lv;
                    } else if (sel == 1) {
                        *(uint32_t*)(g_k16 + idx) = pack_h2(v0, v1);
                    } else {
                        *(uint32_t*)(g_v16 + idx) = pack_h2(v0, v1);
                    }
                }
            }
    } else {
#pragma unroll
        for (int i = 0; i < 4; i++)
#pragma unroll
            for (int j = 0; j < 4; j++) {
                int m0 = bm + wm + i * 16 + gr;
                int n0 = bn + wn + j * 8 + gc;
                *(float2*)&Cext[(size_t)m0 * N_ + n0] = make_float2(acc[i][j][0], acc[i][j][1]);
                *(float2*)&Cext[(size_t)(m0 + 8) * N_ + n0] = make_float2(acc[i][j][2], acc[i][j][3]);
            }
    }
}

// ---------------------------------------------------------------------------
// Flash attention v7 (fp16, 3-stage single-sync pipeline).
// 256 threads, 128 q-rows/CTA. QK^T = 2 MMAs; PV = 1 MMA. No online max.
// ---------------------------------------------------------------------------
#define AST 72
#define PL64  (64 * AST * 2)     // 9216
#define PL16  (16 * AST * 2)     // 2304
#define STAGE_B (2 * PL64)       // 18432: K | V
#define S_NULL  (3 * STAGE_B)    // 55296
#define S_NK  (S_NULL)
#define S_NV  (S_NULL + PL16)
#define S_ATT_TOTAL (S_NULL + 2*PL16)   // 59904

__global__ void __launch_bounds__(256, 2) attn_mma(
    const float* __restrict__ nullk, const float* __restrict__ nullv)
{
    extern __shared__ char sm[];
    const uint32_t sb = smem_u32(sm);
    const int bh = blockIdx.y, h = bh & 15;
    const int qblk = (T_ / 128 - 1) - blockIdx.x;   // longest first
    const int qbase = qblk * 128;
    const int tid = threadIdx.x, warp = tid >> 5, lane = tid & 31;
    const int wm = warp * 16;

    // null tiles: 16 x 64, row 0 real (K, V single fp16)
    for (int i = tid; i < 1024; i += 256) {
        int r = i >> 6, d = i & 63;
        float kvk = (r == 0) ? nullk[h * 64 + d] : 0.f;
        float kvv = (r == 0) ? nullv[h * 64 + d] : 0.f;
        *(__half*)(sm + S_NK + (r * AST + d) * 2) = __float2half(kvk);
        *(__half*)(sm + S_NV + (r * AST + d) * 2) = __float2half(kvv);
    }

    // Q fragments: direct LDG from prescaled fp16 planes
    uint32_t qfh[4][4], qfl[4][4];
    {
        const size_t qrow0 = (size_t)bh * T_ + qbase + wm + (lane >> 2);
        const int cc = (lane & 3) * 2;
#pragma unroll
        for (int kk = 0; kk < 4; kk++) {
#pragma unroll
            for (int rg = 0; rg < 4; rg++) {
                int roff = (rg & 1) * 8;
                int col = kk * 16 + cc + (rg >> 1) * 8;
                size_t idx = (qrow0 + roff) * D_ + col;
                qfh[kk][rg] = *(const uint32_t*)(g_q16h + idx);
                qfl[kk][rg] = *(const uint32_t*)(g_q16l + idx);
            }
        }
    }

    float o[8][4];
#pragma unroll
    for (int j = 0; j < 8; j++)
#pragma unroll
        for (int r = 0; r < 4; r++) o[j][r] = 0.f;
    float l0 = 0.f, l1 = 0.f;

    const int qmin_w = qbase + wm;
    const int qmax_w = qbase + wm + 15;
    const int nkb = (qbase + 128) / 64;      // always >= 2

    // K/V cp.async staging map: row=tid>>2 (0..63), col chunk=(tid&3)*16
    const int sr = tid >> 2, scol = (tid & 3) * 16;
    const uint32_t doff = (uint32_t)((sr * AST + scol) * 2);
    const size_t gbase0 = ((size_t)bh * T_ + sr) * D_ + scol;

#define AISS(st, kb_) do { \
    size_t base_ = gbase0 + (size_t)(kb_) * 64 * D_; \
    uint32_t d_ = sb + (uint32_t)(st) * STAGE_B + doff; \
    CP16(d_,              g_k16 + base_); \
    CP16(d_ + 16,         g_k16 + base_ + 8); \
    CP16(d_ + PL64,       g_v16 + base_); \
    CP16(d_ + PL64 + 16,  g_v16 + base_ + 8); \
} while (0)

    AISS(0, 0); CPCOMMIT();
    AISS(1, 1); CPCOMMIT();

    int st = 0;   // stage of current kb (kb % 3)
    for (int kb = 0; kb < nkb; kb++) {
        CPWAIT(1);                       // stage kb complete (kb+1 may be in flight)
        __syncthreads();                 // visibility + all warps done with stage (kb+2)%3
        {
            int nt = kb + 2;
            if (nt < nkb) { int s2 = st + 2; if (s2 >= 3) s2 -= 3; AISS(s2, nt); }
            CPCOMMIT();
        }
        const uint32_t stb = sb + (uint32_t)st * STAGE_B;
        if (++st == 3) st = 0;
        if (kb * 64 > qmax_w) continue;  // warp fully below diagonal

        // S = Qs K^T   (2 MMAs per acc)
        float s[8][4];
#pragma unroll
        for (int j = 0; j < 8; j++)
#pragma unroll
            for (int r = 0; r < 4; r++) s[j][r] = 0.f;
#pragma unroll
        for (int kk = 0; kk < 4; kk++) {
#pragma unroll
            for (int jb = 0; jb < 4; jb++) {
                uint32_t kf[4];
                uint32_t bd = stb + (uint32_t)((jb * 16 + ((lane >> 4) << 3) + (lane & 7)) * AST
                            + kk * 16 + (lane & 8)) * 2;
                LDSM4(kf[0], kf[1], kf[2], kf[3], bd);
                MMA_F16(s[2*jb],   qfh[kk], kf[0], kf[1]);
                MMA_F16(s[2*jb],   qfl[kk], kf[0], kf[1]);
                MMA_F16(s[2*jb+1], qfh[kk], kf[2], kf[3]);
                MMA_F16(s[2*jb+1], qfl[kk], kf[2], kf[3]);
            }
        }

        // causal mask (diagonal warp-block only)
        if (kb * 64 + 63 > qmin_w) {
            const int q0 = qmin_w + (lane >> 2), q1 = q0 + 8;
#pragma unroll
            for (int j = 0; j < 8; j++) {
                int c = kb * 64 + j * 8 + ((lane & 3) << 1);
                if (c     > q0) s[j][0] = -1e30f;
                if (c + 1 > q0) s[j][1] = -1e30f;
                if (c     > q1) s[j][2] = -1e30f;
                if (c + 1 > q1) s[j][3] = -1e30f;
            }
        }

        // p = exp2(s); accumulate l
#pragma unroll
        for (int j = 0; j < 8; j++) {
            s[j][0] = ex2(s[j][0]); s[j][1] = ex2(s[j][1]);
            s[j][2] = ex2(s[j][2]); s[j][3] = ex2(s[j][3]);
            l0 += s[j][0] + s[j][1];
            l1 += s[j][2] + s[j][3];
        }

        // O += P V   (1 MMA per acc)
#pragma unroll
        for (int kk = 0; kk < 4; kk++) {
            uint32_t ph[4];
            ph[0] = pack_h2(s[2*kk][0],   s[2*kk][1]);
            ph[1] = pack_h2(s[2*kk][2],   s[2*kk][3]);
            ph[2] = pack_h2(s[2*kk+1][0], s[2*kk+1][1]);
            ph[3] = pack_h2(s[2*kk+1][2], s[2*kk+1][3]);
#pragma unroll
            for (int g = 0; g < 4; g++) {
                uint32_t vh[4];
                uint32_t vd = stb + PL64 + (uint32_t)((kk * 16 + (lane & 15)) * AST
                            + g * 16 + ((lane >> 4) << 3)) * 2;
                LDSM4T(vh[0], vh[1], vh[2], vh[3], vd);
                MMA_F16(o[2*g],   ph, vh[0], vh[1]);
                MMA_F16(o[2*g+1], ph, vh[2], vh[3]);
            }
        }
    }

    // null-KV block (16 padded cols, col 0 real)
    {
        float s[2][4];
#pragma unroll
        for (int j = 0; j < 2; j++)
#pragma unroll
            for (int r = 0; r < 4; r++) s[j][r] = 0.f;
#pragma unroll
        for (int kk = 0; kk < 4; kk++) {
            uint32_t kf[4];
            uint32_t bd = sb + S_NK + (uint32_t)((((lane >> 4) << 3) + (lane & 7)) * AST
                        + kk * 16 + (lane & 8)) * 2;
            LDSM4(kf[0], kf[1], kf[2], kf[3], bd);
            MMA_F16(s[0], qfh[kk], kf[0], kf[1]);
            MMA_F16(s[0], qfl[kk], kf[0], kf[1]);
            MMA_F16(s[1], qfh[kk], kf[2], kf[3]);
            MMA_F16(s[1], qfl[kk], kf[2], kf[3]);
        }
#pragma unroll
        for (int j = 0; j < 2; j++) {
            int c = j * 8 + ((lane & 3) << 1);
            s[j][0] = (c == 0) ? ex2(s[j][0]) : 0.f;
            s[j][1] = 0.f;
            s[j][2] = (c == 0) ? ex2(s[j][2]) : 0.f;
            s[j][3] = 0.f;
            l0 += s[j][0];
            l1 += s[j][2];
        }

        uint32_t ph[4];
        ph[0] = pack_h2(s[0][0], s[0][1]);
        ph[1] = pack_h2(s[0][2], s[0][3]);
        ph[2] = pack_h2(s[1][0], s[1][1]);
        ph[3] = pack_h2(s[1][2], s[1][3]);
#pragma unroll
        for (int g = 0; g < 4; g++) {
            uint32_t vh[4];
            uint32_t vd = sb + S_NV + (uint32_t)((lane & 15) * AST + g * 16 + ((lane >> 4) << 3)) * 2;
            LDSM4T(vh[0], vh[1], vh[2], vh[3], vd);
            MMA_F16(o[2*g],   ph, vh[0], vh[1]);
            MMA_F16(o[2*g+1], ph, vh[2], vh[3]);
        }
    }

    // finalize: quad-reduce l, normalize, write y fp16 hi/lo
    l0 += __shfl_xor_sync(0xffffffffu, l0, 1);
    l0 += __shfl_xor_sync(0xffffffffu, l0, 2);
    l1 += __shfl_xor_sync(0xffffffffu, l1, 1);
    l1 += __shfl_xor_sync(0xffffffffu, l1, 2);
    const float i0 = 1.f / l0, i1 = 1.f / l1;
    const int b = bh >> 4;
    const int t0 = qbase + wm + (lane >> 2), t1 = t0 + 8;
    const int cb = h * 64 + ((lane & 3) << 1);
#pragma unroll
    for (int j = 0; j < 8; j++) {
        int cc = cb + j * 8;
        size_t i_0 = (size_t)(b * T_ + t0) * C_ + cc;
        size_t i_1 = (size_t)(b * T_ + t1) * C_ + cc;
        uint32_t hv, lv;
        packpair_h(o[j][0] * i0, o[j][1] * i0, hv, lv);
        *(uint32_t*)(g_y16h + i_0) = hv;
        *(uint32_t*)(g_y16l + i_0) = lv;
        packpair_h(o[j][2] * i1, o[j][3] * i1, hv, lv);
        *(uint32_t*)(g_y16h + i_1) = hv;
        *(uint32_t*)(g_y16l + i_1) = lv;
    }
}

// ---------------------------------------------------------------------------
// kernel_launch
// Inputs: x, Wq, Wk, Wv, Wo, null_k, null_v, logit_scale
// ---------------------------------------------------------------------------
extern "C" void kernel_launch(void* const* d_in, const int* in_sizes, int n_in,
                              void* d_out, int out_size) {
    const float* x  = (const float*)d_in[0];
    const float* Wq = (const float*)d_in[1];
    const float* Wk = (const float*)d_in[2];
    const float* Wv = (const float*)d_in[3];
    const float* Wo = (const float*)d_in[4];
    const float* nk = (const float*)d_in[5];
    const float* nv = (const float*)d_in[6];
    const float* ls = (const float*)d_in[7];
    float* out = (float*)d_out;

    __half *x16h, *x16l, *y16h, *y16l, *w16, *wo16;
    cudaGetSymbolAddress((void**)&x16h, g_x16h);
    cudaGetSymbolAddress((void**)&x16l, g_x16l);
    cudaGetSymbolAddress((void**)&y16h, g_y16h);
    cudaGetSymbolAddress((void**)&y16l, g_y16l);
    cudaGetSymbolAddress((void**)&w16, g_w16);
    cudaGetSymbolAddress((void**)&wo16, g_wo16);

    const int GEMM_SMEM = 2 * QSTG;       // 61440
    cudaFuncSetAttribute(gemm16, cudaFuncAttributeMaxDynamicSharedMemorySize, GEMM_SMEM);
    cudaFuncSetAttribute(attn_mma, cudaFuncAttributeMaxDynamicSharedMemorySize, S_ATT_TOTAL);

    splitx_kernel<<<(M_ * C_) / (256 * 4), 256>>>(x);
    tsplitw_kernel<<<dim3(32, 32, 4), dim3(32, 8)>>>(Wq, Wk, Wv, Wo);

    gemm16<<<dim3(24, 64), 256, GEMM_SMEM>>>(x16h, x16l, w16, nullptr, ls, 0);

    attn_mma<<<dim3(T_ / 128, B_ * H_), 256, S_ATT_TOTAL>>>(nk, nv);

    gemm16<<<dim3(8, 64), 256, GEMM_SMEM>>>(y16h, y16l, wo16, out, ls, 1);
}

// round 12
// speedup vs baseline: 6.5233x; 1.2508x over previous
#include <cuda_runtime.h>
#include <cuda_bf16.h>
#include <cuda_fp16.h>
#include <cstdint>
#include <math.h>

// Problem constants
#define B_ 4
#define T_ 2048
#define C_ 1024
#define H_ 16
#define D_ 64
#define M_ (B_*T_)   // 8192
#define N_ 1024
#define K_ 1024

// Scratch (device globals: allocation-free). All fp16 planes.
__device__ __half g_x16[(size_t)M_ * C_];            // x single fp16
__device__ __half g_y16h[(size_t)M_ * C_];           // attention out fp16 hi
__device__ __half g_y16l[(size_t)M_ * C_];           // attention out fp16 lo
__device__ __half g_w16[3u * 1024u * 1024u];         // Wq|Wk|Wv transposed [N,K], single fp16
__device__ __half g_wo16[1024u * 1024u];             // Wo transposed [N,K], single fp16
// fp16 attention operand planes [B,H,T,D]
__device__ __half g_q16h[(size_t)M_ * C_];   // Q prescaled by exp(ls)*0.125*log2e, hi
__device__ __half g_q16l[(size_t)M_ * C_];   // Q lo
__device__ __half g_k16 [(size_t)M_ * C_];   // K single
__device__ __half g_v16 [(size_t)M_ * C_];   // V single

__device__ __forceinline__ uint32_t smem_u32(const void* p) {
    uint32_t a;
    asm("{ .reg .u64 t; cvta.to.shared.u64 t, %1; cvt.u32.u64 %0, t; }" : "=r"(a) : "l"(p));
    return a;
}

#define LDSM4(r0, r1, r2, r3, a) \
    asm volatile("ldmatrix.sync.aligned.m8n8.x4.shared.b16 {%0,%1,%2,%3}, [%4];" \
        : "=r"(r0), "=r"(r1), "=r"(r2), "=r"(r3) : "r"(a))
#define LDSM4T(r0, r1, r2, r3, a) \
    asm volatile("ldmatrix.sync.aligned.m8n8.x4.trans.shared.b16 {%0,%1,%2,%3}, [%4];" \
        : "=r"(r0), "=r"(r1), "=r"(r2), "=r"(r3) : "r"(a))

#define MMA_F16(c, a, b0, b1) \
    asm volatile("mma.sync.aligned.m16n8k16.row.col.f32.f16.f16.f32 " \
        "{%0,%1,%2,%3}, {%4,%5,%6,%7}, {%8,%9}, {%0,%1,%2,%3};" \
        : "+f"((c)[0]), "+f"((c)[1]), "+f"((c)[2]), "+f"((c)[3]) \
        : "r"((a)[0]), "r"((a)[1]), "r"((a)[2]), "r"((a)[3]), "r"(b0), "r"(b1))

#define CP16(dst, src) \
    asm volatile("cp.async.cg.shared.global [%0], [%1], 16;" :: "r"(dst), "l"(src))
#define CPCOMMIT() asm volatile("cp.async.commit_group;" ::: "memory")
#define CPWAIT(n)  asm volatile("cp.async.wait_group %0;" :: "n"(n) : "memory")

__device__ __forceinline__ float ex2(float x) {
    float r;
    asm("ex2.approx.ftz.f32 %0, %1;" : "=f"(r) : "f"(x));
    return r;
}

// fp16 precise split
__device__ __forceinline__ void packpair_h(float a, float b, uint32_t& hi, uint32_t& lo) {
    __half2 h = __floats2half2_rn(a, b);
    float2 hf = __half22float2(h);
    __half2 l = __floats2half2_rn(a - hf.x, b - hf.y);
    hi = *(uint32_t*)&h;
    lo = *(uint32_t*)&l;
}
__device__ __forceinline__ uint32_t pack_h2(float a, float b) {
    __half2 h = __floats2half2_rn(a, b);
    return *(uint32_t*)&h;
}

// ---------------------------------------------------------------------------
// convert x: fp32 -> single fp16
// ---------------------------------------------------------------------------
__global__ void __launch_bounds__(256) cvtx_kernel(const float* __restrict__ in) {
    int i = (blockIdx.x * 256 + threadIdx.x) * 4;
    float4 v = *(const float4*)(in + i);
    ((__half2*)(g_x16 + i))[0] = __floats2half2_rn(v.x, v.y);
    ((__half2*)(g_x16 + i))[1] = __floats2half2_rn(v.z, v.w);
}

// ---------------------------------------------------------------------------
// transpose weights: Wq/Wk/Wv -> g_w16, Wo -> g_wo16, all single fp16 [N,K]
// ---------------------------------------------------------------------------
__global__ void __launch_bounds__(256) tsplitw_kernel(
    const float* __restrict__ W0, const float* __restrict__ W1,
    const float* __restrict__ W2, const float* __restrict__ W3)
{
    __shared__ float tile[32][33];
    const int widx = blockIdx.z;
    const float* in = (widx == 0) ? W0 : (widx == 1) ? W1 : (widx == 2) ? W2 : W3;
    __half* o16 = (widx < 3) ? (g_w16 + (size_t)widx * 1024 * 1024) : g_wo16;
    int tx = threadIdx.x, ty = threadIdx.y;
    int x = blockIdx.x * 32 + tx, y0 = blockIdx.y * 32;
#pragma unroll
    for (int j = 0; j < 32; j += 8) tile[ty + j][tx] = in[(size_t)(y0 + ty + j) * 1024 + x];
    __syncthreads();
    int x2 = blockIdx.y * 32 + tx, y2 = blockIdx.x * 32;
#pragma unroll
    for (int j = 0; j < 32; j += 8)
        o16[(size_t)(y2 + ty + j) * 1024 + x2] = __float2half(tile[tx][ty + j]);
}

#define NT_K 32
#define GPL 10240          // one 128x40-fp16 plane (bytes)

// ---------------------------------------------------------------------------
// QKV GEMM, 1 MMA/tile: C = x @ W^T, N=3072. A single fp16, B single fp16.
// 2-stage cp.async, 2 planes/stage (40KB total, 2 CTAs/SM).
// Epilogue: Q prescaled fp16 hi/lo; K,V single fp16; [B,H,T,D] scatter.
// ---------------------------------------------------------------------------
#define QSTG (2 * GPL)     // 20480 per stage

__global__ void __launch_bounds__(256, 2) gemm_qkv(const float* __restrict__ ls) {
    extern __shared__ char gsm[];
    const uint32_t sb = smem_u32(gsm);
    const int tid = threadIdx.x;
    const int warp = tid >> 5, lane = tid & 31;
    const int bm = blockIdx.y * 128, bn = blockIdx.x * 128;
    const int wm = (warp >> 2) * 64, wn = (warp & 3) * 32;

    float acc[4][4][4];
#pragma unroll
    for (int i = 0; i < 4; i++)
#pragma unroll
        for (int j = 0; j < 4; j++)
#pragma unroll
            for (int r = 0; r < 4; r++) acc[i][j][r] = 0.f;

    const int lr = tid >> 1, lc = (tid & 1) << 4;
    const size_t aoff = (size_t)(bm + lr) * K_ + lc;
    const size_t boff = (size_t)(bn + lr) * K_ + lc;
    const uint32_t drow = sb + (uint32_t)lr * 80 + (uint32_t)lc * 2;

#define QISSUE(st, kt) do { \
    uint32_t d = drow + (uint32_t)(st) * QSTG; \
    size_t k0 = (size_t)(kt) * 32; \
    CP16(d,              g_x16 + aoff + k0); \
    CP16(d + 16,         g_x16 + aoff + k0 + 8); \
    CP16(d + GPL,        g_w16 + boff + k0); \
    CP16(d + GPL + 16,   g_w16 + boff + k0 + 8); \
} while (0)

    QISSUE(0, 0);
    CPCOMMIT();

    const uint32_t aAddr = (uint32_t)((wm + (lane & 15)) * 80 + (((lane >> 4) << 3)) * 2);
    const uint32_t bAddr = (uint32_t)(GPL + (wn + ((lane >> 4) << 3) + (lane & 7)) * 80 + ((lane & 8)) * 2);

    for (int kt = 0; kt < NT_K; ++kt) {
        {
            int nt = kt + 1;
            if (nt < NT_K) QISSUE(nt & 1, nt);
            CPCOMMIT();
        }
        CPWAIT(1);
        __syncthreads();
        const uint32_t stb = sb + (uint32_t)(kt & 1) * QSTG;

#pragma unroll
        for (int kk = 0; kk < 2; kk++) {
            const uint32_t ko = (uint32_t)(kk * 32);
            uint32_t ah[4][4];
#pragma unroll
            for (int i = 0; i < 4; i++) {
                uint32_t ad = stb + aAddr + (uint32_t)(i * 16 * 80) + ko;
                LDSM4(ah[i][0], ah[i][1], ah[i][2], ah[i][3], ad);
            }
#pragma unroll
            for (int jb = 0; jb < 2; jb++) {
                uint32_t bh[4];
                uint32_t bd = stb + bAddr + (uint32_t)(jb * 16 * 80) + ko;
                LDSM4(bh[0], bh[1], bh[2], bh[3], bd);
#pragma unroll
                for (int i = 0; i < 4; i++) {
                    MMA_F16(acc[i][2*jb],   ah[i], bh[0], bh[1]);
                    MMA_F16(acc[i][2*jb+1], ah[i], bh[2], bh[3]);
                }
            }
        }
        __syncthreads();
    }

    const int gr = lane >> 2, gc = (lane & 3) * 2;
    const int sel = (bn + wn) >> 10;            // 0=Q 1=K 2=V (warp-constant)
    const int hh = ((bn + wn) >> 6) & 15;
    const float qs = (sel == 0) ? __expf(ls[hh]) * 0.125f * 1.4426950408889634f : 1.f;
#pragma unroll
    for (int i = 0; i < 4; i++)
#pragma unroll
        for (int j = 0; j < 4; j++) {
            int m0 = bm + wm + i * 16 + gr;
            int n0 = bn + wn + j * 8 + gc;
            int d = n0 & 63;
#pragma unroll
            for (int hrow = 0; hrow < 2; hrow++) {
                int m = m0 + hrow * 8;
                int b = m >> 11, t = m & (T_ - 1);
                size_t idx = ((size_t)((b * H_ + hh) * T_ + t)) * D_ + d;
                float v0 = acc[i][j][hrow*2] * qs, v1 = acc[i][j][hrow*2+1] * qs;
                if (sel == 0) {
                    uint32_t hv, lv;
                    packpair_h(v0, v1, hv, lv);
                    *(uint32_t*)(g_q16h + idx) = hv;
                    *(uint32_t*)(g_q16l + idx) = lv;
                } else if (sel == 1) {
                    *(uint32_t*)(g_k16 + idx) = pack_h2(v0, v1);
                } else {
                    *(uint32_t*)(g_v16 + idx) = pack_h2(v0, v1);
                }
            }
        }
}

// ---------------------------------------------------------------------------
// Out-projection GEMM, 2 MMAs/tile: out = y @ Wo^T. y fp16 hi/lo, Wo single fp16.
// 2-stage cp.async, 3 planes/stage (60KB, 2 CTAs/SM). fp32 row-major out.
// ---------------------------------------------------------------------------
#define OSTG (3 * GPL)     // 30720 per stage

__global__ void __launch_bounds__(256, 2) gemm_out(float* __restrict__ Cext) {
    extern __shared__ char gsm[];
    const uint32_t sb = smem_u32(gsm);
    const int tid = threadIdx.x;
    const int warp = tid >> 5, lane = tid & 31;
    const int bm = blockIdx.y * 128, bn = blockIdx.x * 128;
    const int wm = (warp >> 2) * 64, wn = (warp & 3) * 32;

    float acc[4][4][4];
#pragma unroll
    for (int i = 0; i < 4; i++)
#pragma unroll
        for (int j = 0; j < 4; j++)
#pragma unroll
            for (int r = 0; r < 4; r++) acc[i][j][r] = 0.f;

    const int lr = tid >> 1, lc = (tid & 1) << 4;
    const size_t aoff = (size_t)(bm + lr) * K_ + lc;
    const size_t boff = (size_t)(bn + lr) * K_ + lc;
    const uint32_t drow = sb + (uint32_t)lr * 80 + (uint32_t)lc * 2;

#define OISSUE(st, kt) do { \
    uint32_t d = drow + (uint32_t)(st) * OSTG; \
    size_t k0 = (size_t)(kt) * 32; \
    CP16(d,                g_y16h + aoff + k0); \
    CP16(d + 16,           g_y16h + aoff + k0 + 8); \
    CP16(d + GPL,          g_y16l + aoff + k0); \
    CP16(d + GPL + 16,     g_y16l + aoff + k0 + 8); \
    CP16(d + 2*GPL,        g_wo16 + boff + k0); \
    CP16(d + 2*GPL + 16,   g_wo16 + boff + k0 + 8); \
} while (0)

    OISSUE(0, 0);
    CPCOMMIT();

    const uint32_t aAddr = (uint32_t)((wm + (lane & 15)) * 80 + (((lane >> 4) << 3)) * 2);
    const uint32_t bAddr = (uint32_t)(2 * GPL + (wn + ((lane >> 4) << 3) + (lane & 7)) * 80 + ((lane & 8)) * 2);

    for (int kt = 0; kt < NT_K; ++kt) {
        {
            int nt = kt + 1;
            if (nt < NT_K) OISSUE(nt & 1, nt);
            CPCOMMIT();
        }
        CPWAIT(1);
        __syncthreads();
        const uint32_t stb = sb + (uint32_t)(kt & 1) * OSTG;

#pragma unroll
        for (int kk = 0; kk < 2; kk++) {
            const uint32_t ko = (uint32_t)(kk * 32);
            uint32_t ah[4][4], al[4][4];
#pragma unroll
            for (int i = 0; i < 4; i++) {
                uint32_t ad = stb + aAddr + (uint32_t)(i * 16 * 80) + ko;
                LDSM4(ah[i][0], ah[i][1], ah[i][2], ah[i][3], ad);
                LDSM4(al[i][0], al[i][1], al[i][2], al[i][3], ad + GPL);
            }
#pragma unroll
            for (int jb = 0; jb < 2; jb++) {
                uint32_t bh[4];
                uint32_t bd = stb + bAddr + (uint32_t)(jb * 16 * 80) + ko;
                LDSM4(bh[0], bh[1], bh[2], bh[3], bd);
#pragma unroll
                for (int i = 0; i < 4; i++) {
                    MMA_F16(acc[i][2*jb],   ah[i], bh[0], bh[1]);
                    MMA_F16(acc[i][2*jb],   al[i], bh[0], bh[1]);
                    MMA_F16(acc[i][2*jb+1], ah[i], bh[2], bh[3]);
                    MMA_F16(acc[i][2*jb+1], al[i], bh[2], bh[3]);
                }
            }
        }
        __syncthreads();
    }

    const int gr = lane >> 2, gc = (lane & 3) * 2;
#pragma unroll
    for (int i = 0; i < 4; i++)
#pragma unroll
        for (int j = 0; j < 4; j++) {
            int m0 = bm + wm + i * 16 + gr;
            int n0 = bn + wn + j * 8 + gc;
            *(float2*)&Cext[(size_t)m0 * N_ + n0] = make_float2(acc[i][j][0], acc[i][j][1]);
            *(float2*)&Cext[(size_t)(m0 + 8) * N_ + n0] = make_float2(acc[i][j][2], acc[i][j][3]);
        }
}

// ---------------------------------------------------------------------------
// Flash attention (fp16, 2-stage — reverted to R10 structure, fp16 y out).
// 256 threads, 128 q-rows/CTA. QK^T = 2 MMAs; PV = 1 MMA. No online max.
// ---------------------------------------------------------------------------
#define AST 72
#define PL64  (64 * AST * 2)     // 9216
#define PL16  (16 * AST * 2)     // 2304
#define STAGE_B (2 * PL64)       // 18432: K | V
#define S_NULL  (2 * STAGE_B)    // 36864
#define S_NK  (S_NULL)
#define S_NV  (S_NULL + PL16)
#define S_ATT_TOTAL (S_NULL + 2*PL16)   // 41472

__global__ void __launch_bounds__(256, 2) attn_mma(
    const float* __restrict__ nullk, const float* __restrict__ nullv)
{
    extern __shared__ char sm[];
    const uint32_t sb = smem_u32(sm);
    const int bh = blockIdx.y, h = bh & 15;
    const int qblk = (T_ / 128 - 1) - blockIdx.x;   // longest first
    const int qbase = qblk * 128;
    const int tid = threadIdx.x, warp = tid >> 5, lane = tid & 31;
    const int wm = warp * 16;

    // null tiles: 16 x 64, row 0 real (K, V single fp16)
    for (int i = tid; i < 1024; i += 256) {
        int r = i >> 6, d = i & 63;
        float kvk = (r == 0) ? nullk[h * 64 + d] : 0.f;
        float kvv = (r == 0) ? nullv[h * 64 + d] : 0.f;
        *(__half*)(sm + S_NK + (r * AST + d) * 2) = __float2half(kvk);
        *(__half*)(sm + S_NV + (r * AST + d) * 2) = __float2half(kvv);
    }

    // Q fragments: direct LDG from prescaled fp16 planes
    uint32_t qfh[4][4], qfl[4][4];
    {
        const size_t qrow0 = (size_t)bh * T_ + qbase + wm + (lane >> 2);
        const int cc = (lane & 3) * 2;
#pragma unroll
        for (int kk = 0; kk < 4; kk++) {
#pragma unroll
            for (int rg = 0; rg < 4; rg++) {
                int roff = (rg & 1) * 8;
                int col = kk * 16 + cc + (rg >> 1) * 8;
                size_t idx = (qrow0 + roff) * D_ + col;
                qfh[kk][rg] = *(const uint32_t*)(g_q16h + idx);
                qfl[kk][rg] = *(const uint32_t*)(g_q16l + idx);
            }
        }
    }

    float o[8][4];
#pragma unroll
    for (int j = 0; j < 8; j++)
#pragma unroll
        for (int r = 0; r < 4; r++) o[j][r] = 0.f;
    float l0 = 0.f, l1 = 0.f;

    const int qmin_w = qbase + wm;
    const int qmax_w = qbase + wm + 15;
    const int nkb = (qbase + 128) / 64;

    // K/V cp.async staging map: row=tid>>2 (0..63), col chunk=(tid&3)*16
    const int sr = tid >> 2, scol = (tid & 3) * 16;
    const uint32_t doff = (uint32_t)((sr * AST + scol) * 2);
    const size_t gbase0 = ((size_t)bh * T_ + sr) * D_ + scol;

#define AISS(st, kb_) do { \
    size_t base_ = gbase0 + (size_t)(kb_) * 64 * D_; \
    uint32_t d_ = sb + (uint32_t)(st) * STAGE_B + doff; \
    CP16(d_,              g_k16 + base_); \
    CP16(d_ + 16,         g_k16 + base_ + 8); \
    CP16(d_ + PL64,       g_v16 + base_); \
    CP16(d_ + PL64 + 16,  g_v16 + base_ + 8); \
} while (0)

    AISS(0, 0);
    CPCOMMIT();

    for (int kb = 0; kb < nkb; kb++) {
        __syncthreads();                 // everyone done reading the other stage
        if (kb + 1 < nkb) AISS((kb + 1) & 1, kb + 1);
        CPCOMMIT();
        CPWAIT(1);
        __syncthreads();                 // stage kb visible to all
        if (kb * 64 > qmax_w) continue;  // warp fully below diagonal
        const uint32_t stb = sb + (uint32_t)(kb & 1) * STAGE_B;

        // S = Qs K^T   (2 MMAs per acc)
        float s[8][4];
#pragma unroll
        for (int j = 0; j < 8; j++)
#pragma unroll
            for (int r = 0; r < 4; r++) s[j][r] = 0.f;
#pragma unroll
        for (int kk = 0; kk < 4; kk++) {
#pragma unroll
            for (int jb = 0; jb < 4; jb++) {
                uint32_t kf[4];
                uint32_t bd = stb + (uint32_t)((jb * 16 + ((lane >> 4) << 3) + (lane & 7)) * AST
                            + kk * 16 + (lane & 8)) * 2;
                LDSM4(kf[0], kf[1], kf[2], kf[3], bd);
                MMA_F16(s[2*jb],   qfh[kk], kf[0], kf[1]);
                MMA_F16(s[2*jb],   qfl[kk], kf[0], kf[1]);
                MMA_F16(s[2*jb+1], qfh[kk], kf[2], kf[3]);
                MMA_F16(s[2*jb+1], qfl[kk], kf[2], kf[3]);
            }
        }

        // causal mask (diagonal warp-block only)
        if (kb * 64 + 63 > qmin_w) {
            const int q0 = qmin_w + (lane >> 2), q1 = q0 + 8;
#pragma unroll
            for (int j = 0; j < 8; j++) {
                int c = kb * 64 + j * 8 + ((lane & 3) << 1);
                if (c     > q0) s[j][0] = -1e30f;
                if (c + 1 > q0) s[j][1] = -1e30f;
                if (c     > q1) s[j][2] = -1e30f;
                if (c + 1 > q1) s[j][3] = -1e30f;
            }
        }

        // p = exp2(s); accumulate l
#pragma unroll
        for (int j = 0; j < 8; j++) {
            s[j][0] = ex2(s[j][0]); s[j][1] = ex2(s[j][1]);
            s[j][2] = ex2(s[j][2]); s[j][3] = ex2(s[j][3]);
            l0 += s[j][0] + s[j][1];
            l1 += s[j][2] + s[j][3];
        }

        // O += P V   (1 MMA per acc)
#pragma unroll
        for (int kk = 0; kk < 4; kk++) {
            uint32_t ph[4];
            ph[0] = pack_h2(s[2*kk][0],   s[2*kk][1]);
            ph[1] = pack_h2(s[2*kk][2],   s[2*kk][3]);
            ph[2] = pack_h2(s[2*kk+1][0], s[2*kk+1][1]);
            ph[3] = pack_h2(s[2*kk+1][2], s[2*kk+1][3]);
#pragma unroll
            for (int g = 0; g < 4; g++) {
                uint32_t vh[4];
                uint32_t vd = stb + PL64 + (uint32_t)((kk * 16 + (lane & 15)) * AST
                            + g * 16 + ((lane >> 4) << 3)) * 2;
                LDSM4T(vh[0], vh[1], vh[2], vh[3], vd);
                MMA_F16(o[2*g],   ph, vh[0], vh[1]);
                MMA_F16(o[2*g+1], ph, vh[2], vh[3]);
            }
        }
    }

    // null-KV block (16 padded cols, col 0 real)
    {
        float s[2][4];
#pragma unroll
        for (int j = 0; j < 2; j++)
#pragma unroll
            for (int r = 0; r < 4; r++) s[j][r] = 0.f;
#pragma unroll
        for (int kk = 0; kk < 4; kk++) {
            uint32_t kf[4];
            uint32_t bd = sb + S_NK + (uint32_t)((((lane >> 4) << 3) + (lane & 7)) * AST
                        + kk * 16 + (lane & 8)) * 2;
            LDSM4(kf[0], kf[1], kf[2], kf[3], bd);
            MMA_F16(s[0], qfh[kk], kf[0], kf[1]);
            MMA_F16(s[0], qfl[kk], kf[0], kf[1]);
            MMA_F16(s[1], qfh[kk], kf[2], kf[3]);
            MMA_F16(s[1], qfl[kk], kf[2], kf[3]);
        }
#pragma unroll
        for (int j = 0; j < 2; j++) {
            int c = j * 8 + ((lane & 3) << 1);
            s[j][0] = (c == 0) ? ex2(s[j][0]) : 0.f;
            s[j][1] = 0.f;
            s[j][2] = (c == 0) ? ex2(s[j][2]) : 0.f;
            s[j][3] = 0.f;
            l0 += s[j][0];
            l1 += s[j][2];
        }

        uint32_t ph[4];
        ph[0] = pack_h2(s[0][0], s[0][1]);
        ph[1] = pack_h2(s[0][2], s[0][3]);
        ph[2] = pack_h2(s[1][0], s[1][1]);
        ph[3] = pack_h2(s[1][2], s[1][3]);
#pragma unroll
        for (int g = 0; g < 4; g++) {
            uint32_t vh[4];
            uint32_t vd = sb + S_NV + (uint32_t)((lane & 15) * AST + g * 16 + ((lane >> 4) << 3)) * 2;
            LDSM4T(vh[0], vh[1], vh[2], vh[3], vd);
            MMA_F16(o[2*g],   ph, vh[0], vh[1]);
            MMA_F16(o[2*g+1], ph, vh[2], vh[3]);
        }
    }

    // finalize: quad-reduce l, normalize, write y fp16 hi/lo
    l0 += __shfl_xor_sync(0xffffffffu, l0, 1);
    l0 += __shfl_xor_sync(0xffffffffu, l0, 2);
    l1 += __shfl_xor_sync(0xffffffffu, l1, 1);
    l1 += __shfl_xor_sync(0xffffffffu, l1, 2);
    const float i0 = 1.f / l0, i1 = 1.f / l1;
    const int b = bh >> 4;
    const int t0 = qbase + wm + (lane >> 2), t1 = t0 + 8;
    const int cb = h * 64 + ((lane & 3) << 1);
#pragma unroll
    for (int j = 0; j < 8; j++) {
        int cc = cb + j * 8;
        size_t i_0 = (size_t)(b * T_ + t0) * C_ + cc;
        size_t i_1 = (size_t)(b * T_ + t1) * C_ + cc;
        uint32_t hv, lv;
        packpair_h(o[j][0] * i0, o[j][1] * i0, hv, lv);
        *(uint32_t*)(g_y16h + i_0) = hv;
        *(uint32_t*)(g_y16l + i_0) = lv;
        packpair_h(o[j][2] * i1, o[j][3] * i1, hv, lv);
        *(uint32_t*)(g_y16h + i_1) = hv;
        *(uint32_t*)(g_y16l + i_1) = lv;
    }
}

// ---------------------------------------------------------------------------
// kernel_launch
// Inputs: x, Wq, Wk, Wv, Wo, null_k, null_v, logit_scale
// ---------------------------------------------------------------------------
extern "C" void kernel_launch(void* const* d_in, const int* in_sizes, int n_in,
                              void* d_out, int out_size) {
    const float* x  = (const float*)d_in[0];
    const float* Wq = (const float*)d_in[1];
    const float* Wk = (const float*)d_in[2];
    const float* Wv = (const float*)d_in[3];
    const float* Wo = (const float*)d_in[4];
    const float* nk = (const float*)d_in[5];
    const float* nv = (const float*)d_in[6];
    const float* ls = (const float*)d_in[7];
    float* out = (float*)d_out;

    const int QKV_SMEM = 2 * QSTG;        // 40960
    const int OUT_SMEM = 2 * OSTG;        // 61440
    cudaFuncSetAttribute(gemm_qkv, cudaFuncAttributeMaxDynamicSharedMemorySize, QKV_SMEM);
    cudaFuncSetAttribute(gemm_out, cudaFuncAttributeMaxDynamicSharedMemorySize, OUT_SMEM);
    cudaFuncSetAttribute(attn_mma, cudaFuncAttributeMaxDynamicSharedMemorySize, S_ATT_TOTAL);

    cvtx_kernel<<<(M_ * C_) / (256 * 4), 256>>>(x);
    tsplitw_kernel<<<dim3(32, 32, 4), dim3(32, 8)>>>(Wq, Wk, Wv, Wo);

    gemm_qkv<<<dim3(24, 64), 256, QKV_SMEM>>>(ls);

    attn_mma<<<dim3(T_ / 128, B_ * H_), 256, S_ATT_TOTAL>>>(nk, nv);

    gemm_out<<<dim3(8, 64), 256, OUT_SMEM>>>(out);
}

// round 13
// speedup vs baseline: 8.1044x; 1.2424x over previous
#include <cuda_runtime.h>
#include <cuda_fp16.h>
#include <cstdint>
#include <math.h>

// Problem constants
#define B_ 4
#define T_ 2048
#define C_ 1024
#define H_ 16
#define D_ 64
#define M_ (B_*T_)   // 8192
#define N_ 1024
#define K_ 1024

// Scratch (device globals: allocation-free). All single fp16 planes.
__device__ __half g_x16[(size_t)M_ * C_];            // x
__device__ __half g_y16[(size_t)M_ * C_];            // attention out
__device__ __half g_w16[3u * 1024u * 1024u];         // Wq|Wk|Wv transposed [N,K]
__device__ __half g_wo16[1024u * 1024u];             // Wo transposed [N,K]
// fp16 attention operand planes [B,H,T,D]
__device__ __half g_q16[(size_t)M_ * C_];            // Q prescaled by exp(ls)*0.125*log2e
__device__ __half g_k16[(size_t)M_ * C_];            // K
__device__ __half g_v16[(size_t)M_ * C_];            // V

__device__ __forceinline__ uint32_t smem_u32(const void* p) {
    uint32_t a;
    asm("{ .reg .u64 t; cvta.to.shared.u64 t, %1; cvt.u32.u64 %0, t; }" : "=r"(a) : "l"(p));
    return a;
}

#define LDSM4(r0, r1, r2, r3, a) \
    asm volatile("ldmatrix.sync.aligned.m8n8.x4.shared.b16 {%0,%1,%2,%3}, [%4];" \
        : "=r"(r0), "=r"(r1), "=r"(r2), "=r"(r3) : "r"(a))
#define LDSM4T(r0, r1, r2, r3, a) \
    asm volatile("ldmatrix.sync.aligned.m8n8.x4.trans.shared.b16 {%0,%1,%2,%3}, [%4];" \
        : "=r"(r0), "=r"(r1), "=r"(r2), "=r"(r3) : "r"(a))

#define MMA_F16(c, a, b0, b1) \
    asm volatile("mma.sync.aligned.m16n8k16.row.col.f32.f16.f16.f32 " \
        "{%0,%1,%2,%3}, {%4,%5,%6,%7}, {%8,%9}, {%0,%1,%2,%3};" \
        : "+f"((c)[0]), "+f"((c)[1]), "+f"((c)[2]), "+f"((c)[3]) \
        : "r"((a)[0]), "r"((a)[1]), "r"((a)[2]), "r"((a)[3]), "r"(b0), "r"(b1))

#define CP16(dst, src) \
    asm volatile("cp.async.cg.shared.global [%0], [%1], 16;" :: "r"(dst), "l"(src))
#define CPCOMMIT() asm volatile("cp.async.commit_group;" ::: "memory")
#define CPWAIT(n)  asm volatile("cp.async.wait_group %0;" :: "n"(n) : "memory")

__device__ __forceinline__ float ex2(float x) {
    float r;
    asm("ex2.approx.ftz.f32 %0, %1;" : "=f"(r) : "f"(x));
    return r;
}
__device__ __forceinline__ uint32_t pack_h2(float a, float b) {
    __half2 h = __floats2half2_rn(a, b);
    return *(uint32_t*)&h;
}

// ---------------------------------------------------------------------------
// convert x: fp32 -> single fp16
// ---------------------------------------------------------------------------
__global__ void __launch_bounds__(256) cvtx_kernel(const float* __restrict__ in) {
    int i = (blockIdx.x * 256 + threadIdx.x) * 4;
    float4 v = *(const float4*)(in + i);
    ((__half2*)(g_x16 + i))[0] = __floats2half2_rn(v.x, v.y);
    ((__half2*)(g_x16 + i))[1] = __floats2half2_rn(v.z, v.w);
}

// ---------------------------------------------------------------------------
// transpose weights: Wq/Wk/Wv -> g_w16, Wo -> g_wo16, all single fp16 [N,K]
// ---------------------------------------------------------------------------
__global__ void __launch_bounds__(256) tsplitw_kernel(
    const float* __restrict__ W0, const float* __restrict__ W1,
    const float* __restrict__ W2, const float* __restrict__ W3)
{
    __shared__ float tile[32][33];
    const int widx = blockIdx.z;
    const float* in = (widx == 0) ? W0 : (widx == 1) ? W1 : (widx == 2) ? W2 : W3;
    __half* o16 = (widx < 3) ? (g_w16 + (size_t)widx * 1024 * 1024) : g_wo16;
    int tx = threadIdx.x, ty = threadIdx.y;
    int x = blockIdx.x * 32 + tx, y0 = blockIdx.y * 32;
#pragma unroll
    for (int j = 0; j < 32; j += 8) tile[ty + j][tx] = in[(size_t)(y0 + ty + j) * 1024 + x];
    __syncthreads();
    int x2 = blockIdx.y * 32 + tx, y2 = blockIdx.x * 32;
#pragma unroll
    for (int j = 0; j < 32; j += 8)
        o16[(size_t)(y2 + ty + j) * 1024 + x2] = __float2half(tile[tx][ty + j]);
}

#define NT_K 32
#define GPL 10240          // one 128x40-fp16 plane (bytes)
#define GSTG (2 * GPL)     // 20480 per stage: A | B

// ---------------------------------------------------------------------------
// Unified fp16 GEMM, 1 MMA/tile: C = A @ B^T. Single fp16 A and B.
// 2-stage cp.async, 2 planes/stage (40KB total, 2 CTAs/SM).
// mode 0 (QKV, N=3072): scatter Q(prescaled)/K/V single fp16 [B,H,T,D].
// mode 1 (out, N=1024): fp32 row-major Cext.
// ---------------------------------------------------------------------------
__global__ void __launch_bounds__(256, 2) gemm16(
    const __half* __restrict__ Ap, const __half* __restrict__ Bp,
    float* __restrict__ Cext, const float* __restrict__ ls, int mode)
{
    extern __shared__ char gsm[];
    const uint32_t sb = smem_u32(gsm);
    const int tid = threadIdx.x;
    const int warp = tid >> 5, lane = tid & 31;
    const int bm = blockIdx.y * 128, bn = blockIdx.x * 128;
    const int wm = (warp >> 2) * 64, wn = (warp & 3) * 32;

    float acc[4][4][4];
#pragma unroll
    for (int i = 0; i < 4; i++)
#pragma unroll
        for (int j = 0; j < 4; j++)
#pragma unroll
            for (int r = 0; r < 4; r++) acc[i][j][r] = 0.f;

    const int lr = tid >> 1, lc = (tid & 1) << 4;
    const size_t aoff = (size_t)(bm + lr) * K_ + lc;
    const size_t boff = (size_t)(bn + lr) * K_ + lc;
    const uint32_t drow = sb + (uint32_t)lr * 80 + (uint32_t)lc * 2;

#define GISSUE(st, kt) do { \
    uint32_t d = drow + (uint32_t)(st) * GSTG; \
    size_t k0 = (size_t)(kt) * 32; \
    CP16(d,              Ap + aoff + k0); \
    CP16(d + 16,         Ap + aoff + k0 + 8); \
    CP16(d + GPL,        Bp + boff + k0); \
    CP16(d + GPL + 16,   Bp + boff + k0 + 8); \
} while (0)

    GISSUE(0, 0);
    CPCOMMIT();

    const uint32_t aAddr = (uint32_t)((wm + (lane & 15)) * 80 + (((lane >> 4) << 3)) * 2);
    const uint32_t bAddr = (uint32_t)(GPL + (wn + ((lane >> 4) << 3) + (lane & 7)) * 80 + ((lane & 8)) * 2);

    for (int kt = 0; kt < NT_K; ++kt) {
        {
            int nt = kt + 1;
            if (nt < NT_K) GISSUE(nt & 1, nt);
            CPCOMMIT();
        }
        CPWAIT(1);
        __syncthreads();
        const uint32_t stb = sb + (uint32_t)(kt & 1) * GSTG;

#pragma unroll
        for (int kk = 0; kk < 2; kk++) {
            const uint32_t ko = (uint32_t)(kk * 32);
            uint32_t ah[4][4];
#pragma unroll
            for (int i = 0; i < 4; i++) {
                uint32_t ad = stb + aAddr + (uint32_t)(i * 16 * 80) + ko;
                LDSM4(ah[i][0], ah[i][1], ah[i][2], ah[i][3], ad);
            }
#pragma unroll
            for (int jb = 0; jb < 2; jb++) {
                uint32_t bh[4];
                uint32_t bd = stb + bAddr + (uint32_t)(jb * 16 * 80) + ko;
                LDSM4(bh[0], bh[1], bh[2], bh[3], bd);
#pragma unroll
                for (int i = 0; i < 4; i++) {
                    MMA_F16(acc[i][2*jb],   ah[i], bh[0], bh[1]);
                    MMA_F16(acc[i][2*jb+1], ah[i], bh[2], bh[3]);
                }
            }
        }
        __syncthreads();
    }

    const int gr = lane >> 2, gc = (lane & 3) * 2;
    if (mode == 0) {
        const int sel = (bn + wn) >> 10;            // 0=Q 1=K 2=V (warp-constant)
        const int hh = ((bn + wn) >> 6) & 15;
        const float qs = (sel == 0) ? __expf(ls[hh]) * 0.125f * 1.4426950408889634f : 1.f;
        __half* Dst = (sel == 0) ? g_q16 : (sel == 1) ? g_k16 : g_v16;
#pragma unroll
        for (int i = 0; i < 4; i++)
#pragma unroll
            for (int j = 0; j < 4; j++) {
                int m0 = bm + wm + i * 16 + gr;
                int n0 = bn + wn + j * 8 + gc;
                int d = n0 & 63;
#pragma unroll
                for (int hrow = 0; hrow < 2; hrow++) {
                    int m = m0 + hrow * 8;
                    int b = m >> 11, t = m & (T_ - 1);
                    size_t idx = ((size_t)((b * H_ + hh) * T_ + t)) * D_ + d;
                    *(uint32_t*)(Dst + idx) =
                        pack_h2(acc[i][j][hrow*2] * qs, acc[i][j][hrow*2+1] * qs);
                }
            }
    } else {
#pragma unroll
        for (int i = 0; i < 4; i++)
#pragma unroll
            for (int j = 0; j < 4; j++) {
                int m0 = bm + wm + i * 16 + gr;
                int n0 = bn + wn + j * 8 + gc;
                *(float2*)&Cext[(size_t)m0 * N_ + n0] = make_float2(acc[i][j][0], acc[i][j][1]);
                *(float2*)&Cext[(size_t)(m0 + 8) * N_ + n0] = make_float2(acc[i][j][2], acc[i][j][3]);
            }
    }
}

// ---------------------------------------------------------------------------
// Flash attention (all single fp16): 256 threads, 128 q-rows/CTA.
// QK^T = 1 MMA; PV = 1 MMA. No online max. 2-stage cp.async K/V.
// ---------------------------------------------------------------------------
#define AST 72
#define PL64  (64 * AST * 2)     // 9216
#define PL16  (16 * AST * 2)     // 2304
#define STAGE_B (2 * PL64)       // 18432: K | V
#define S_NULL  (2 * STAGE_B)    // 36864
#define S_NK  (S_NULL)
#define S_NV  (S_NULL + PL16)
#define S_ATT_TOTAL (S_NULL + 2*PL16)   // 41472

__global__ void __launch_bounds__(256, 2) attn_mma(
    const float* __restrict__ nullk, const float* __restrict__ nullv)
{
    extern __shared__ char sm[];
    const uint32_t sb = smem_u32(sm);
    const int bh = blockIdx.y, h = bh & 15;
    const int qblk = (T_ / 128 - 1) - blockIdx.x;   // longest first
    const int qbase = qblk * 128;
    const int tid = threadIdx.x, warp = tid >> 5, lane = tid & 31;
    const int wm = warp * 16;

    // null tiles: 16 x 64, row 0 real
    for (int i = tid; i < 1024; i += 256) {
        int r = i >> 6, d = i & 63;
        float kvk = (r == 0) ? nullk[h * 64 + d] : 0.f;
        float kvv = (r == 0) ? nullv[h * 64 + d] : 0.f;
        *(__half*)(sm + S_NK + (r * AST + d) * 2) = __float2half(kvk);
        *(__half*)(sm + S_NV + (r * AST + d) * 2) = __float2half(kvv);
    }

    // Q fragments: direct LDG from prescaled fp16 plane
    uint32_t qf[4][4];
    {
        const size_t qrow0 = (size_t)bh * T_ + qbase + wm + (lane >> 2);
        const int cc = (lane & 3) * 2;
#pragma unroll
        for (int kk = 0; kk < 4; kk++) {
#pragma unroll
            for (int rg = 0; rg < 4; rg++) {
                int roff = (rg & 1) * 8;
                int col = kk * 16 + cc + (rg >> 1) * 8;
                qf[kk][rg] = *(const uint32_t*)(g_q16 + (qrow0 + roff) * D_ + col);
            }
        }
    }

    float o[8][4];
#pragma unroll
    for (int j = 0; j < 8; j++)
#pragma unroll
        for (int r = 0; r < 4; r++) o[j][r] = 0.f;
    float l0 = 0.f, l1 = 0.f;

    const int qmin_w = qbase + wm;
    const int qmax_w = qbase + wm + 15;
    const int nkb = (qbase + 128) / 64;

    // K/V cp.async staging map: row=tid>>2 (0..63), col chunk=(tid&3)*16
    const int sr = tid >> 2, scol = (tid & 3) * 16;
    const uint32_t doff = (uint32_t)((sr * AST + scol) * 2);
    const size_t gbase0 = ((size_t)bh * T_ + sr) * D_ + scol;

#define AISS(st, kb_) do { \
    size_t base_ = gbase0 + (size_t)(kb_) * 64 * D_; \
    uint32_t d_ = sb + (uint32_t)(st) * STAGE_B + doff; \
    CP16(d_,              g_k16 + base_); \
    CP16(d_ + 16,         g_k16 + base_ + 8); \
    CP16(d_ + PL64,       g_v16 + base_); \
    CP16(d_ + PL64 + 16,  g_v16 + base_ + 8); \
} while (0)

    AISS(0, 0);
    CPCOMMIT();

    for (int kb = 0; kb < nkb; kb++) {
        __syncthreads();                 // everyone done reading the other stage
        if (kb + 1 < nkb) AISS((kb + 1) & 1, kb + 1);
        CPCOMMIT();
        CPWAIT(1);
        __syncthreads();                 // stage kb visible to all
        if (kb * 64 > qmax_w) continue;  // warp fully below diagonal
        const uint32_t stb = sb + (uint32_t)(kb & 1) * STAGE_B;

        // S = Qs K^T   (1 MMA per acc)
        float s[8][4];
#pragma unroll
        for (int j = 0; j < 8; j++)
#pragma unroll
            for (int r = 0; r < 4; r++) s[j][r] = 0.f;
#pragma unroll
        for (int kk = 0; kk < 4; kk++) {
#pragma unroll
            for (int jb = 0; jb < 4; jb++) {
                uint32_t kf[4];
                uint32_t bd = stb + (uint32_t)((jb * 16 + ((lane >> 4) << 3) + (lane & 7)) * AST
                            + kk * 16 + (lane & 8)) * 2;
                LDSM4(kf[0], kf[1], kf[2], kf[3], bd);
                MMA_F16(s[2*jb],   qf[kk], kf[0], kf[1]);
                MMA_F16(s[2*jb+1], qf[kk], kf[2], kf[3]);
            }
        }

        // causal mask (diagonal warp-block only)
        if (kb * 64 + 63 > qmin_w) {
            const int q0 = qmin_w + (lane >> 2), q1 = q0 + 8;
#pragma unroll
            for (int j = 0; j < 8; j++) {
                int c = kb * 64 + j * 8 + ((lane & 3) << 1);
                if (c     > q0) s[j][0] = -1e30f;
                if (c + 1 > q0) s[j][1] = -1e30f;
                if (c     > q1) s[j][2] = -1e30f;
                if (c + 1 > q1) s[j][3] = -1e30f;
            }
        }

        // p = exp2(s); accumulate l
#pragma unroll
        for (int j = 0; j < 8; j++) {
            s[j][0] = ex2(s[j][0]); s[j][1] = ex2(s[j][1]);
            s[j][2] = ex2(s[j][2]); s[j][3] = ex2(s[j][3]);
            l0 += s[j][0] + s[j][1];
            l1 += s[j][2] + s[j][3];
        }

        // O += P V   (1 MMA per acc)
#pragma unroll
        for (int kk = 0; kk < 4; kk++) {
            uint32_t ph[4];
            ph[0] = pack_h2(s[2*kk][0],   s[2*kk][1]);
            ph[1] = pack_h2(s[2*kk][2],   s[2*kk][3]);
            ph[2] = pack_h2(s[2*kk+1][0], s[2*kk+1][1]);
            ph[3] = pack_h2(s[2*kk+1][2], s[2*kk+1][3]);
#pragma unroll
            for (int g = 0; g < 4; g++) {
                uint32_t vh[4];
                uint32_t vd = stb + PL64 + (uint32_t)((kk * 16 + (lane & 15)) * AST
                            + g * 16 + ((lane >> 4) << 3)) * 2;
                LDSM4T(vh[0], vh[1], vh[2], vh[3], vd);
                MMA_F16(o[2*g],   ph, vh[0], vh[1]);
                MMA_F16(o[2*g+1], ph, vh[2], vh[3]);
            }
        }
    }

    // null-KV block (16 padded cols, col 0 real)
    {
        float s[2][4];
#pragma unroll
        for (int j = 0; j < 2; j++)
#pragma unroll
            for (int r = 0; r < 4; r++) s[j][r] = 0.f;
#pragma unroll
        for (int kk = 0; kk < 4; kk++) {
            uint32_t kf[4];
            uint32_t bd = sb + S_NK + (uint32_t)((((lane >> 4) << 3) + (lane & 7)) * AST
                        + kk * 16 + (lane & 8)) * 2;
            LDSM4(kf[0], kf[1], kf[2], kf[3], bd);
            MMA_F16(s[0], qf[kk], kf[0], kf[1]);
            MMA_F16(s[1], qf[kk], kf[2], kf[3]);
        }
#pragma unroll
        for (int j = 0; j < 2; j++) {
            int c = j * 8 + ((lane & 3) << 1);
            s[j][0] = (c == 0) ? ex2(s[j][0]) : 0.f;
            s[j][1] = 0.f;
            s[j][2] = (c == 0) ? ex2(s[j][2]) : 0.f;
            s[j][3] = 0.f;
            l0 += s[j][0];
            l1 += s[j][2];
        }

        uint32_t ph[4];
        ph[0] = pack_h2(s[0][0], s[0][1]);
        ph[1] = pack_h2(s[0][2], s[0][3]);
        ph[2] = pack_h2(s[1][0], s[1][1]);
        ph[3] = pack_h2(s[1][2], s[1][3]);
#pragma unroll
        for (int g = 0; g < 4; g++) {
            uint32_t vh[4];
            uint32_t vd = sb + S_NV + (uint32_t)((lane & 15) * AST + g * 16 + ((lane >> 4) << 3)) * 2;
            LDSM4T(vh[0], vh[1], vh[2], vh[3], vd);
            MMA_F16(o[2*g],   ph, vh[0], vh[1]);
            MMA_F16(o[2*g+1], ph, vh[2], vh[3]);
        }
    }

    // finalize: quad-reduce l, normalize, write y single fp16
    l0 += __shfl_xor_sync(0xffffffffu, l0, 1);
    l0 += __shfl_xor_sync(0xffffffffu, l0, 2);
    l1 += __shfl_xor_sync(0xffffffffu, l1, 1);
    l1 += __shfl_xor_sync(0xffffffffu, l1, 2);
    const float i0 = 1.f / l0, i1 = 1.f / l1;
    const int b = bh >> 4;
    const int t0 = qbase + wm + (lane >> 2), t1 = t0 + 8;
    const int cb = h * 64 + ((lane & 3) << 1);
#pragma unroll
    for (int j = 0; j < 8; j++) {
        int cc = cb + j * 8;
        *(uint32_t*)(g_y16 + (size_t)(b * T_ + t0) * C_ + cc) = pack_h2(o[j][0] * i0, o[j][1] * i0);
        *(uint32_t*)(g_y16 + (size_t)(b * T_ + t1) * C_ + cc) = pack_h2(o[j][2] * i1, o[j][3] * i1);
    }
}

// ---------------------------------------------------------------------------
// kernel_launch
// Inputs: x, Wq, Wk, Wv, Wo, null_k, null_v, logit_scale
// ---------------------------------------------------------------------------
extern "C" void kernel_launch(void* const* d_in, const int* in_sizes, int n_in,
                              void* d_out, int out_size) {
    const float* x  = (const float*)d_in[0];
    const float* Wq = (const float*)d_in[1];
    const float* Wk = (const float*)d_in[2];
    const float* Wv = (const float*)d_in[3];
    const float* Wo = (const float*)d_in[4];
    const float* nk = (const float*)d_in[5];
    const float* nv = (const float*)d_in[6];
    const float* ls = (const float*)d_in[7];
    float* out = (float*)d_out;

    __half *x16, *y16, *w16, *wo16;
    cudaGetSymbolAddress((void**)&x16, g_x16);
    cudaGetSymbolAddress((void**)&y16, g_y16);
    cudaGetSymbolAddress((void**)&w16, g_w16);
    cudaGetSymbolAddress((void**)&wo16, g_wo16);

    const int GEMM_SMEM = 2 * GSTG;       // 40960
    cudaFuncSetAttribute(gemm16, cudaFuncAttributeMaxDynamicSharedMemorySize, GEMM_SMEM);
    cudaFuncSetAttribute(attn_mma, cudaFuncAttributeMaxDynamicSharedMemorySize, S_ATT_TOTAL);

    cvtx_kernel<<<(M_ * C_) / (256 * 4), 256>>>(x);
    tsplitw_kernel<<<dim3(32, 32, 4), dim3(32, 8)>>>(Wq, Wk, Wv, Wo);

    gemm16<<<dim3(24, 64), 256, GEMM_SMEM>>>(x16, w16, nullptr, ls, 0);

    attn_mma<<<dim3(T_ / 128, B_ * H_), 256, S_ATT_TOTAL>>>(nk, nv);

    gemm16<<<dim3(8, 64), 256, GEMM_SMEM>>>(y16, wo16, out, ls, 1);
}